// round 1
// baseline (speedup 1.0000x reference)
#include <cuda_runtime.h>
#include <cuda_bf16.h>

#define SEQ 8192
#define CTX 2048
#define DK  128
#define NT  64                    // SEQ / 128
#define SCALE 11.313708498984760f // sqrt(128)
#define THRESH -25.0f             // exp(-25) ~ 1.4e-11, negligible vs Z >= 1

// ---- scratch (device globals: allocation-free per harness rules) ----
__device__ float g_q[SEQ * DK];
__device__ float g_k[SEQ * DK];
__device__ float g_v[SEQ * DK];
__device__ float g_sc[(size_t)SEQ * SEQ];   // 256 MB fp32 scores
__device__ float g_pm[NT * SEQ];            // per s-tile column max partials
__device__ float g_pz[NT * SEQ];            // per s-tile column sum partials
__device__ float g_m[SEQ];                  // column max
__device__ float g_rz[SEQ];                 // 1 / column sum

// ============================================================
// K1: Q/K/V = x @ w   (M=8192, K=2048, N=128), BM=64 BN=128 BK=8
// ============================================================
__global__ __launch_bounds__(256) void qkv_kernel(
    const float* __restrict__ x, const float* __restrict__ wq,
    const float* __restrict__ wk, const float* __restrict__ wv)
{
    __shared__ float sA[8][64];
    __shared__ float sB[8][128];
    const int m0 = blockIdx.x * 64;
    const float* __restrict__ w = (blockIdx.y == 0) ? wq : (blockIdx.y == 1) ? wk : wv;
    float* out = (blockIdx.y == 0) ? g_q : (blockIdx.y == 1) ? g_k : g_v;
    const int tid = threadIdx.x;
    const int tx = tid & 15, ty = tid >> 4;
    const int ar = tid >> 2, ac = (tid & 3) * 2;   // A loader: 64 rows x 8 cols
    const int br = tid >> 5, bc = (tid & 31) * 4;  // B loader: 8 rows x 128 cols

    float acc[4][8];
#pragma unroll
    for (int i = 0; i < 4; i++)
#pragma unroll
        for (int j = 0; j < 8; j++) acc[i][j] = 0.f;

    const float* xp = x + (size_t)(m0 + ar) * CTX + ac;
    for (int k0 = 0; k0 < CTX; k0 += 8) {
        float2 av = *reinterpret_cast<const float2*>(xp + k0);
        float4 bv = *reinterpret_cast<const float4*>(w + (size_t)(k0 + br) * DK + bc);
        __syncthreads();
        sA[ac][ar] = av.x;
        sA[ac + 1][ar] = av.y;
        *reinterpret_cast<float4*>(&sB[br][bc]) = bv;
        __syncthreads();
#pragma unroll
        for (int kk = 0; kk < 8; kk++) {
            float4 a  = *reinterpret_cast<const float4*>(&sA[kk][ty * 4]);
            float4 b0 = *reinterpret_cast<const float4*>(&sB[kk][tx * 8]);
            float4 b1 = *reinterpret_cast<const float4*>(&sB[kk][tx * 8 + 4]);
            float aa[4] = {a.x, a.y, a.z, a.w};
            float bb[8] = {b0.x, b0.y, b0.z, b0.w, b1.x, b1.y, b1.z, b1.w};
#pragma unroll
            for (int i = 0; i < 4; i++)
#pragma unroll
                for (int j = 0; j < 8; j++) acc[i][j] += aa[i] * bb[j];
        }
    }
#pragma unroll
    for (int i = 0; i < 4; i++) {
        float* op = out + (size_t)(m0 + ty * 4 + i) * DK + tx * 8;
        *reinterpret_cast<float4*>(op)     = make_float4(acc[i][0], acc[i][1], acc[i][2], acc[i][3]);
        *reinterpret_cast<float4*>(op + 4) = make_float4(acc[i][4], acc[i][5], acc[i][6], acc[i][7]);
    }
}

// ============================================================
// K2: scores = (Q @ K^T) * SCALE  (128x128 tiles), write fp32 +
//     per-tile column max partials (softmax is over axis 0 = rows)
// ============================================================
__global__ __launch_bounds__(256) void scores_kernel()
{
    __shared__ float sA[8][128];
    __shared__ float sB[8][128];
    __shared__ float red[16][128];
    const int t0 = blockIdx.x * 128, s0 = blockIdx.y * 128;
    const int tid = threadIdx.x;
    const int tx = tid & 15, ty = tid >> 4;
    const int lr = tid >> 1, lc = (tid & 1) * 4;   // loader: 128 rows x 8 cols

    float acc[8][8];
#pragma unroll
    for (int i = 0; i < 8; i++)
#pragma unroll
        for (int j = 0; j < 8; j++) acc[i][j] = 0.f;

    for (int k0 = 0; k0 < DK; k0 += 8) {
        float4 aq = *reinterpret_cast<const float4*>(g_q + (size_t)(s0 + lr) * DK + k0 + lc);
        float4 ak = *reinterpret_cast<const float4*>(g_k + (size_t)(t0 + lr) * DK + k0 + lc);
        __syncthreads();
        sA[lc][lr] = aq.x; sA[lc + 1][lr] = aq.y; sA[lc + 2][lr] = aq.z; sA[lc + 3][lr] = aq.w;
        sB[lc][lr] = ak.x; sB[lc + 1][lr] = ak.y; sB[lc + 2][lr] = ak.z; sB[lc + 3][lr] = ak.w;
        __syncthreads();
#pragma unroll
        for (int kk = 0; kk < 8; kk++) {
            float4 a0 = *reinterpret_cast<const float4*>(&sA[kk][ty * 8]);
            float4 a1 = *reinterpret_cast<const float4*>(&sA[kk][ty * 8 + 4]);
            float4 b0 = *reinterpret_cast<const float4*>(&sB[kk][tx * 8]);
            float4 b1 = *reinterpret_cast<const float4*>(&sB[kk][tx * 8 + 4]);
            float aa[8] = {a0.x, a0.y, a0.z, a0.w, a1.x, a1.y, a1.z, a1.w};
            float bb[8] = {b0.x, b0.y, b0.z, b0.w, b1.x, b1.y, b1.z, b1.w};
#pragma unroll
            for (int i = 0; i < 8; i++)
#pragma unroll
                for (int j = 0; j < 8; j++) acc[i][j] += aa[i] * bb[j];
        }
    }

    // epilogue: scale, store fp32, column (over-rows) max
    float cmax[8];
#pragma unroll
    for (int j = 0; j < 8; j++) cmax[j] = -3.4e38f;
#pragma unroll
    for (int i = 0; i < 8; i++) {
        float r[8];
#pragma unroll
        for (int j = 0; j < 8; j++) {
            r[j] = acc[i][j] * SCALE;
            cmax[j] = fmaxf(cmax[j], r[j]);
        }
        float* op = g_sc + (size_t)(s0 + ty * 8 + i) * SEQ + t0 + tx * 8;
        *reinterpret_cast<float4*>(op)     = make_float4(r[0], r[1], r[2], r[3]);
        *reinterpret_cast<float4*>(op + 4) = make_float4(r[4], r[5], r[6], r[7]);
    }
    __syncthreads();
#pragma unroll
    for (int j = 0; j < 8; j++) red[ty][tx * 8 + j] = cmax[j];
    __syncthreads();
    if (tid < 128) {
        float m = -3.4e38f;
#pragma unroll
        for (int r = 0; r < 16; r++) m = fmaxf(m, red[r][tid]);
        g_pm[blockIdx.y * SEQ + t0 + tid] = m;
    }
}

// K3: combine column max over 64 s-tiles (fixed order: deterministic)
__global__ void colmax_kernel()
{
    const int t = blockIdx.x * 256 + threadIdx.x;
    float m = -3.4e38f;
#pragma unroll 8
    for (int i = 0; i < NT; i++) m = fmaxf(m, g_pm[i * SEQ + t]);
    g_m[t] = m;
}

// ============================================================
// K4: Z partials: per (s-tile, t) sum of exp(sc - m_t), skip-heavy
// ============================================================
__global__ __launch_bounds__(256) void zsum_kernel()
{
    __shared__ float s_m[128];
    __shared__ float red[16][128];
    const int t0 = blockIdx.x * 128, s0 = blockIdx.y * 128;
    const int tid = threadIdx.x;
    if (tid < 128) s_m[tid] = g_m[t0 + tid];
    __syncthreads();
    const int cg = tid & 15, rb = tid >> 4;
    float mloc[8];
#pragma unroll
    for (int j = 0; j < 8; j++) mloc[j] = s_m[cg * 8 + j];
    float z[8];
#pragma unroll
    for (int j = 0; j < 8; j++) z[j] = 0.f;

    for (int rr = 0; rr < 8; rr++) {
        const int r = rb + rr * 16;
        const float* p = g_sc + (size_t)(s0 + r) * SEQ + t0 + cg * 8;
        float4 u0 = reinterpret_cast<const float4*>(p)[0];
        float4 u1 = reinterpret_cast<const float4*>(p)[1];
        float d[8] = {u0.x - mloc[0], u0.y - mloc[1], u0.z - mloc[2], u0.w - mloc[3],
                      u1.x - mloc[4], u1.y - mloc[5], u1.z - mloc[6], u1.w - mloc[7]};
        float dm = d[0];
#pragma unroll
        for (int j = 1; j < 8; j++) dm = fmaxf(dm, d[j]);
        if (dm > THRESH) {
#pragma unroll
            for (int j = 0; j < 8; j++)
                if (d[j] > THRESH) z[j] += __expf(d[j]);
        }
    }
#pragma unroll
    for (int j = 0; j < 8; j++) red[rb][cg * 8 + j] = z[j];
    __syncthreads();
    if (tid < 128) {
        float s = 0.f;
#pragma unroll
        for (int r = 0; r < 16; r++) s += red[r][tid];
        g_pz[blockIdx.y * SEQ + t0 + tid] = s;
    }
}

// K5: 1/Z (fixed-order sum: deterministic, no float atomics anywhere)
__global__ void rz_kernel()
{
    const int t = blockIdx.x * 256 + threadIdx.x;
    float s = 0.f;
#pragma unroll 8
    for (int i = 0; i < NT; i++) s += g_pz[i * SEQ + t];
    g_rz[t] = 1.0f / s;
}

// ============================================================
// K6: out = P @ (V / Z), P[s,t] = exp(sc[s,t] - m_t) on the fly.
//     BM=64, N=128, BK=8; tile-skip when P-chunk is all zero.
// ============================================================
__global__ __launch_bounds__(256) void pv_kernel(float* __restrict__ out)
{
    __shared__ float s_m[SEQ];   // 32 KB: full column-max vector
    __shared__ float sA[8][64];
    __shared__ float sB[8][128];
    const int s0 = blockIdx.x * 64;
    const int tid = threadIdx.x;
    const int tx = tid & 15, ty = tid >> 4;
    const int ar = tid >> 2, ac = (tid & 3) * 2;
    const int br = tid >> 5, bc = (tid & 31) * 4;

    for (int i = tid * 4; i < SEQ; i += 1024)
        *reinterpret_cast<float4*>(&s_m[i]) = *reinterpret_cast<const float4*>(&g_m[i]);

    float acc[4][8];
#pragma unroll
    for (int i = 0; i < 4; i++)
#pragma unroll
        for (int j = 0; j < 8; j++) acc[i][j] = 0.f;

    const float* sp = g_sc + (size_t)(s0 + ar) * SEQ + ac;
    __syncthreads();

    for (int k0 = 0; k0 < SEQ; k0 += 8) {
        float2 sv = *reinterpret_cast<const float2*>(sp + k0);
        float d0 = sv.x - s_m[k0 + ac];
        float d1 = sv.y - s_m[k0 + ac + 1];
        float rzv = g_rz[k0 + br];
        float4 bv = *reinterpret_cast<const float4*>(g_v + (size_t)(k0 + br) * DK + bc);
        float p0 = 0.f, p1 = 0.f;
        if (fmaxf(d0, d1) > THRESH) {        // branch: skip MUFU for the ~99% dead region
            if (d0 > THRESH) p0 = __expf(d0);
            if (d1 > THRESH) p1 = __expf(d1);
        }
        __syncthreads();                      // WAR guard on sA/sB
        sA[ac][ar] = p0;
        sA[ac + 1][ar] = p1;
        *reinterpret_cast<float4*>(&sB[br][bc]) =
            make_float4(bv.x * rzv, bv.y * rzv, bv.z * rzv, bv.w * rzv);
        int active = __syncthreads_or(p0 != 0.f || p1 != 0.f);
        if (active) {                         // uniform across block
#pragma unroll
            for (int kk = 0; kk < 8; kk++) {
                float4 a  = *reinterpret_cast<const float4*>(&sA[kk][ty * 4]);
                float4 b0 = *reinterpret_cast<const float4*>(&sB[kk][tx * 8]);
                float4 b1 = *reinterpret_cast<const float4*>(&sB[kk][tx * 8 + 4]);
                float aa[4] = {a.x, a.y, a.z, a.w};
                float bb[8] = {b0.x, b0.y, b0.z, b0.w, b1.x, b1.y, b1.z, b1.w};
#pragma unroll
                for (int i = 0; i < 4; i++)
#pragma unroll
                    for (int j = 0; j < 8; j++) acc[i][j] += aa[i] * bb[j];
            }
        }
    }
#pragma unroll
    for (int i = 0; i < 4; i++) {
        float* op = out + (size_t)(s0 + ty * 4 + i) * DK + tx * 8;
        *reinterpret_cast<float4*>(op)     = make_float4(acc[i][0], acc[i][1], acc[i][2], acc[i][3]);
        *reinterpret_cast<float4*>(op + 4) = make_float4(acc[i][4], acc[i][5], acc[i][6], acc[i][7]);
    }
}

// ============================================================
extern "C" void kernel_launch(void* const* d_in, const int* in_sizes, int n_in,
                              void* d_out, int out_size)
{
    const float* x  = (const float*)d_in[0];
    const float* wq = (const float*)d_in[1];
    const float* wk = (const float*)d_in[2];
    const float* wv = (const float*)d_in[3];
    float* out = (float*)d_out;

    qkv_kernel<<<dim3(SEQ / 64, 3), 256>>>(x, wq, wk, wv);
    scores_kernel<<<dim3(NT, NT), 256>>>();
    colmax_kernel<<<SEQ / 256, 256>>>();
    zsum_kernel<<<dim3(NT, NT), 256>>>();
    rz_kernel<<<SEQ / 256, 256>>>();
    pv_kernel<<<SEQ / 64, 256>>>(out);
}

// round 2
// speedup vs baseline: 1.0094x; 1.0094x over previous
#include <cuda_runtime.h>
#include <cuda_bf16.h>
#include <cstdint>

#define SEQ 8192
#define CTX 2048
#define DK  128
#define NT  64                    // SEQ / 128
#define SCALE 11.313708498984760f // sqrt(128)
#define THRESH -25.0f             // exp(-25) ~ 1.4e-11, negligible vs Z >= 1

// ---- scratch (device globals: allocation-free per harness rules) ----
__device__ float g_q[SEQ * DK];
__device__ float g_k[SEQ * DK];
__device__ float g_v[SEQ * DK];
__device__ float g_sc[(size_t)SEQ * SEQ];   // 256 MB fp32 scores
__device__ float g_pm[NT * SEQ];            // per s-tile column max partials
__device__ float g_pz[NT * SEQ];            // per s-tile column sum partials
__device__ float g_m[SEQ];                  // column max
__device__ float g_rz[SEQ];                 // 1 / column sum

// ============================================================
// tf32 helpers (3xTF32 fp32 emulation on tensor cores)
// ============================================================
__device__ __forceinline__ uint2 split_tf32(float a) {
    uint32_t h;
    asm("cvt.rna.tf32.f32 %0, %1;" : "=r"(h) : "f"(a));
    float res = a - __uint_as_float(h);
    uint32_t l;
    asm("cvt.rna.tf32.f32 %0, %1;" : "=r"(l) : "f"(res));
    return make_uint2(h, l);
}

__device__ __forceinline__ void mma8(float* c, const uint32_t* a, const uint32_t* b) {
    asm("mma.sync.aligned.m16n8k8.row.col.f32.tf32.tf32.f32 "
        "{%0,%1,%2,%3}, {%4,%5,%6,%7}, {%8,%9}, {%0,%1,%2,%3};"
        : "+f"(c[0]), "+f"(c[1]), "+f"(c[2]), "+f"(c[3])
        : "r"(a[0]), "r"(a[1]), "r"(a[2]), "r"(a[3]), "r"(b[0]), "r"(b[1]));
}

// store 8 consecutive (hi,lo) pairs starting at dst (16B-aligned)
__device__ __forceinline__ void store8_split(uint2* dst, float4 a, float4 b) {
    uint2 e0 = split_tf32(a.x), e1 = split_tf32(a.y), e2 = split_tf32(a.z), e3 = split_tf32(a.w);
    uint2 e4 = split_tf32(b.x), e5 = split_tf32(b.y), e6 = split_tf32(b.z), e7 = split_tf32(b.w);
    uint4* d = reinterpret_cast<uint4*>(dst);
    d[0] = make_uint4(e0.x, e0.y, e1.x, e1.y);
    d[1] = make_uint4(e2.x, e2.y, e3.x, e3.y);
    d[2] = make_uint4(e4.x, e4.y, e5.x, e5.y);
    d[3] = make_uint4(e6.x, e6.y, e7.x, e7.y);
}

// ============================================================
// K1: Q/K/V = x @ w  via 3xTF32 MMA. BM=128, BN=128(=DK), BK=16.
// grid (64, 3), 256 threads (8 warps, warp tile 64x32)
// ============================================================
__global__ __launch_bounds__(256) void qkv_mma_kernel(
    const float* __restrict__ x, const float* __restrict__ wq,
    const float* __restrict__ wk, const float* __restrict__ wv)
{
    __shared__ uint2 sA[128][20];   // [m][k] (hi,lo), stride 20: conflict-free frags
    __shared__ uint2 sB[16][132];   // [k][n] (hi,lo), stride 132

    const int m0 = blockIdx.x * 128;
    const float* __restrict__ w = (blockIdx.y == 0) ? wq : (blockIdx.y == 1) ? wk : wv;
    float* out = (blockIdx.y == 0) ? g_q : (blockIdx.y == 1) ? g_k : g_v;

    const int tid = threadIdx.x;
    const int wid = tid >> 5, lane = tid & 31;
    const int g = lane >> 2, tig = lane & 3;
    const int wm = (wid & 1) * 64;
    const int wn = (wid >> 1) * 32;

    const int fr = tid >> 1, fk = (tid & 1) * 8;   // A fill: 128 rows x 16 k
    const int br = tid >> 4, bn = (tid & 15) * 8;  // B fill: 16 rows x 128 n

    float acc[4][4][4];
#pragma unroll
    for (int i = 0; i < 4; i++)
#pragma unroll
        for (int j = 0; j < 4; j++)
#pragma unroll
            for (int q = 0; q < 4; q++) acc[i][j][q] = 0.f;

    const float* gx = x + (size_t)(m0 + fr) * CTX + fk;
    const float* gw = w + (size_t)br * DK + bn;

    float4 a0 = *reinterpret_cast<const float4*>(gx);
    float4 a1 = *reinterpret_cast<const float4*>(gx + 4);
    float4 b0 = *reinterpret_cast<const float4*>(gw);
    float4 b1 = *reinterpret_cast<const float4*>(gw + 4);

    for (int kc = 0; kc < CTX / 16; kc++) {
        __syncthreads();
        store8_split(&sA[fr][fk], a0, a1);
        store8_split(&sB[br][bn], b0, b1);
        __syncthreads();
        if (kc + 1 < CTX / 16) {
            const float* pa = gx + (kc + 1) * 16;
            const float* pb = gw + (size_t)(kc + 1) * 16 * DK;
            a0 = *reinterpret_cast<const float4*>(pa);
            a1 = *reinterpret_cast<const float4*>(pa + 4);
            b0 = *reinterpret_cast<const float4*>(pb);
            b1 = *reinterpret_cast<const float4*>(pb + 4);
        }
#pragma unroll
        for (int kk = 0; kk < 16; kk += 8) {
            uint32_t ah[4][4], al[4][4];
#pragma unroll
            for (int mt = 0; mt < 4; mt++) {
                const int r = wm + mt * 16 + g;
                uint2 A0 = sA[r][kk + tig];
                uint2 A1 = sA[r + 8][kk + tig];
                uint2 A2 = sA[r][kk + 4 + tig];
                uint2 A3 = sA[r + 8][kk + 4 + tig];
                ah[mt][0] = A0.x; ah[mt][1] = A1.x; ah[mt][2] = A2.x; ah[mt][3] = A3.x;
                al[mt][0] = A0.y; al[mt][1] = A1.y; al[mt][2] = A2.y; al[mt][3] = A3.y;
            }
#pragma unroll
            for (int nt = 0; nt < 4; nt++) {
                const int c = wn + nt * 8 + g;
                uint2 B0 = sB[kk + tig][c];
                uint2 B1 = sB[kk + 4 + tig][c];
                uint32_t bh[2] = {B0.x, B1.x};
                uint32_t bl[2] = {B0.y, B1.y};
#pragma unroll
                for (int mt = 0; mt < 4; mt++) {
                    mma8(acc[mt][nt], ah[mt], bh);
                    mma8(acc[mt][nt], ah[mt], bl);
                    mma8(acc[mt][nt], al[mt], bh);
                }
            }
        }
    }

#pragma unroll
    for (int mt = 0; mt < 4; mt++) {
#pragma unroll
        for (int nt = 0; nt < 4; nt++) {
            const int r0 = m0 + wm + mt * 16 + g;
            const int col = wn + nt * 8 + 2 * tig;
            *reinterpret_cast<float2*>(out + (size_t)r0 * DK + col) =
                make_float2(acc[mt][nt][0], acc[mt][nt][1]);
            *reinterpret_cast<float2*>(out + (size_t)(r0 + 8) * DK + col) =
                make_float2(acc[mt][nt][2], acc[mt][nt][3]);
        }
    }
}

// ============================================================
// K2: scores = (Q @ K^T) * SCALE via 3xTF32 MMA + column-max partials.
// BM=128 (s), BN=128 (t), K=DK=128, BK=16. grid (NT, NT), 256 thr.
// ============================================================
__global__ __launch_bounds__(256) void scores_mma_kernel()
{
    __shared__ uint2 sQ[128][20];
    __shared__ uint2 sK[128][20];
    __shared__ float colred[2][128];

    const int t0 = blockIdx.x * 128, s0 = blockIdx.y * 128;
    const int tid = threadIdx.x;
    const int wid = tid >> 5, lane = tid & 31;
    const int g = lane >> 2, tig = lane & 3;
    const int wm = (wid & 1) * 64;
    const int wn = (wid >> 1) * 32;

    const int fr = tid >> 1, fk = (tid & 1) * 8;

    float acc[4][4][4];
#pragma unroll
    for (int i = 0; i < 4; i++)
#pragma unroll
        for (int j = 0; j < 4; j++)
#pragma unroll
            for (int q = 0; q < 4; q++) acc[i][j][q] = 0.f;

    const float* gq = g_q + (size_t)(s0 + fr) * DK + fk;
    const float* gk = g_k + (size_t)(t0 + fr) * DK + fk;

    float4 qa = *reinterpret_cast<const float4*>(gq);
    float4 qb = *reinterpret_cast<const float4*>(gq + 4);
    float4 ka = *reinterpret_cast<const float4*>(gk);
    float4 kb = *reinterpret_cast<const float4*>(gk + 4);

    for (int kc = 0; kc < DK / 16; kc++) {
        __syncthreads();
        store8_split(&sQ[fr][fk], qa, qb);
        store8_split(&sK[fr][fk], ka, kb);
        __syncthreads();
        if (kc + 1 < DK / 16) {
            const float* pq = gq + (kc + 1) * 16;
            const float* pk = gk + (kc + 1) * 16;
            qa = *reinterpret_cast<const float4*>(pq);
            qb = *reinterpret_cast<const float4*>(pq + 4);
            ka = *reinterpret_cast<const float4*>(pk);
            kb = *reinterpret_cast<const float4*>(pk + 4);
        }
#pragma unroll
        for (int kk = 0; kk < 16; kk += 8) {
            uint32_t ah[4][4], al[4][4];
#pragma unroll
            for (int mt = 0; mt < 4; mt++) {
                const int r = wm + mt * 16 + g;
                uint2 A0 = sQ[r][kk + tig];
                uint2 A1 = sQ[r + 8][kk + tig];
                uint2 A2 = sQ[r][kk + 4 + tig];
                uint2 A3 = sQ[r + 8][kk + 4 + tig];
                ah[mt][0] = A0.x; ah[mt][1] = A1.x; ah[mt][2] = A2.x; ah[mt][3] = A3.x;
                al[mt][0] = A0.y; al[mt][1] = A1.y; al[mt][2] = A2.y; al[mt][3] = A3.y;
            }
#pragma unroll
            for (int nt = 0; nt < 4; nt++) {
                const int c = wn + nt * 8 + g;
                uint2 B0 = sK[c][kk + tig];
                uint2 B1 = sK[c][kk + 4 + tig];
                uint32_t bh[2] = {B0.x, B1.x};
                uint32_t bl[2] = {B0.y, B1.y};
#pragma unroll
                for (int mt = 0; mt < 4; mt++) {
                    mma8(acc[mt][nt], ah[mt], bh);
                    mma8(acc[mt][nt], ah[mt], bl);
                    mma8(acc[mt][nt], al[mt], bh);
                }
            }
        }
    }

    // epilogue: scale, store fp32 scores, column (over-s) max partials
    float cm[8];
#pragma unroll
    for (int j = 0; j < 8; j++) cm[j] = -3.4e38f;

#pragma unroll
    for (int mt = 0; mt < 4; mt++) {
#pragma unroll
        for (int nt = 0; nt < 4; nt++) {
            float v0 = acc[mt][nt][0] * SCALE;
            float v1 = acc[mt][nt][1] * SCALE;
            float v2 = acc[mt][nt][2] * SCALE;
            float v3 = acc[mt][nt][3] * SCALE;
            const int r0 = s0 + wm + mt * 16 + g;
            const int col = t0 + wn + nt * 8 + 2 * tig;
            *reinterpret_cast<float2*>(g_sc + (size_t)r0 * SEQ + col) = make_float2(v0, v1);
            *reinterpret_cast<float2*>(g_sc + (size_t)(r0 + 8) * SEQ + col) = make_float2(v2, v3);
            cm[nt * 2 + 0] = fmaxf(cm[nt * 2 + 0], fmaxf(v0, v2));
            cm[nt * 2 + 1] = fmaxf(cm[nt * 2 + 1], fmaxf(v1, v3));
        }
    }
    // reduce over g (lanes differing in bits 2..4)
#pragma unroll
    for (int off = 4; off < 32; off <<= 1)
#pragma unroll
        for (int j = 0; j < 8; j++)
            cm[j] = fmaxf(cm[j], __shfl_xor_sync(0xffffffffu, cm[j], off));

    if (g == 0) {
#pragma unroll
        for (int nt = 0; nt < 4; nt++) {
            colred[wid & 1][wn + nt * 8 + 2 * tig + 0] = cm[nt * 2 + 0];
            colred[wid & 1][wn + nt * 8 + 2 * tig + 1] = cm[nt * 2 + 1];
        }
    }
    __syncthreads();
    if (tid < 128)
        g_pm[blockIdx.y * SEQ + t0 + tid] = fmaxf(colred[0][tid], colred[1][tid]);
}

// K3: combine column max over 64 s-tiles (fixed order: deterministic)
__global__ void colmax_kernel()
{
    const int t = blockIdx.x * 256 + threadIdx.x;
    float m = -3.4e38f;
#pragma unroll 8
    for (int i = 0; i < NT; i++) m = fmaxf(m, g_pm[i * SEQ + t]);
    g_m[t] = m;
}

// ============================================================
// K4: Z partials: per (s-tile, t) sum of exp(sc - m_t), skip-heavy
// ============================================================
__global__ __launch_bounds__(256) void zsum_kernel()
{
    __shared__ float s_m[128];
    __shared__ float red[16][128];
    const int t0 = blockIdx.x * 128, s0 = blockIdx.y * 128;
    const int tid = threadIdx.x;
    if (tid < 128) s_m[tid] = g_m[t0 + tid];
    __syncthreads();
    const int cg = tid & 15, rb = tid >> 4;
    float mloc[8];
#pragma unroll
    for (int j = 0; j < 8; j++) mloc[j] = s_m[cg * 8 + j];
    float z[8];
#pragma unroll
    for (int j = 0; j < 8; j++) z[j] = 0.f;

    for (int rr = 0; rr < 8; rr++) {
        const int r = rb + rr * 16;
        const float* p = g_sc + (size_t)(s0 + r) * SEQ + t0 + cg * 8;
        float4 u0 = reinterpret_cast<const float4*>(p)[0];
        float4 u1 = reinterpret_cast<const float4*>(p)[1];
        float d[8] = {u0.x - mloc[0], u0.y - mloc[1], u0.z - mloc[2], u0.w - mloc[3],
                      u1.x - mloc[4], u1.y - mloc[5], u1.z - mloc[6], u1.w - mloc[7]};
        float dm = d[0];
#pragma unroll
        for (int j = 1; j < 8; j++) dm = fmaxf(dm, d[j]);
        if (dm > THRESH) {
#pragma unroll
            for (int j = 0; j < 8; j++)
                if (d[j] > THRESH) z[j] += __expf(d[j]);
        }
    }
#pragma unroll
    for (int j = 0; j < 8; j++) red[rb][cg * 8 + j] = z[j];
    __syncthreads();
    if (tid < 128) {
        float s = 0.f;
#pragma unroll
        for (int r = 0; r < 16; r++) s += red[r][tid];
        g_pz[blockIdx.y * SEQ + t0 + tid] = s;
    }
}

// K5: 1/Z (fixed-order sum: deterministic, no float atomics anywhere)
__global__ void rz_kernel()
{
    const int t = blockIdx.x * 256 + threadIdx.x;
    float s = 0.f;
#pragma unroll 8
    for (int i = 0; i < NT; i++) s += g_pz[i * SEQ + t];
    g_rz[t] = 1.0f / s;
}

// ============================================================
// K6: out = P @ (V / Z), P[s,t] = exp(sc[s,t] - m_t) on the fly.
//     BM=64, N=128, BK=8; tile-skip when P-chunk is all zero.
// ============================================================
__global__ __launch_bounds__(256) void pv_kernel(float* __restrict__ out)
{
    __shared__ float s_m[SEQ];   // 32 KB: full column-max vector
    __shared__ float sA[8][64];
    __shared__ float sB[8][128];
    const int s0 = blockIdx.x * 64;
    const int tid = threadIdx.x;
    const int tx = tid & 15, ty = tid >> 4;
    const int ar = tid >> 2, ac = (tid & 3) * 2;
    const int br = tid >> 5, bc = (tid & 31) * 4;

    for (int i = tid * 4; i < SEQ; i += 1024)
        *reinterpret_cast<float4*>(&s_m[i]) = *reinterpret_cast<const float4*>(&g_m[i]);

    float acc[4][8];
#pragma unroll
    for (int i = 0; i < 4; i++)
#pragma unroll
        for (int j = 0; j < 8; j++) acc[i][j] = 0.f;

    const float* sp = g_sc + (size_t)(s0 + ar) * SEQ + ac;
    __syncthreads();

    for (int k0 = 0; k0 < SEQ; k0 += 8) {
        float2 sv = *reinterpret_cast<const float2*>(sp + k0);
        float d0 = sv.x - s_m[k0 + ac];
        float d1 = sv.y - s_m[k0 + ac + 1];
        float rzv = g_rz[k0 + br];
        float4 bv = *reinterpret_cast<const float4*>(g_v + (size_t)(k0 + br) * DK + bc);
        float p0 = 0.f, p1 = 0.f;
        if (fmaxf(d0, d1) > THRESH) {        // branch: skip MUFU for the ~99% dead region
            if (d0 > THRESH) p0 = __expf(d0);
            if (d1 > THRESH) p1 = __expf(d1);
        }
        __syncthreads();                      // WAR guard on sA/sB
        sA[ac][ar] = p0;
        sA[ac + 1][ar] = p1;
        *reinterpret_cast<float4*>(&sB[br][bc]) =
            make_float4(bv.x * rzv, bv.y * rzv, bv.z * rzv, bv.w * rzv);
        int active = __syncthreads_or(p0 != 0.f || p1 != 0.f);
        if (active) {                         // uniform across block
#pragma unroll
            for (int kk = 0; kk < 8; kk++) {
                float4 a  = *reinterpret_cast<const float4*>(&sA[kk][ty * 4]);
                float4 b0 = *reinterpret_cast<const float4*>(&sB[kk][tx * 8]);
                float4 b1 = *reinterpret_cast<const float4*>(&sB[kk][tx * 8 + 4]);
                float aa[4] = {a.x, a.y, a.z, a.w};
                float bb[8] = {b0.x, b0.y, b0.z, b0.w, b1.x, b1.y, b1.z, b1.w};
#pragma unroll
                for (int i = 0; i < 4; i++)
#pragma unroll
                    for (int j = 0; j < 8; j++) acc[i][j] += aa[i] * bb[j];
            }
        }
    }
#pragma unroll
    for (int i = 0; i < 4; i++) {
        float* op = out + (size_t)(s0 + ty * 4 + i) * DK + tx * 8;
        *reinterpret_cast<float4*>(op)     = make_float4(acc[i][0], acc[i][1], acc[i][2], acc[i][3]);
        *reinterpret_cast<float4*>(op + 4) = make_float4(acc[i][4], acc[i][5], acc[i][6], acc[i][7]);
    }
}

// ============================================================
extern "C" void kernel_launch(void* const* d_in, const int* in_sizes, int n_in,
                              void* d_out, int out_size)
{
    const float* x  = (const float*)d_in[0];
    const float* wq = (const float*)d_in[1];
    const float* wk = (const float*)d_in[2];
    const float* wv = (const float*)d_in[3];
    float* out = (float*)d_out;

    qkv_mma_kernel<<<dim3(SEQ / 128, 3), 256>>>(x, wq, wk, wv);
    scores_mma_kernel<<<dim3(NT, NT), 256>>>();
    colmax_kernel<<<SEQ / 256, 256>>>();
    zsum_kernel<<<dim3(NT, NT), 256>>>();
    rz_kernel<<<SEQ / 256, 256>>>();
    pv_kernel<<<SEQ / 64, 256>>>(out);
}

// round 3
// speedup vs baseline: 2.5339x; 2.5102x over previous
#include <cuda_runtime.h>
#include <cuda_bf16.h>
#include <cstdint>

#define SEQ 8192
#define CTX 2048
#define DK  128
#define NT  64                    // SEQ / 128
#define SPLIT 32
#define TCH (SEQ / SPLIT)         // 256 t-columns per pv block
#define SCALE 11.313708498984760f // sqrt(128)
#define THRESH -25.0f             // exp(-25) ~ 1.4e-11, negligible vs Z >= 1

// ---- scratch (device globals: allocation-free per harness rules) ----
__device__ float g_q[SEQ * DK];
__device__ float g_k[SEQ * DK];
__device__ float g_v[SEQ * DK];
__device__ float g_sc[(size_t)SEQ * SEQ];     // 256 MB fp32 scores
__device__ float g_pm[NT * SEQ];              // per s-tile column max partials
__device__ float g_pz[NT * SEQ];              // per s-tile column sum partials
__device__ float g_m[SEQ];                    // column max
__device__ float g_rz[SEQ];                   // 1 / column sum
__device__ float g_po[SPLIT][SEQ * DK];       // 128 MB pv split-K partials

// ============================================================
// bf16-pair helpers (3-pass fp32 emulation: AhBh + AhBl + AlBh)
// ============================================================
// pack (x0 -> low half, x1 -> high half), hi = rn-bf16, lo = rn-bf16(residual)
__device__ __forceinline__ uint2 split2(float x0, float x1) {
    uint32_t h, l;
    asm("cvt.rn.bf16x2.f32 %0, %1, %2;" : "=r"(h) : "f"(x1), "f"(x0));
    float h0 = __uint_as_float(h << 16);
    float h1 = __uint_as_float(h & 0xffff0000u);
    asm("cvt.rn.bf16x2.f32 %0, %1, %2;" : "=r"(l) : "f"(x1 - h1), "f"(x0 - h0));
    return make_uint2(h, l);
}

__device__ __forceinline__ void mma16(float* c, const uint32_t* a, const uint32_t* b) {
    asm("mma.sync.aligned.m16n8k16.row.col.f32.bf16.bf16.f32 "
        "{%0,%1,%2,%3}, {%4,%5,%6,%7}, {%8,%9}, {%0,%1,%2,%3};"
        : "+f"(c[0]), "+f"(c[1]), "+f"(c[2]), "+f"(c[3])
        : "r"(a[0]), "r"(a[1]), "r"(a[2]), "r"(a[3]), "r"(b[0]), "r"(b[1]));
}

// 3-pass product into acc: uses hi/lo planes in .x/.y of the uint2 frags
__device__ __forceinline__ void mma3(float* c, const uint2 A0, const uint2 A1,
                                     const uint2 A2, const uint2 A3,
                                     const uint2 B0, const uint2 B1) {
    uint32_t ah[4] = {A0.x, A1.x, A2.x, A3.x};
    uint32_t al[4] = {A0.y, A1.y, A2.y, A3.y};
    uint32_t bh[2] = {B0.x, B1.x};
    uint32_t bl[2] = {B0.y, B1.y};
    mma16(c, ah, bh);
    mma16(c, ah, bl);
    mma16(c, al, bh);
}

// ============================================================
// K1: Q/K/V = x @ w  (bf16-pair MMA). BM=128, BN=128(=DK), BK=16.
// grid (64, 3), 256 threads (8 warps, warp tile 64x32)
// ============================================================
__global__ __launch_bounds__(256) void qkv_mma_kernel(
    const float* __restrict__ x, const float* __restrict__ wq,
    const float* __restrict__ wk, const float* __restrict__ wv)
{
    __shared__ uint2 sA[128][10];   // [m][kpair] (hi2, lo2), pad to 10
    __shared__ uint2 sB[8][132];    // [kpair][n]

    const int m0 = blockIdx.x * 128;
    const float* __restrict__ w = (blockIdx.y == 0) ? wq : (blockIdx.y == 1) ? wk : wv;
    float* out = (blockIdx.y == 0) ? g_q : (blockIdx.y == 1) ? g_k : g_v;

    const int tid = threadIdx.x;
    const int wid = tid >> 5, lane = tid & 31;
    const int g = lane >> 2, tg = lane & 3;
    const int wm = (wid & 1) * 64;
    const int wn = (wid >> 1) * 32;

    const int fr = tid >> 1, fk = (tid & 1) * 4;   // A fill: 128 rows x 4 kpairs
    const int kp = tid >> 5, n4 = (tid & 31) * 4;  // B fill: 8 kpairs x 128 n

    float acc[4][4][4];
#pragma unroll
    for (int i = 0; i < 4; i++)
#pragma unroll
        for (int j = 0; j < 4; j++)
#pragma unroll
            for (int q = 0; q < 4; q++) acc[i][j][q] = 0.f;

    const float* gx = x + (size_t)(m0 + fr) * CTX + fk * 2;
    const float* gw0 = w + (size_t)(2 * kp) * DK + n4;
    const float* gw1 = w + (size_t)(2 * kp + 1) * DK + n4;

    float4 a0 = *reinterpret_cast<const float4*>(gx);
    float4 a1 = *reinterpret_cast<const float4*>(gx + 4);
    float4 b0 = *reinterpret_cast<const float4*>(gw0);
    float4 b1 = *reinterpret_cast<const float4*>(gw1);

    for (int kc = 0; kc < CTX / 16; kc++) {
        __syncthreads();
        {
            uint2 e0 = split2(a0.x, a0.y), e1 = split2(a0.z, a0.w);
            uint2 e2 = split2(a1.x, a1.y), e3 = split2(a1.z, a1.w);
            uint4* d = reinterpret_cast<uint4*>(&sA[fr][fk]);
            d[0] = make_uint4(e0.x, e0.y, e1.x, e1.y);
            d[1] = make_uint4(e2.x, e2.y, e3.x, e3.y);
            uint2 f0 = split2(b0.x, b1.x), f1 = split2(b0.y, b1.y);
            uint2 f2 = split2(b0.z, b1.z), f3 = split2(b0.w, b1.w);
            uint4* e = reinterpret_cast<uint4*>(&sB[kp][n4]);
            e[0] = make_uint4(f0.x, f0.y, f1.x, f1.y);
            e[1] = make_uint4(f2.x, f2.y, f3.x, f3.y);
        }
        __syncthreads();
        if (kc + 1 < CTX / 16) {
            const float* pa = gx + (kc + 1) * 16;
            a0 = *reinterpret_cast<const float4*>(pa);
            a1 = *reinterpret_cast<const float4*>(pa + 4);
            b0 = *reinterpret_cast<const float4*>(gw0 + (size_t)(kc + 1) * 16 * DK);
            b1 = *reinterpret_cast<const float4*>(gw1 + (size_t)(kc + 1) * 16 * DK);
        }
        uint2 A[4][4];
#pragma unroll
        for (int mt = 0; mt < 4; mt++) {
            const int r = wm + mt * 16 + g;
            A[mt][0] = sA[r][tg];     A[mt][1] = sA[r + 8][tg];
            A[mt][2] = sA[r][4 + tg]; A[mt][3] = sA[r + 8][4 + tg];
        }
#pragma unroll
        for (int nt = 0; nt < 4; nt++) {
            const int c = wn + nt * 8 + g;
            uint2 B0 = sB[tg][c], B1 = sB[4 + tg][c];
#pragma unroll
            for (int mt = 0; mt < 4; mt++)
                mma3(acc[mt][nt], A[mt][0], A[mt][1], A[mt][2], A[mt][3], B0, B1);
        }
    }

#pragma unroll
    for (int mt = 0; mt < 4; mt++) {
#pragma unroll
        for (int nt = 0; nt < 4; nt++) {
            const int r0 = m0 + wm + mt * 16 + g;
            const int col = wn + nt * 8 + 2 * tg;
            *reinterpret_cast<float2*>(out + (size_t)r0 * DK + col) =
                make_float2(acc[mt][nt][0], acc[mt][nt][1]);
            *reinterpret_cast<float2*>(out + (size_t)(r0 + 8) * DK + col) =
                make_float2(acc[mt][nt][2], acc[mt][nt][3]);
        }
    }
}

// ============================================================
// K2: scores = (Q @ K^T) * SCALE (bf16-pair MMA) + column-max partials.
// BM=128(s), BN=128(t), K=DK, BK=16. grid (NT, NT), 256 thr.
// ============================================================
__global__ __launch_bounds__(256) void scores_mma_kernel()
{
    __shared__ uint2 sQ[128][10];
    __shared__ uint2 sK[128][10];
    __shared__ float colred[2][128];

    const int t0 = blockIdx.x * 128, s0 = blockIdx.y * 128;
    const int tid = threadIdx.x;
    const int wid = tid >> 5, lane = tid & 31;
    const int g = lane >> 2, tg = lane & 3;
    const int wm = (wid & 1) * 64;
    const int wn = (wid >> 1) * 32;

    const int fr = tid >> 1, fk = (tid & 1) * 4;

    float acc[4][4][4];
#pragma unroll
    for (int i = 0; i < 4; i++)
#pragma unroll
        for (int j = 0; j < 4; j++)
#pragma unroll
            for (int q = 0; q < 4; q++) acc[i][q][0] = 0.f, acc[i][q][1] = 0.f,
                                        acc[i][q][2] = 0.f, acc[i][q][3] = 0.f;

    const float* gq = g_q + (size_t)(s0 + fr) * DK + fk * 2;
    const float* gk = g_k + (size_t)(t0 + fr) * DK + fk * 2;

    float4 qa = *reinterpret_cast<const float4*>(gq);
    float4 qb = *reinterpret_cast<const float4*>(gq + 4);
    float4 ka = *reinterpret_cast<const float4*>(gk);
    float4 kb = *reinterpret_cast<const float4*>(gk + 4);

    for (int kc = 0; kc < DK / 16; kc++) {
        __syncthreads();
        {
            uint2 e0 = split2(qa.x, qa.y), e1 = split2(qa.z, qa.w);
            uint2 e2 = split2(qb.x, qb.y), e3 = split2(qb.z, qb.w);
            uint4* d = reinterpret_cast<uint4*>(&sQ[fr][fk]);
            d[0] = make_uint4(e0.x, e0.y, e1.x, e1.y);
            d[1] = make_uint4(e2.x, e2.y, e3.x, e3.y);
            uint2 f0 = split2(ka.x, ka.y), f1 = split2(ka.z, ka.w);
            uint2 f2 = split2(kb.x, kb.y), f3 = split2(kb.z, kb.w);
            uint4* e = reinterpret_cast<uint4*>(&sK[fr][fk]);
            e[0] = make_uint4(f0.x, f0.y, f1.x, f1.y);
            e[1] = make_uint4(f2.x, f2.y, f3.x, f3.y);
        }
        __syncthreads();
        if (kc + 1 < DK / 16) {
            const float* pq = gq + (kc + 1) * 16;
            const float* pk = gk + (kc + 1) * 16;
            qa = *reinterpret_cast<const float4*>(pq);
            qb = *reinterpret_cast<const float4*>(pq + 4);
            ka = *reinterpret_cast<const float4*>(pk);
            kb = *reinterpret_cast<const float4*>(pk + 4);
        }
        uint2 A[4][4];
#pragma unroll
        for (int mt = 0; mt < 4; mt++) {
            const int r = wm + mt * 16 + g;
            A[mt][0] = sQ[r][tg];     A[mt][1] = sQ[r + 8][tg];
            A[mt][2] = sQ[r][4 + tg]; A[mt][3] = sQ[r + 8][4 + tg];
        }
#pragma unroll
        for (int nt = 0; nt < 4; nt++) {
            const int c = wn + nt * 8 + g;
            uint2 B0 = sK[c][tg], B1 = sK[c][4 + tg];
#pragma unroll
            for (int mt = 0; mt < 4; mt++)
                mma3(acc[mt][nt], A[mt][0], A[mt][1], A[mt][2], A[mt][3], B0, B1);
        }
    }

    // epilogue: scale, store fp32 scores, column (over-s) max partials
    float cm[8];
#pragma unroll
    for (int j = 0; j < 8; j++) cm[j] = -3.4e38f;

#pragma unroll
    for (int mt = 0; mt < 4; mt++) {
#pragma unroll
        for (int nt = 0; nt < 4; nt++) {
            float v0 = acc[mt][nt][0] * SCALE;
            float v1 = acc[mt][nt][1] * SCALE;
            float v2 = acc[mt][nt][2] * SCALE;
            float v3 = acc[mt][nt][3] * SCALE;
            const int r0 = s0 + wm + mt * 16 + g;
            const int col = t0 + wn + nt * 8 + 2 * tg;
            *reinterpret_cast<float2*>(g_sc + (size_t)r0 * SEQ + col) = make_float2(v0, v1);
            *reinterpret_cast<float2*>(g_sc + (size_t)(r0 + 8) * SEQ + col) = make_float2(v2, v3);
            cm[nt * 2 + 0] = fmaxf(cm[nt * 2 + 0], fmaxf(v0, v2));
            cm[nt * 2 + 1] = fmaxf(cm[nt * 2 + 1], fmaxf(v1, v3));
        }
    }
#pragma unroll
    for (int off = 4; off < 32; off <<= 1)
#pragma unroll
        for (int j = 0; j < 8; j++)
            cm[j] = fmaxf(cm[j], __shfl_xor_sync(0xffffffffu, cm[j], off));

    if (g == 0) {
#pragma unroll
        for (int nt = 0; nt < 4; nt++) {
            colred[wid & 1][wn + nt * 8 + 2 * tg + 0] = cm[nt * 2 + 0];
            colred[wid & 1][wn + nt * 8 + 2 * tg + 1] = cm[nt * 2 + 1];
        }
    }
    __syncthreads();
    if (tid < 128)
        g_pm[blockIdx.y * SEQ + t0 + tid] = fmaxf(colred[0][tid], colred[1][tid]);
}

// K3: combine column max over 64 s-tiles (fixed order: deterministic)
__global__ void colmax_kernel()
{
    const int t = blockIdx.x * 256 + threadIdx.x;
    float m = -3.4e38f;
#pragma unroll 8
    for (int i = 0; i < NT; i++) m = fmaxf(m, g_pm[i * SEQ + t]);
    g_m[t] = m;
}

// ============================================================
// K4: Z partials: per (s-tile, t) sum of exp(sc - m_t), skip-heavy
// ============================================================
__global__ __launch_bounds__(256) void zsum_kernel()
{
    __shared__ float s_m[128];
    __shared__ float red[16][128];
    const int t0 = blockIdx.x * 128, s0 = blockIdx.y * 128;
    const int tid = threadIdx.x;
    if (tid < 128) s_m[tid] = g_m[t0 + tid];
    __syncthreads();
    const int cg = tid & 15, rb = tid >> 4;
    float mloc[8];
#pragma unroll
    for (int j = 0; j < 8; j++) mloc[j] = s_m[cg * 8 + j];
    float z[8];
#pragma unroll
    for (int j = 0; j < 8; j++) z[j] = 0.f;

    for (int rr = 0; rr < 8; rr++) {
        const int r = rb + rr * 16;
        const float* p = g_sc + (size_t)(s0 + r) * SEQ + t0 + cg * 8;
        float4 u0 = reinterpret_cast<const float4*>(p)[0];
        float4 u1 = reinterpret_cast<const float4*>(p)[1];
        float d[8] = {u0.x - mloc[0], u0.y - mloc[1], u0.z - mloc[2], u0.w - mloc[3],
                      u1.x - mloc[4], u1.y - mloc[5], u1.z - mloc[6], u1.w - mloc[7]};
        float dm = d[0];
#pragma unroll
        for (int j = 1; j < 8; j++) dm = fmaxf(dm, d[j]);
        if (dm > THRESH) {
#pragma unroll
            for (int j = 0; j < 8; j++)
                if (d[j] > THRESH) z[j] += __expf(d[j]);
        }
    }
#pragma unroll
    for (int j = 0; j < 8; j++) red[rb][cg * 8 + j] = z[j];
    __syncthreads();
    if (tid < 128) {
        float s = 0.f;
#pragma unroll
        for (int r = 0; r < 16; r++) s += red[r][tid];
        g_pz[blockIdx.y * SEQ + t0 + tid] = s;
    }
}

// K5: 1/Z (fixed-order sum: deterministic, no float atomics anywhere)
__global__ void rz_kernel()
{
    const int t = blockIdx.x * 256 + threadIdx.x;
    float s = 0.f;
#pragma unroll 8
    for (int i = 0; i < NT; i++) s += g_pz[i * SEQ + t];
    g_rz[t] = 1.0f / s;
}

// ============================================================
// K6: split-K PV. grid (SPLIT, SEQ/64). Each block: 64 s-rows x
//     TCH=256 t-cols -> fp32 partial [64 x 128] into g_po[split].
//     Tile-skip when the 64x8 P-chunk is all ~zero.
// ============================================================
__global__ __launch_bounds__(256) void pv_kernel()
{
    __shared__ float s_m[TCH];
    __shared__ float s_rz[TCH];
    __shared__ float sA[8][64];
    __shared__ float sB[8][128];
    const int s0 = blockIdx.y * 64;
    const int tb = blockIdx.x * TCH;
    const int tid = threadIdx.x;
    const int tx = tid & 15, ty = tid >> 4;
    const int ar = tid >> 2, ac = (tid & 3) * 2;
    const int br = tid >> 5, bc = (tid & 31) * 4;

    s_m[tid] = g_m[tb + tid];        // 256 threads == TCH
    s_rz[tid] = g_rz[tb + tid];

    float acc[4][8];
#pragma unroll
    for (int i = 0; i < 4; i++)
#pragma unroll
        for (int j = 0; j < 8; j++) acc[i][j] = 0.f;

    const float* sp = g_sc + (size_t)(s0 + ar) * SEQ + tb + ac;
    __syncthreads();

    for (int k0 = 0; k0 < TCH; k0 += 8) {
        float2 sv = *reinterpret_cast<const float2*>(sp + k0);
        float d0 = sv.x - s_m[k0 + ac];
        float d1 = sv.y - s_m[k0 + ac + 1];
        float rzv = s_rz[k0 + br];
        float4 bv = *reinterpret_cast<const float4*>(g_v + (size_t)(tb + k0 + br) * DK + bc);
        float p0 = 0.f, p1 = 0.f;
        if (fmaxf(d0, d1) > THRESH) {
            if (d0 > THRESH) p0 = __expf(d0);
            if (d1 > THRESH) p1 = __expf(d1);
        }
        __syncthreads();                      // WAR guard on sA/sB
        sA[ac][ar] = p0;
        sA[ac + 1][ar] = p1;
        *reinterpret_cast<float4*>(&sB[br][bc]) =
            make_float4(bv.x * rzv, bv.y * rzv, bv.z * rzv, bv.w * rzv);
        int active = __syncthreads_or(p0 != 0.f || p1 != 0.f);
        if (active) {
#pragma unroll
            for (int kk = 0; kk < 8; kk++) {
                float4 a  = *reinterpret_cast<const float4*>(&sA[kk][ty * 4]);
                float4 b0 = *reinterpret_cast<const float4*>(&sB[kk][tx * 8]);
                float4 b1 = *reinterpret_cast<const float4*>(&sB[kk][tx * 8 + 4]);
                float aa[4] = {a.x, a.y, a.z, a.w};
                float bb[8] = {b0.x, b0.y, b0.z, b0.w, b1.x, b1.y, b1.z, b1.w};
#pragma unroll
                for (int i = 0; i < 4; i++)
#pragma unroll
                    for (int j = 0; j < 8; j++) acc[i][j] += aa[i] * bb[j];
            }
        }
    }
    float* po = g_po[blockIdx.x];
#pragma unroll
    for (int i = 0; i < 4; i++) {
        float* op = po + (size_t)(s0 + ty * 4 + i) * DK + tx * 8;
        *reinterpret_cast<float4*>(op)     = make_float4(acc[i][0], acc[i][1], acc[i][2], acc[i][3]);
        *reinterpret_cast<float4*>(op + 4) = make_float4(acc[i][4], acc[i][5], acc[i][6], acc[i][7]);
    }
}

// K7: fixed-order split reduction (deterministic)
__global__ void pv_reduce_kernel(float* __restrict__ out)
{
    const int i = blockIdx.x * 256 + threadIdx.x;
    float s = 0.f;
#pragma unroll
    for (int p = 0; p < SPLIT; p++) s += g_po[p][i];
    out[i] = s;
}

// ============================================================
extern "C" void kernel_launch(void* const* d_in, const int* in_sizes, int n_in,
                              void* d_out, int out_size)
{
    const float* x  = (const float*)d_in[0];
    const float* wq = (const float*)d_in[1];
    const float* wk = (const float*)d_in[2];
    const float* wv = (const float*)d_in[3];
    float* out = (float*)d_out;

    qkv_mma_kernel<<<dim3(SEQ / 128, 3), 256>>>(x, wq, wk, wv);
    scores_mma_kernel<<<dim3(NT, NT), 256>>>();
    colmax_kernel<<<SEQ / 256, 256>>>();
    zsum_kernel<<<dim3(NT, NT), 256>>>();
    rz_kernel<<<SEQ / 256, 256>>>();
    pv_kernel<<<dim3(SPLIT, SEQ / 64), 256>>>();
    pv_reduce_kernel<<<SEQ * DK / 256, 256>>>(out);
}

// round 5
// speedup vs baseline: 3.1817x; 1.2556x over previous
#include <cuda_runtime.h>
#include <cuda_fp16.h>
#include <cstdint>

#define SEQ 8192
#define CTX 2048
#define DK  128
#define NT  64                    // SEQ / 128 score tiles
#define SPLIT 16
#define TCH (SEQ / SPLIT)         // 512 t-columns per pv block
#define SCALE 11.313708498984760f // sqrt(128)
#define THRESH -25.0f             // exp(-25) ~ 1.4e-11, negligible vs Z >= 1

// ---- scratch (device globals: allocation-free per harness rules) ----
__device__ uint2  g_xp[(size_t)SEQ * (CTX / 2)];   // x in bf16-pair format (64 MB)
__device__ uint2  g_wp[3][DK][CTX / 2];            // w^T pair format (3 MB)
__device__ uint2  g_qp[(size_t)SEQ * (DK / 2)];    // q pair (4 MB)
__device__ uint2  g_kp[(size_t)SEQ * (DK / 2)];    // k pair (4 MB)
__device__ float  g_v[SEQ * DK];
__device__ __half g_sch[(size_t)SEQ * SEQ];        // 128 MB fp16 (sc - m_tile)
__device__ float  g_pm[NT * SEQ];                  // per-tile column max (scaled)
__device__ float  g_pzt[NT * SEQ];                 // per-tile column sum exp(sc - m_tile)
__device__ float  g_m[SEQ];                        // global column max
__device__ float  g_rz[SEQ];                       // 1 / Z_t
__device__ float  g_po[SPLIT][SEQ * DK];           // pv split-K partials (64 MB)

// ============================================================
// helpers
// ============================================================
__device__ __forceinline__ uint32_t smem_u32(const void* p) {
    uint32_t a;
    asm("{ .reg .u64 t; cvta.to.shared.u64 t, %1; cvt.u32.u64 %0, t; }" : "=r"(a) : "l"(p));
    return a;
}
__device__ __forceinline__ void cp16(uint32_t dst, const void* src) {
    asm volatile("cp.async.cg.shared.global [%0], [%1], 16;" :: "r"(dst), "l"(src));
}
#define CP_COMMIT asm volatile("cp.async.commit_group;" ::: "memory")
#define CP_WAIT0  asm volatile("cp.async.wait_group 0;" ::: "memory")

// bf16 pair split: pack (x0 -> low half, x1 -> high half); hi=rn-bf16, lo=rn-bf16(residual)
__device__ __forceinline__ uint2 split2(float x0, float x1) {
    uint32_t h, l;
    asm("cvt.rn.bf16x2.f32 %0, %1, %2;" : "=r"(h) : "f"(x1), "f"(x0));
    float h0 = __uint_as_float(h << 16);
    float h1 = __uint_as_float(h & 0xffff0000u);
    asm("cvt.rn.bf16x2.f32 %0, %1, %2;" : "=r"(l) : "f"(x1 - h1), "f"(x0 - h0));
    return make_uint2(h, l);
}
__device__ __forceinline__ void mma16(float* c, const uint32_t* a, const uint32_t* b) {
    asm("mma.sync.aligned.m16n8k16.row.col.f32.bf16.bf16.f32 "
        "{%0,%1,%2,%3}, {%4,%5,%6,%7}, {%8,%9}, {%0,%1,%2,%3};"
        : "+f"(c[0]), "+f"(c[1]), "+f"(c[2]), "+f"(c[3])
        : "r"(a[0]), "r"(a[1]), "r"(a[2]), "r"(a[3]), "r"(b[0]), "r"(b[1]));
}
// 3-pass product (AhBh + AhBl + AlBh); frag uint2 = (hi bf16x2, lo bf16x2)
__device__ __forceinline__ void mma3(float* c, const uint2 A0, const uint2 A1,
                                     const uint2 A2, const uint2 A3,
                                     const uint2 B0, const uint2 B1) {
    uint32_t ah[4] = {A0.x, A1.x, A2.x, A3.x};
    uint32_t al[4] = {A0.y, A1.y, A2.y, A3.y};
    uint32_t bh[2] = {B0.x, B1.x};
    uint32_t bl[2] = {B0.y, B1.y};
    mma16(c, ah, bh);
    mma16(c, ah, bl);
    mma16(c, al, bh);
}

// ============================================================
// K0a: convert x to pair format
// ============================================================
__global__ __launch_bounds__(256) void cvt_x_kernel(const float* __restrict__ x)
{
    const int i = blockIdx.x * 256 + threadIdx.x;       // < SEQ*CTX/4
    float4 v = reinterpret_cast<const float4*>(x)[i];
    g_xp[2 * (size_t)i]     = split2(v.x, v.y);
    g_xp[2 * (size_t)i + 1] = split2(v.z, v.w);
}

// K0b: convert w (transposed: [n][kpair]) to pair format
__global__ __launch_bounds__(256) void cvt_w_kernel(
    const float* __restrict__ wq, const float* __restrict__ wk, const float* __restrict__ wv)
{
    const int i = blockIdx.x * 256 + threadIdx.x;       // < 3*DK*CTX/2
    const int mat = i / (DK * CTX / 2);
    const int r = i % (DK * CTX / 2);
    const int n = r / (CTX / 2);
    const int kp = r % (CTX / 2);
    const float* w = (mat == 0) ? wq : (mat == 1) ? wk : wv;
    g_wp[mat][n][kp] = split2(w[(size_t)(2 * kp) * DK + n], w[(size_t)(2 * kp + 1) * DK + n]);
}

// ============================================================
// K1: Q/K/V = x @ w. M-tile 64, N=128, BK=16, cp.async double-buffered.
// grid (128, 3), 256 threads, 8 warps (2m x 4n), warp tile 32x32.
// q/k written in pair format; v in fp32.
// ============================================================
__global__ __launch_bounds__(256, 2) void qkv_kernel()
{
    __shared__ uint2 sA[2][64][10];
    __shared__ uint2 sB[2][128][10];

    const int m0 = blockIdx.x * 64;
    const int mat = blockIdx.y;
    const int tid = threadIdx.x;
    const int wid = tid >> 5, lane = tid & 31;
    const int g = lane >> 2, tg = lane & 3;
    const int wm = (wid & 1) * 32;
    const int wn = (wid >> 1) * 32;

    float acc[2][4][4];
#pragma unroll
    for (int i = 0; i < 2; i++)
#pragma unroll
        for (int j = 0; j < 4; j++)
#pragma unroll
            for (int q = 0; q < 4; q++) acc[i][j][q] = 0.f;

    const int arow = tid >> 2, aq = tid & 3;            // A: 64 rows x 4 16B-chunks
    const uint2* gA = &g_xp[(size_t)(m0 + arow) * (CTX / 2)];
    const uint2* gB = &g_wp[mat][0][0];

#define QKV_ISSUE(kc, buf)                                                          \
    do {                                                                            \
        cp16(smem_u32(&sA[buf][arow][aq * 2]), gA + (kc) * 8 + aq * 2);             \
        _Pragma("unroll")                                                           \
        for (int j = 0; j < 2; j++) {                                               \
            int idx = tid + j * 256;                                                \
            int br = idx >> 2, bq = idx & 3;                                        \
            cp16(smem_u32(&sB[buf][br][bq * 2]),                                    \
                 gB + (size_t)br * (CTX / 2) + (kc) * 8 + bq * 2);                  \
        }                                                                           \
    } while (0)

    QKV_ISSUE(0, 0);
    CP_COMMIT;
    const int NC = CTX / 16;
    for (int kc = 0; kc < NC; kc++) {
        CP_WAIT0;
        __syncthreads();
        if (kc + 1 < NC) { QKV_ISSUE(kc + 1, (kc + 1) & 1); CP_COMMIT; }
        const int buf = kc & 1;
        uint2 A[2][4];
#pragma unroll
        for (int mt = 0; mt < 2; mt++) {
            const int r = wm + mt * 16 + g;
            A[mt][0] = sA[buf][r][tg];     A[mt][1] = sA[buf][r + 8][tg];
            A[mt][2] = sA[buf][r][4 + tg]; A[mt][3] = sA[buf][r + 8][4 + tg];
        }
#pragma unroll
        for (int nt = 0; nt < 4; nt++) {
            const int c = wn + nt * 8 + g;
            uint2 B0 = sB[buf][c][tg], B1 = sB[buf][c][4 + tg];
#pragma unroll
            for (int mt = 0; mt < 2; mt++)
                mma3(acc[mt][nt], A[mt][0], A[mt][1], A[mt][2], A[mt][3], B0, B1);
        }
    }

#pragma unroll
    for (int mt = 0; mt < 2; mt++) {
#pragma unroll
        for (int nt = 0; nt < 4; nt++) {
            const int r0 = m0 + wm + mt * 16 + g;
            const int col = wn + nt * 8 + 2 * tg;
            if (mat == 2) {
                *reinterpret_cast<float2*>(g_v + (size_t)r0 * DK + col) =
                    make_float2(acc[mt][nt][0], acc[mt][nt][1]);
                *reinterpret_cast<float2*>(g_v + (size_t)(r0 + 8) * DK + col) =
                    make_float2(acc[mt][nt][2], acc[mt][nt][3]);
            } else {
                uint2* dst = (mat == 0) ? g_qp : g_kp;
                dst[(size_t)r0 * (DK / 2) + col / 2] = split2(acc[mt][nt][0], acc[mt][nt][1]);
                dst[(size_t)(r0 + 8) * (DK / 2) + col / 2] = split2(acc[mt][nt][2], acc[mt][nt][3]);
            }
        }
    }
#undef QKV_ISSUE
}

// ============================================================
// K2: scores tile 128(s) x 128(t), K=128, BK=16, double-buffered.
// Fused epilogue: store fp16 (sc*SCALE - m_tile), per-tile col max + Z partials.
// grid (NT, NT), 256 threads, 8 warps (2m x 4n), warp tile 64x32.
// ============================================================
__global__ __launch_bounds__(256, 2) void scores_kernel()
{
    __shared__ uint2 sQ[2][128][10];
    __shared__ uint2 sK[2][128][10];
    __shared__ float s_red[2][128];

    const int t0 = blockIdx.x * 128, s0 = blockIdx.y * 128;
    const int tid = threadIdx.x;
    const int wid = tid >> 5, lane = tid & 31;
    const int g = lane >> 2, tg = lane & 3;
    const int wm = (wid & 1) * 64;
    const int wn = (wid >> 1) * 32;

    float acc[4][4][4];
#pragma unroll
    for (int i = 0; i < 4; i++)
#pragma unroll
        for (int j = 0; j < 4; j++)
#pragma unroll
            for (int q = 0; q < 4; q++) acc[i][j][q] = 0.f;

#define SC_ISSUE(kc, buf)                                                           \
    do {                                                                            \
        _Pragma("unroll")                                                           \
        for (int j = 0; j < 2; j++) {                                               \
            int idx = tid + j * 256;                                                \
            int row = idx >> 2, q = idx & 3;                                        \
            cp16(smem_u32(&sQ[buf][row][q * 2]),                                    \
                 g_qp + (size_t)(s0 + row) * 64 + (kc) * 8 + q * 2);                \
            cp16(smem_u32(&sK[buf][row][q * 2]),                                    \
                 g_kp + (size_t)(t0 + row) * 64 + (kc) * 8 + q * 2);                \
        }                                                                           \
    } while (0)

    SC_ISSUE(0, 0);
    CP_COMMIT;
    const int NC = DK / 16;   // 8
    for (int kc = 0; kc < NC; kc++) {
        CP_WAIT0;
        __syncthreads();
        if (kc + 1 < NC) { SC_ISSUE(kc + 1, (kc + 1) & 1); CP_COMMIT; }
        const int buf = kc & 1;
        uint2 A[4][4];
#pragma unroll
        for (int mt = 0; mt < 4; mt++) {
            const int r = wm + mt * 16 + g;
            A[mt][0] = sQ[buf][r][tg];     A[mt][1] = sQ[buf][r + 8][tg];
            A[mt][2] = sQ[buf][r][4 + tg]; A[mt][3] = sQ[buf][r + 8][4 + tg];
        }
#pragma unroll
        for (int nt = 0; nt < 4; nt++) {
            const int c = wn + nt * 8 + g;
            uint2 B0 = sK[buf][c][tg], B1 = sK[buf][c][4 + tg];
#pragma unroll
            for (int mt = 0; mt < 4; mt++)
                mma3(acc[mt][nt], A[mt][0], A[mt][1], A[mt][2], A[mt][3], B0, B1);
        }
    }
#undef SC_ISSUE

    // ---- epilogue ----
#pragma unroll
    for (int mt = 0; mt < 4; mt++)
#pragma unroll
        for (int nt = 0; nt < 4; nt++)
#pragma unroll
            for (int q = 0; q < 4; q++) acc[mt][nt][q] *= SCALE;

    // per-lane column max over this warp-half's 64 rows (cols: nt x parity)
    float lmax[8];
#pragma unroll
    for (int nt = 0; nt < 4; nt++) {
        float m0v = -3.4e38f, m1v = -3.4e38f;
#pragma unroll
        for (int mt = 0; mt < 4; mt++) {
            m0v = fmaxf(m0v, fmaxf(acc[mt][nt][0], acc[mt][nt][2]));
            m1v = fmaxf(m1v, fmaxf(acc[mt][nt][1], acc[mt][nt][3]));
        }
        lmax[nt * 2] = m0v; lmax[nt * 2 + 1] = m1v;
    }
#pragma unroll
    for (int off = 4; off < 32; off <<= 1)
#pragma unroll
        for (int j = 0; j < 8; j++)
            lmax[j] = fmaxf(lmax[j], __shfl_xor_sync(0xffffffffu, lmax[j], off));
    if (g == 0) {
#pragma unroll
        for (int nt = 0; nt < 4; nt++) {
            s_red[wid & 1][wn + nt * 8 + 2 * tg + 0] = lmax[nt * 2 + 0];
            s_red[wid & 1][wn + nt * 8 + 2 * tg + 1] = lmax[nt * 2 + 1];
        }
    }
    __syncthreads();
    if (tid < 128)
        g_pm[(s0 >> 7) * SEQ + t0 + tid] = fmaxf(s_red[0][tid], s_red[1][tid]);

    // tile max for this lane's columns
    float mcol[8];
#pragma unroll
    for (int nt = 0; nt < 4; nt++) {
        const int c = wn + nt * 8 + 2 * tg;
        mcol[nt * 2 + 0] = fmaxf(s_red[0][c], s_red[1][c]);
        mcol[nt * 2 + 1] = fmaxf(s_red[0][c + 1], s_red[1][c + 1]);
    }

    // store d = sc - m_tile as fp16; accumulate z = sum exp(d) with skip
    float z[8];
#pragma unroll
    for (int j = 0; j < 8; j++) z[j] = 0.f;
#pragma unroll
    for (int mt = 0; mt < 4; mt++) {
#pragma unroll
        for (int nt = 0; nt < 4; nt++) {
            const int r0 = s0 + wm + mt * 16 + g;
            const int col = t0 + wn + nt * 8 + 2 * tg;
            float d00 = acc[mt][nt][0] - mcol[nt * 2],     d01 = acc[mt][nt][1] - mcol[nt * 2 + 1];
            float d10 = acc[mt][nt][2] - mcol[nt * 2],     d11 = acc[mt][nt][3] - mcol[nt * 2 + 1];
            *reinterpret_cast<__half2*>(&g_sch[(size_t)r0 * SEQ + col]) = __floats2half2_rn(d00, d01);
            *reinterpret_cast<__half2*>(&g_sch[(size_t)(r0 + 8) * SEQ + col]) = __floats2half2_rn(d10, d11);
            z[nt * 2 + 0] += (d00 > THRESH ? __expf(d00) : 0.f) + (d10 > THRESH ? __expf(d10) : 0.f);
            z[nt * 2 + 1] += (d01 > THRESH ? __expf(d01) : 0.f) + (d11 > THRESH ? __expf(d11) : 0.f);
        }
    }
#pragma unroll
    for (int off = 4; off < 32; off <<= 1)
#pragma unroll
        for (int j = 0; j < 8; j++)
            z[j] += __shfl_xor_sync(0xffffffffu, z[j], off);
    __syncthreads();   // all reads of s_red done before overwrite
    if (g == 0) {
#pragma unroll
        for (int nt = 0; nt < 4; nt++) {
            s_red[wid & 1][wn + nt * 8 + 2 * tg + 0] = z[nt * 2 + 0];
            s_red[wid & 1][wn + nt * 8 + 2 * tg + 1] = z[nt * 2 + 1];
        }
    }
    __syncthreads();
    if (tid < 128)
        g_pzt[(s0 >> 7) * SEQ + t0 + tid] = s_red[0][tid] + s_red[1][tid];
}

// ============================================================
// K3: combine tile stats -> global m_t and 1/Z_t (fixed order, deterministic)
// ============================================================
__global__ void combine_kernel()
{
    const int t = blockIdx.x * 256 + threadIdx.x;
    float m = -3.4e38f;
#pragma unroll 8
    for (int b = 0; b < NT; b++) m = fmaxf(m, g_pm[b * SEQ + t]);
    float Z = 0.f;
#pragma unroll 8
    for (int b = 0; b < NT; b++) {
        float d = g_pm[b * SEQ + t] - m;
        if (d > THRESH - 10.f) Z += g_pzt[b * SEQ + t] * __expf(d);
    }
    g_m[t] = m;
    g_rz[t] = 1.0f / Z;
}

// ============================================================
// K4: split-K PV. grid (SPLIT, SEQ/64). 64 s-rows x TCH=512 t-cols.
// P = exp(d_fp16 + (m_tile - m_t)), 1/Z folded into V. Tile-skip on dead P.
// ============================================================
__global__ __launch_bounds__(256) void pv_kernel()
{
    __shared__ float s_adj[TCH];
    __shared__ float s_rz[TCH];
    __shared__ float sA[8][64];
    __shared__ float sB[8][128];
    const int s0 = blockIdx.y * 64;
    const int tb = blockIdx.x * TCH;
    const int b = blockIdx.y >> 1;              // scores s-tile of these 64 rows
    const int tid = threadIdx.x;
    const int tx = tid & 15, ty = tid >> 4;
    const int ar = tid >> 2, ac = (tid & 3) * 2;
    const int br = tid >> 5, bc = (tid & 31) * 4;

#pragma unroll
    for (int j = 0; j < 2; j++) {
        int t = tid + j * 256;
        s_adj[t] = g_pm[b * SEQ + tb + t] - g_m[tb + t];
        s_rz[t] = g_rz[tb + t];
    }

    float acc[4][8];
#pragma unroll
    for (int i = 0; i < 4; i++)
#pragma unroll
        for (int j = 0; j < 8; j++) acc[i][j] = 0.f;

    const __half* sp = g_sch + (size_t)(s0 + ar) * SEQ + tb + ac;
    __syncthreads();

    for (int k0 = 0; k0 < TCH; k0 += 8) {
        __half2 hv = *reinterpret_cast<const __half2*>(sp + k0);
        float2 fv = __half22float2(hv);
        float dd0 = fv.x + s_adj[k0 + ac];
        float dd1 = fv.y + s_adj[k0 + ac + 1];
        float rzv = s_rz[k0 + br];
        float4 bv = *reinterpret_cast<const float4*>(g_v + (size_t)(tb + k0 + br) * DK + bc);
        float p0 = 0.f, p1 = 0.f;
        if (fmaxf(dd0, dd1) > THRESH) {
            if (dd0 > THRESH) p0 = __expf(dd0);
            if (dd1 > THRESH) p1 = __expf(dd1);
        }
        __syncthreads();
        sA[ac][ar] = p0;
        sA[ac + 1][ar] = p1;
        *reinterpret_cast<float4*>(&sB[br][bc]) =
            make_float4(bv.x * rzv, bv.y * rzv, bv.z * rzv, bv.w * rzv);
        int active = __syncthreads_or(p0 != 0.f || p1 != 0.f);
        if (active) {
#pragma unroll
            for (int kk = 0; kk < 8; kk++) {
                float4 a  = *reinterpret_cast<const float4*>(&sA[kk][ty * 4]);
                float4 b0 = *reinterpret_cast<const float4*>(&sB[kk][tx * 8]);
                float4 b1 = *reinterpret_cast<const float4*>(&sB[kk][tx * 8 + 4]);
                float aa[4] = {a.x, a.y, a.z, a.w};
                float bb[8] = {b0.x, b0.y, b0.z, b0.w, b1.x, b1.y, b1.z, b1.w};
#pragma unroll
                for (int i = 0; i < 4; i++)
#pragma unroll
                    for (int j = 0; j < 8; j++) acc[i][j] += aa[i] * bb[j];
            }
        }
    }
    float* po = g_po[blockIdx.x];
#pragma unroll
    for (int i = 0; i < 4; i++) {
        float* op = po + (size_t)(s0 + ty * 4 + i) * DK + tx * 8;
        *reinterpret_cast<float4*>(op)     = make_float4(acc[i][0], acc[i][1], acc[i][2], acc[i][3]);
        *reinterpret_cast<float4*>(op + 4) = make_float4(acc[i][4], acc[i][5], acc[i][6], acc[i][7]);
    }
}

// K5: fixed-order split reduction (deterministic)
__global__ void pv_reduce_kernel(float* __restrict__ out)
{
    const int i = blockIdx.x * 256 + threadIdx.x;
    float s = 0.f;
#pragma unroll
    for (int p = 0; p < SPLIT; p++) s += g_po[p][i];
    out[i] = s;
}

// ============================================================
extern "C" void kernel_launch(void* const* d_in, const int* in_sizes, int n_in,
                              void* d_out, int out_size)
{
    const float* x  = (const float*)d_in[0];
    const float* wq = (const float*)d_in[1];
    const float* wk = (const float*)d_in[2];
    const float* wv = (const float*)d_in[3];
    float* out = (float*)d_out;

    cvt_x_kernel<<<SEQ * CTX / 4 / 256, 256>>>(x);
    cvt_w_kernel<<<3 * DK * (CTX / 2) / 256, 256>>>(wq, wk, wv);
    qkv_kernel<<<dim3(SEQ / 64, 3), 256>>>();
    scores_kernel<<<dim3(NT, NT), 256>>>();
    combine_kernel<<<SEQ / 256, 256>>>();
    pv_kernel<<<dim3(SPLIT, SEQ / 64), 256>>>();
    pv_reduce_kernel<<<SEQ * DK / 256, 256>>>(out);
}

// round 6
// speedup vs baseline: 4.1455x; 1.3029x over previous
#include <cuda_runtime.h>
#include <cuda_fp16.h>
#include <cstdint>

#define SEQ 8192
#define CTX 2048
#define DK  128
#define NT  64                    // SEQ/128 s-tiles
#define SPLIT 16
#define TCH (SEQ / SPLIT)         // 512 t-columns per pv block
#define SCALE 11.313708498984760f
#define THRESH -25.0f

// ---- scratch (device globals) ----
// blocked pair-plane format: per row, per 32-k block: [hi 32 bf16 (64B) | lo 32 bf16 (64B)]
__device__ uint32_t g_xb[(size_t)SEQ * (CTX / 32) * 32];   // 64 MB (words)
__device__ uint32_t g_wb[3 * DK * (CTX / 32) * 32];        // 3 MB
__device__ uint32_t g_qb[(size_t)SEQ * (DK / 32) * 32];    // 4 MB
__device__ uint32_t g_kb[(size_t)SEQ * (DK / 32) * 32];    // 4 MB
__device__ float  g_v[SEQ * DK];
__device__ __half g_sch[(size_t)SEQ * SEQ];                // 128 MB fp16 (sc - m_tile)
__device__ float  g_pm[NT * SEQ];
__device__ float  g_pzt[NT * SEQ];
__device__ float  g_m[SEQ];
__device__ float  g_rz[SEQ];
__device__ float  g_po[SPLIT][SEQ * DK];

// ============================================================
// helpers
// ============================================================
__device__ __forceinline__ uint32_t smem_u32(const void* p) {
    uint32_t a;
    asm("{ .reg .u64 t; cvta.to.shared.u64 t, %1; cvt.u32.u64 %0, t; }" : "=r"(a) : "l"(p));
    return a;
}
__device__ __forceinline__ void cp16(uint32_t dst, const void* src) {
    asm volatile("cp.async.cg.shared.global [%0], [%1], 16;" :: "r"(dst), "l"(src));
}
#define CP_COMMIT asm volatile("cp.async.commit_group;" ::: "memory")
#define CP_WAIT0  asm volatile("cp.async.wait_group 0;" ::: "memory")

__device__ __forceinline__ uint2 split2(float x0, float x1) {
    uint32_t h, l;
    asm("cvt.rn.bf16x2.f32 %0, %1, %2;" : "=r"(h) : "f"(x1), "f"(x0));
    float h0 = __uint_as_float(h << 16);
    float h1 = __uint_as_float(h & 0xffff0000u);
    asm("cvt.rn.bf16x2.f32 %0, %1, %2;" : "=r"(l) : "f"(x1 - h1), "f"(x0 - h0));
    return make_uint2(h, l);
}
__device__ __forceinline__ void mma16(float* c, const uint32_t* a, const uint32_t* b) {
    asm("mma.sync.aligned.m16n8k16.row.col.f32.bf16.bf16.f32 "
        "{%0,%1,%2,%3}, {%4,%5,%6,%7}, {%8,%9}, {%0,%1,%2,%3};"
        : "+f"(c[0]), "+f"(c[1]), "+f"(c[2]), "+f"(c[3])
        : "r"(a[0]), "r"(a[1]), "r"(a[2]), "r"(a[3]), "r"(b[0]), "r"(b[1]));
}
__device__ __forceinline__ void ldsm_x4(uint32_t* d, uint32_t a) {
    asm volatile("ldmatrix.sync.aligned.m8n8.x4.shared.b16 {%0,%1,%2,%3}, [%4];"
                 : "=r"(d[0]), "=r"(d[1]), "=r"(d[2]), "=r"(d[3]) : "r"(a));
}
// tile row = 128B (8 chunks of 16B); swizzle: chunk ^= row&7
__device__ __forceinline__ uint32_t tile_addr(uint32_t base, int row, int chunk) {
    return base + row * 128 + (((chunk ^ (row & 7)) & 7) << 4);
}

// ============================================================
// K0a: x -> blocked pair-plane
// ============================================================
__global__ __launch_bounds__(256) void cvt_x_kernel(const float* __restrict__ x)
{
    const int i = blockIdx.x * 256 + threadIdx.x;       // < SEQ*CTX/4
    const int row = i >> 9;                              // CTX/4 = 512 quads per row
    const int j = i & 511;
    const int k4 = j * 4;
    float4 v = *reinterpret_cast<const float4*>(x + (size_t)row * CTX + k4);
    uint2 p0 = split2(v.x, v.y), p1 = split2(v.z, v.w);
    uint32_t* base = g_xb + (size_t)row * 2048 + (k4 >> 5) * 32;
    const int kw = (k4 & 31) >> 1;
    base[kw] = p0.x; base[kw + 1] = p1.x;
    base[16 + kw] = p0.y; base[16 + kw + 1] = p1.y;
}

// K0b: w^T -> blocked pair-plane, [mat][n][blk]
__global__ __launch_bounds__(256) void cvt_w_kernel(
    const float* __restrict__ wq, const float* __restrict__ wk, const float* __restrict__ wv)
{
    const int i = blockIdx.x * 256 + threadIdx.x;       // < 3*128*512
    const int mat = i / (DK * 512);
    const int r = i % (DK * 512);
    const int n = r >> 9;
    const int k4 = (r & 511) * 4;
    const float* w = (mat == 0) ? wq : (mat == 1) ? wk : wv;
    float w0 = w[(size_t)(k4 + 0) * DK + n];
    float w1 = w[(size_t)(k4 + 1) * DK + n];
    float w2 = w[(size_t)(k4 + 2) * DK + n];
    float w3 = w[(size_t)(k4 + 3) * DK + n];
    uint2 p0 = split2(w0, w1), p1 = split2(w2, w3);
    uint32_t* base = g_wb + ((size_t)(mat * DK + n)) * 2048 + (k4 >> 5) * 32;
    const int kw = (k4 & 31) >> 1;
    base[kw] = p0.x; base[kw + 1] = p1.x;
    base[16 + kw] = p0.y; base[16 + kw + 1] = p1.y;
}

// ============================================================
// K1: Q/K/V = x @ w. Tile 64m x 128n, BK=32, LDSM + swizzle.
// grid (SEQ/64, 3), 256 thr (8 warps, warp 32x32).
// ============================================================
__global__ __launch_bounds__(256, 2) void qkv_kernel()
{
    __shared__ uint32_t sA[2][64 * 32];    // 16 KB
    __shared__ uint32_t sB[2][128 * 32];   // 32 KB

    const int m0 = blockIdx.x * 64;
    const int mat = blockIdx.y;
    const int tid = threadIdx.x;
    const int wid = tid >> 5, lane = tid & 31;
    const int g = lane >> 2, tg = lane & 3;
    const int wm = (wid & 1) * 32;
    const int wn = (wid >> 1) * 32;
    const int lr = (lane & 7) + ((lane >> 3) & 1) * 8;
    const int lc = lane >> 4;
    const uint32_t saAddr = smem_u32(sA);
    const uint32_t sbAddr = smem_u32(sB);

    float acc[2][4][4];
#pragma unroll
    for (int i = 0; i < 2; i++)
#pragma unroll
        for (int j = 0; j < 4; j++)
#pragma unroll
            for (int q = 0; q < 4; q++) acc[i][j][q] = 0.f;

#define QKV_ISSUE(kc, buf)                                                       \
    do {                                                                         \
        _Pragma("unroll")                                                        \
        for (int j = 0; j < 2; j++) {                                            \
            int idx = tid + j * 256, row = idx >> 3, q = idx & 7;                \
            cp16(saAddr + (buf) * 8192 + row * 128 + ((q ^ (row & 7)) << 4),     \
                 g_xb + (size_t)(m0 + row) * 2048 + (kc) * 32 + q * 4);          \
        }                                                                        \
        _Pragma("unroll")                                                        \
        for (int j = 0; j < 4; j++) {                                            \
            int idx = tid + j * 256, row = idx >> 3, q = idx & 7;                \
            cp16(sbAddr + (buf) * 16384 + row * 128 + ((q ^ (row & 7)) << 4),    \
                 g_wb + (size_t)(mat * DK + row) * 2048 + (kc) * 32 + q * 4);    \
        }                                                                        \
    } while (0)

    QKV_ISSUE(0, 0);
    CP_COMMIT;
    const int NC = CTX / 32;   // 64
    for (int kc = 0; kc < NC; kc++) {
        CP_WAIT0;
        __syncthreads();
        if (kc + 1 < NC) { QKV_ISSUE(kc + 1, (kc + 1) & 1); CP_COMMIT; }
        const int buf = kc & 1;
        const uint32_t aB = saAddr + buf * 8192;
        const uint32_t bB = sbAddr + buf * 16384;
#pragma unroll
        for (int half = 0; half < 2; half++) {
            uint32_t Ah[2][4], Al[2][4], Bh[2][4], Bl[2][4];
#pragma unroll
            for (int mt = 0; mt < 2; mt++) {
                int r = wm + mt * 16 + lr;
                ldsm_x4(Ah[mt], tile_addr(aB, r, half * 2 + lc));
                ldsm_x4(Al[mt], tile_addr(aB, r, 4 + half * 2 + lc));
            }
#pragma unroll
            for (int pr = 0; pr < 2; pr++) {
                int r = wn + pr * 16 + lr;
                ldsm_x4(Bh[pr], tile_addr(bB, r, half * 2 + lc));
                ldsm_x4(Bl[pr], tile_addr(bB, r, 4 + half * 2 + lc));
            }
#pragma unroll
            for (int nt = 0; nt < 4; nt++) {
                uint32_t bh[2] = {Bh[nt >> 1][nt & 1], Bh[nt >> 1][2 + (nt & 1)]};
                uint32_t bl[2] = {Bl[nt >> 1][nt & 1], Bl[nt >> 1][2 + (nt & 1)]};
#pragma unroll
                for (int mt = 0; mt < 2; mt++) {
                    mma16(acc[mt][nt], Ah[mt], bh);
                    mma16(acc[mt][nt], Ah[mt], bl);
                    mma16(acc[mt][nt], Al[mt], bh);
                }
            }
        }
    }
#undef QKV_ISSUE

#pragma unroll
    for (int mt = 0; mt < 2; mt++) {
#pragma unroll
        for (int nt = 0; nt < 4; nt++) {
            const int r0 = m0 + wm + mt * 16 + g;
            const int col = wn + nt * 8 + 2 * tg;
            if (mat == 2) {
                *reinterpret_cast<float2*>(g_v + (size_t)r0 * DK + col) =
                    make_float2(acc[mt][nt][0], acc[mt][nt][1]);
                *reinterpret_cast<float2*>(g_v + (size_t)(r0 + 8) * DK + col) =
                    make_float2(acc[mt][nt][2], acc[mt][nt][3]);
            } else {
                uint32_t* dst = (mat == 0) ? g_qb : g_kb;
                const int blk = col >> 5, kw = (col & 31) >> 1;
                uint2 p0 = split2(acc[mt][nt][0], acc[mt][nt][1]);
                uint2 p1 = split2(acc[mt][nt][2], acc[mt][nt][3]);
                uint32_t* b0 = dst + (size_t)r0 * 128 + blk * 32;
                uint32_t* b1 = dst + (size_t)(r0 + 8) * 128 + blk * 32;
                b0[kw] = p0.x; b0[16 + kw] = p0.y;
                b1[kw] = p1.x; b1[16 + kw] = p1.y;
            }
        }
    }
}

// ============================================================
// K2: scores tile 128(s) x 64(t), K=128 (4 chunks of 32), LDSM + swizzle.
// grid (SEQ/64 t, SEQ/128 s), 256 thr (8 warps: 4m x 2n, warp 32x32).
// Fused: fp16 (sc - m_tile) store + per-tile colmax + Z partials.
// ============================================================
__global__ __launch_bounds__(256, 2) void scores_kernel()
{
    __shared__ uint32_t sQ[2][128 * 32];   // 32 KB
    __shared__ uint32_t sK[2][64 * 32];    // 16 KB (aliased as s_red after compute)

    const int t0 = blockIdx.x * 64, s0 = blockIdx.y * 128;
    const int tid = threadIdx.x;
    const int wid = tid >> 5, lane = tid & 31;
    const int g = lane >> 2, tg = lane & 3;
    const int wm = (wid & 3) * 32;
    const int wn = (wid >> 2) * 32;
    const int lr = (lane & 7) + ((lane >> 3) & 1) * 8;
    const int lc = lane >> 4;
    const uint32_t sqAddr = smem_u32(sQ);
    const uint32_t skAddr = smem_u32(sK);

    float acc[2][4][4];
#pragma unroll
    for (int i = 0; i < 2; i++)
#pragma unroll
        for (int j = 0; j < 4; j++)
#pragma unroll
            for (int q = 0; q < 4; q++) acc[i][j][q] = 0.f;

#define SC_ISSUE(kc, buf)                                                        \
    do {                                                                         \
        _Pragma("unroll")                                                        \
        for (int j = 0; j < 4; j++) {                                            \
            int idx = tid + j * 256, row = idx >> 3, q = idx & 7;                \
            cp16(sqAddr + (buf) * 16384 + row * 128 + ((q ^ (row & 7)) << 4),    \
                 g_qb + (size_t)(s0 + row) * 128 + (kc) * 32 + q * 4);           \
        }                                                                        \
        _Pragma("unroll")                                                        \
        for (int j = 0; j < 2; j++) {                                            \
            int idx = tid + j * 256, row = idx >> 3, q = idx & 7;                \
            cp16(skAddr + (buf) * 8192 + row * 128 + ((q ^ (row & 7)) << 4),     \
                 g_kb + (size_t)(t0 + row) * 128 + (kc) * 32 + q * 4);           \
        }                                                                        \
    } while (0)

    SC_ISSUE(0, 0);
    CP_COMMIT;
    const int NC = DK / 32;   // 4
    for (int kc = 0; kc < NC; kc++) {
        CP_WAIT0;
        __syncthreads();
        if (kc + 1 < NC) { SC_ISSUE(kc + 1, (kc + 1) & 1); CP_COMMIT; }
        const int buf = kc & 1;
        const uint32_t aB = sqAddr + buf * 16384;
        const uint32_t bB = skAddr + buf * 8192;
#pragma unroll
        for (int half = 0; half < 2; half++) {
            uint32_t Ah[2][4], Al[2][4], Bh[2][4], Bl[2][4];
#pragma unroll
            for (int mt = 0; mt < 2; mt++) {
                int r = wm + mt * 16 + lr;
                ldsm_x4(Ah[mt], tile_addr(aB, r, half * 2 + lc));
                ldsm_x4(Al[mt], tile_addr(aB, r, 4 + half * 2 + lc));
            }
#pragma unroll
            for (int pr = 0; pr < 2; pr++) {
                int r = wn + pr * 16 + lr;
                ldsm_x4(Bh[pr], tile_addr(bB, r, half * 2 + lc));
                ldsm_x4(Bl[pr], tile_addr(bB, r, 4 + half * 2 + lc));
            }
#pragma unroll
            for (int nt = 0; nt < 4; nt++) {
                uint32_t bh[2] = {Bh[nt >> 1][nt & 1], Bh[nt >> 1][2 + (nt & 1)]};
                uint32_t bl[2] = {Bl[nt >> 1][nt & 1], Bl[nt >> 1][2 + (nt & 1)]};
#pragma unroll
                for (int mt = 0; mt < 2; mt++) {
                    mma16(acc[mt][nt], Ah[mt], bh);
                    mma16(acc[mt][nt], Ah[mt], bl);
                    mma16(acc[mt][nt], Al[mt], bh);
                }
            }
        }
    }
#undef SC_ISSUE

    __syncthreads();          // all MMA reads of sK done; safe to alias
    float (*s_red)[64] = reinterpret_cast<float(*)[64]>(sK);

    // scale
#pragma unroll
    for (int mt = 0; mt < 2; mt++)
#pragma unroll
        for (int nt = 0; nt < 4; nt++)
#pragma unroll
            for (int q = 0; q < 4; q++) acc[mt][nt][q] *= SCALE;

    // per-warp column max over its 32 rows
    float cm[8];
#pragma unroll
    for (int nt = 0; nt < 4; nt++) {
        float a0 = fmaxf(fmaxf(acc[0][nt][0], acc[0][nt][2]), fmaxf(acc[1][nt][0], acc[1][nt][2]));
        float a1 = fmaxf(fmaxf(acc[0][nt][1], acc[0][nt][3]), fmaxf(acc[1][nt][1], acc[1][nt][3]));
        cm[nt * 2] = a0; cm[nt * 2 + 1] = a1;
    }
#pragma unroll
    for (int off = 4; off < 32; off <<= 1)
#pragma unroll
        for (int j = 0; j < 8; j++)
            cm[j] = fmaxf(cm[j], __shfl_xor_sync(0xffffffffu, cm[j], off));
    if (g == 0) {
#pragma unroll
        for (int nt = 0; nt < 4; nt++) {
            s_red[wid & 3][wn + nt * 8 + 2 * tg + 0] = cm[nt * 2 + 0];
            s_red[wid & 3][wn + nt * 8 + 2 * tg + 1] = cm[nt * 2 + 1];
        }
    }
    __syncthreads();
    float m4 = 0.f;
    if (tid < 64) {
        m4 = fmaxf(fmaxf(s_red[0][tid], s_red[1][tid]), fmaxf(s_red[2][tid], s_red[3][tid]));
        g_pm[(s0 >> 7) * SEQ + t0 + tid] = m4;
    }
    __syncthreads();
    if (tid < 64) s_red[0][tid] = m4;
    __syncthreads();

    float mcol[8];
#pragma unroll
    for (int nt = 0; nt < 4; nt++) {
        const int c = wn + nt * 8 + 2 * tg;
        mcol[nt * 2 + 0] = s_red[0][c];
        mcol[nt * 2 + 1] = s_red[0][c + 1];
    }

    float z[8];
#pragma unroll
    for (int j = 0; j < 8; j++) z[j] = 0.f;
#pragma unroll
    for (int mt = 0; mt < 2; mt++) {
#pragma unroll
        for (int nt = 0; nt < 4; nt++) {
            const int r0 = s0 + wm + mt * 16 + g;
            const int col = t0 + wn + nt * 8 + 2 * tg;
            float d00 = acc[mt][nt][0] - mcol[nt * 2],     d01 = acc[mt][nt][1] - mcol[nt * 2 + 1];
            float d10 = acc[mt][nt][2] - mcol[nt * 2],     d11 = acc[mt][nt][3] - mcol[nt * 2 + 1];
            *reinterpret_cast<__half2*>(&g_sch[(size_t)r0 * SEQ + col]) = __floats2half2_rn(d00, d01);
            *reinterpret_cast<__half2*>(&g_sch[(size_t)(r0 + 8) * SEQ + col]) = __floats2half2_rn(d10, d11);
            z[nt * 2 + 0] += (d00 > THRESH ? __expf(d00) : 0.f) + (d10 > THRESH ? __expf(d10) : 0.f);
            z[nt * 2 + 1] += (d01 > THRESH ? __expf(d01) : 0.f) + (d11 > THRESH ? __expf(d11) : 0.f);
        }
    }
#pragma unroll
    for (int off = 4; off < 32; off <<= 1)
#pragma unroll
        for (int j = 0; j < 8; j++)
            z[j] += __shfl_xor_sync(0xffffffffu, z[j], off);
    __syncthreads();
    if (g == 0) {
#pragma unroll
        for (int nt = 0; nt < 4; nt++) {
            s_red[wid & 3][wn + nt * 8 + 2 * tg + 0] = z[nt * 2 + 0];
            s_red[wid & 3][wn + nt * 8 + 2 * tg + 1] = z[nt * 2 + 1];
        }
    }
    __syncthreads();
    if (tid < 64)
        g_pzt[(s0 >> 7) * SEQ + t0 + tid] =
            (s_red[0][tid] + s_red[1][tid]) + (s_red[2][tid] + s_red[3][tid]);
}

// ============================================================
// K3: combine tile stats -> global m_t and 1/Z_t
// ============================================================
__global__ void combine_kernel()
{
    const int t = blockIdx.x * 256 + threadIdx.x;
    float m = -3.4e38f;
#pragma unroll 8
    for (int b = 0; b < NT; b++) m = fmaxf(m, g_pm[b * SEQ + t]);
    float Z = 0.f;
#pragma unroll 8
    for (int b = 0; b < NT; b++) {
        float d = g_pm[b * SEQ + t] - m;
        if (d > THRESH - 10.f) Z += g_pzt[b * SEQ + t] * __expf(d);
    }
    g_m[t] = m;
    g_rz[t] = 1.0f / Z;
}

// ============================================================
// K4: split-K PV (unchanged)
// ============================================================
__global__ __launch_bounds__(256) void pv_kernel()
{
    __shared__ float s_adj[TCH];
    __shared__ float s_rz[TCH];
    __shared__ float sA[8][64];
    __shared__ float sB[8][128];
    const int s0 = blockIdx.y * 64;
    const int tb = blockIdx.x * TCH;
    const int b = blockIdx.y >> 1;
    const int tid = threadIdx.x;
    const int tx = tid & 15, ty = tid >> 4;
    const int ar = tid >> 2, ac = (tid & 3) * 2;
    const int br = tid >> 5, bc = (tid & 31) * 4;

#pragma unroll
    for (int j = 0; j < 2; j++) {
        int t = tid + j * 256;
        s_adj[t] = g_pm[b * SEQ + tb + t] - g_m[tb + t];
        s_rz[t] = g_rz[tb + t];
    }

    float acc[4][8];
#pragma unroll
    for (int i = 0; i < 4; i++)
#pragma unroll
        for (int j = 0; j < 8; j++) acc[i][j] = 0.f;

    const __half* sp = g_sch + (size_t)(s0 + ar) * SEQ + tb + ac;
    __syncthreads();

    for (int k0 = 0; k0 < TCH; k0 += 8) {
        __half2 hv = *reinterpret_cast<const __half2*>(sp + k0);
        float2 fv = __half22float2(hv);
        float dd0 = fv.x + s_adj[k0 + ac];
        float dd1 = fv.y + s_adj[k0 + ac + 1];
        float rzv = s_rz[k0 + br];
        float4 bv = *reinterpret_cast<const float4*>(g_v + (size_t)(tb + k0 + br) * DK + bc);
        float p0 = 0.f, p1 = 0.f;
        if (fmaxf(dd0, dd1) > THRESH) {
            if (dd0 > THRESH) p0 = __expf(dd0);
            if (dd1 > THRESH) p1 = __expf(dd1);
        }
        __syncthreads();
        sA[ac][ar] = p0;
        sA[ac + 1][ar] = p1;
        *reinterpret_cast<float4*>(&sB[br][bc]) =
            make_float4(bv.x * rzv, bv.y * rzv, bv.z * rzv, bv.w * rzv);
        int active = __syncthreads_or(p0 != 0.f || p1 != 0.f);
        if (active) {
#pragma unroll
            for (int kk = 0; kk < 8; kk++) {
                float4 a  = *reinterpret_cast<const float4*>(&sA[kk][ty * 4]);
                float4 b0 = *reinterpret_cast<const float4*>(&sB[kk][tx * 8]);
                float4 b1 = *reinterpret_cast<const float4*>(&sB[kk][tx * 8 + 4]);
                float aa[4] = {a.x, a.y, a.z, a.w};
                float bb[8] = {b0.x, b0.y, b0.z, b0.w, b1.x, b1.y, b1.z, b1.w};
#pragma unroll
                for (int i = 0; i < 4; i++)
#pragma unroll
                    for (int j = 0; j < 8; j++) acc[i][j] += aa[i] * bb[j];
            }
        }
    }
    float* po = g_po[blockIdx.x];
#pragma unroll
    for (int i = 0; i < 4; i++) {
        float* op = po + (size_t)(s0 + ty * 4 + i) * DK + tx * 8;
        *reinterpret_cast<float4*>(op)     = make_float4(acc[i][0], acc[i][1], acc[i][2], acc[i][3]);
        *reinterpret_cast<float4*>(op + 4) = make_float4(acc[i][4], acc[i][5], acc[i][6], acc[i][7]);
    }
}

// K5: fixed-order split reduction
__global__ void pv_reduce_kernel(float* __restrict__ out)
{
    const int i = blockIdx.x * 256 + threadIdx.x;
    float s = 0.f;
#pragma unroll
    for (int p = 0; p < SPLIT; p++) s += g_po[p][i];
    out[i] = s;
}

// ============================================================
extern "C" void kernel_launch(void* const* d_in, const int* in_sizes, int n_in,
                              void* d_out, int out_size)
{
    const float* x  = (const float*)d_in[0];
    const float* wq = (const float*)d_in[1];
    const float* wk = (const float*)d_in[2];
    const float* wv = (const float*)d_in[3];
    float* out = (float*)d_out;

    cvt_x_kernel<<<SEQ * CTX / 4 / 256, 256>>>(x);
    cvt_w_kernel<<<3 * DK * 512 / 256, 256>>>(wq, wk, wv);
    qkv_kernel<<<dim3(SEQ / 64, 3), 256>>>();
    scores_kernel<<<dim3(SEQ / 64, SEQ / 128), 256>>>();
    combine_kernel<<<SEQ / 256, 256>>>();
    pv_kernel<<<dim3(SPLIT, SEQ / 64), 256>>>();
    pv_reduce_kernel<<<SEQ * DK / 256, 256>>>(out);
}

// round 7
// speedup vs baseline: 4.1857x; 1.0097x over previous
#include <cuda_runtime.h>
#include <cuda_fp16.h>
#include <cstdint>

#define SEQ 8192
#define CTX 2048
#define DK  128
#define NT  64                    // SEQ/128 s-tiles
#define SPLIT 16
#define TCH (SEQ / SPLIT)         // 512 t-columns per pv block
#define SCALE 11.313708498984760f
#define THRESH -25.0f

// ---- scratch (device globals) ----
// blocked pair-plane format: per row, per 32-k block: [hi 32 bf16 (64B) | lo 32 bf16 (64B)]
__device__ uint32_t g_xb[(size_t)SEQ * (CTX / 32) * 32];   // 64 MB (words)
__device__ uint32_t g_wb[3 * DK * (CTX / 32) * 32];        // 3 MB
__device__ uint32_t g_qb[(size_t)SEQ * (DK / 32) * 32];    // 4 MB
__device__ uint32_t g_kb[(size_t)SEQ * (DK / 32) * 32];    // 4 MB
__device__ float  g_v[SEQ * DK];
__device__ __half g_sch[(size_t)SEQ * SEQ];                // 128 MB fp16 (sc - m_tile)
__device__ float  g_pm[NT * SEQ];
__device__ float  g_pzt[NT * SEQ];
__device__ float  g_m[SEQ];
__device__ float  g_rz[SEQ];
__device__ float  g_po[SPLIT][SEQ * DK];

// ============================================================
// helpers
// ============================================================
__device__ __forceinline__ uint32_t smem_u32(const void* p) {
    uint32_t a;
    asm("{ .reg .u64 t; cvta.to.shared.u64 t, %1; cvt.u32.u64 %0, t; }" : "=r"(a) : "l"(p));
    return a;
}
__device__ __forceinline__ void cp16(uint32_t dst, const void* src) {
    asm volatile("cp.async.cg.shared.global [%0], [%1], 16;" :: "r"(dst), "l"(src));
}
#define CP_COMMIT asm volatile("cp.async.commit_group;" ::: "memory")
#define CP_WAIT0  asm volatile("cp.async.wait_group 0;" ::: "memory")

__device__ __forceinline__ uint2 split2(float x0, float x1) {
    uint32_t h, l;
    asm("cvt.rn.bf16x2.f32 %0, %1, %2;" : "=r"(h) : "f"(x1), "f"(x0));
    float h0 = __uint_as_float(h << 16);
    float h1 = __uint_as_float(h & 0xffff0000u);
    asm("cvt.rn.bf16x2.f32 %0, %1, %2;" : "=r"(l) : "f"(x1 - h1), "f"(x0 - h0));
    return make_uint2(h, l);
}
__device__ __forceinline__ void mma16(float* c, const uint32_t* a, const uint32_t* b) {
    asm("mma.sync.aligned.m16n8k16.row.col.f32.bf16.bf16.f32 "
        "{%0,%1,%2,%3}, {%4,%5,%6,%7}, {%8,%9}, {%0,%1,%2,%3};"
        : "+f"(c[0]), "+f"(c[1]), "+f"(c[2]), "+f"(c[3])
        : "r"(a[0]), "r"(a[1]), "r"(a[2]), "r"(a[3]), "r"(b[0]), "r"(b[1]));
}
__device__ __forceinline__ void ldsm_x4(uint32_t* d, uint32_t a) {
    asm volatile("ldmatrix.sync.aligned.m8n8.x4.shared.b16 {%0,%1,%2,%3}, [%4];"
                 : "=r"(d[0]), "=r"(d[1]), "=r"(d[2]), "=r"(d[3]) : "r"(a));
}
// row = rowb bytes, per-128B-block swizzle: chunk ^= row&7
__device__ __forceinline__ uint32_t tadr(uint32_t base, int row, int rowb, int blk, int chunk) {
    return base + row * rowb + blk * 128 + (((chunk ^ (row & 7)) & 7) << 4);
}

// ============================================================
// K0a: x -> blocked pair-plane
// ============================================================
__global__ __launch_bounds__(256) void cvt_x_kernel(const float* __restrict__ x)
{
    const int i = blockIdx.x * 256 + threadIdx.x;       // < SEQ*CTX/4
    const int row = i >> 9;
    const int j = i & 511;
    const int k4 = j * 4;
    float4 v = *reinterpret_cast<const float4*>(x + (size_t)row * CTX + k4);
    uint2 p0 = split2(v.x, v.y), p1 = split2(v.z, v.w);
    uint32_t* base = g_xb + (size_t)row * 2048 + (k4 >> 5) * 32;
    const int kw = (k4 & 31) >> 1;
    base[kw] = p0.x; base[kw + 1] = p1.x;
    base[16 + kw] = p0.y; base[16 + kw + 1] = p1.y;
}

// K0b: w^T -> blocked pair-plane, [mat][n][blk]
__global__ __launch_bounds__(256) void cvt_w_kernel(
    const float* __restrict__ wq, const float* __restrict__ wk, const float* __restrict__ wv)
{
    const int i = blockIdx.x * 256 + threadIdx.x;       // < 3*128*512
    const int mat = i / (DK * 512);
    const int r = i % (DK * 512);
    const int n = r >> 9;
    const int k4 = (r & 511) * 4;
    const float* w = (mat == 0) ? wq : (mat == 1) ? wk : wv;
    float w0 = w[(size_t)(k4 + 0) * DK + n];
    float w1 = w[(size_t)(k4 + 1) * DK + n];
    float w2 = w[(size_t)(k4 + 2) * DK + n];
    float w3 = w[(size_t)(k4 + 3) * DK + n];
    uint2 p0 = split2(w0, w1), p1 = split2(w2, w3);
    uint32_t* base = g_wb + ((size_t)(mat * DK + n)) * 2048 + (k4 >> 5) * 32;
    const int kw = (k4 & 31) >> 1;
    base[kw] = p0.x; base[kw + 1] = p1.x;
    base[16 + kw] = p0.y; base[16 + kw + 1] = p1.y;
}

// ============================================================
// K1: Q/K/V = x @ w. Tile 64m x 128n, BK=64, dyn smem 96KB, 2-buf.
// grid (SEQ/64, 3), 256 thr (8 warps, warp 32x32).
// dyn smem layout (words): A0=0(4096) A1=4096 B0=8192(8192) B1=16384
// row bytes: A 256 (2 blocks), B 256.
// ============================================================
__global__ __launch_bounds__(256, 2) void qkv_kernel()
{
    extern __shared__ uint32_t dsm[];
    const uint32_t base0 = smem_u32(dsm);

    const int m0 = blockIdx.x * 64;
    const int mat = blockIdx.y;
    const int tid = threadIdx.x;
    const int wid = tid >> 5, lane = tid & 31;
    const int g = lane >> 2, tg = lane & 3;
    const int wm = (wid & 1) * 32;
    const int wn = (wid >> 1) * 32;
    const int lr = (lane & 7) + ((lane >> 3) & 1) * 8;
    const int lc = lane >> 4;

    float acc[2][4][4];
#pragma unroll
    for (int i = 0; i < 2; i++)
#pragma unroll
        for (int j = 0; j < 4; j++)
#pragma unroll
            for (int q = 0; q < 4; q++) acc[i][j][q] = 0.f;

    // loader indices: A 64 rows x 16 chunks (1024 total, 4/thr), B 128 x 16 (2048, 8/thr)
#define QKV_ISSUE(kc, buf)                                                        \
    do {                                                                          \
        _Pragma("unroll")                                                         \
        for (int j = 0; j < 4; j++) {                                             \
            int idx = tid + j * 256, row = idx >> 4, c = idx & 15;                \
            int blk = c >> 3, q = c & 7;                                          \
            cp16(base0 + (buf) * 16384 + row * 256 + blk * 128 + ((q ^ (row & 7)) << 4), \
                 g_xb + (size_t)(m0 + row) * 2048 + ((kc) * 2 + blk) * 32 + q * 4);      \
        }                                                                         \
        _Pragma("unroll")                                                         \
        for (int j = 0; j < 8; j++) {                                             \
            int idx = tid + j * 256, row = idx >> 4, c = idx & 15;                \
            int blk = c >> 3, q = c & 7;                                          \
            cp16(base0 + 32768 + (buf) * 32768 + row * 256 + blk * 128 + ((q ^ (row & 7)) << 4), \
                 g_wb + (size_t)(mat * DK + row) * 2048 + ((kc) * 2 + blk) * 32 + q * 4);        \
        }                                                                         \
    } while (0)

    QKV_ISSUE(0, 0);
    CP_COMMIT;
    const int NC = CTX / 64;   // 32
    for (int kc = 0; kc < NC; kc++) {
        CP_WAIT0;
        __syncthreads();
        if (kc + 1 < NC) { QKV_ISSUE(kc + 1, (kc + 1) & 1); CP_COMMIT; }
        const int buf = kc & 1;
        const uint32_t aB = base0 + buf * 16384;
        const uint32_t bB = base0 + 32768 + buf * 32768;
#pragma unroll
        for (int blk = 0; blk < 2; blk++) {
#pragma unroll
            for (int half = 0; half < 2; half++) {
                uint32_t Ah[2][4], Al[2][4], Bh[2][4], Bl[2][4];
#pragma unroll
                for (int mt = 0; mt < 2; mt++) {
                    int r = wm + mt * 16 + lr;
                    ldsm_x4(Ah[mt], tadr(aB, r, 256, blk, half * 2 + lc));
                    ldsm_x4(Al[mt], tadr(aB, r, 256, blk, 4 + half * 2 + lc));
                }
#pragma unroll
                for (int pr = 0; pr < 2; pr++) {
                    int r = wn + pr * 16 + lr;
                    ldsm_x4(Bh[pr], tadr(bB, r, 256, blk, half * 2 + lc));
                    ldsm_x4(Bl[pr], tadr(bB, r, 256, blk, 4 + half * 2 + lc));
                }
                // pass-major: 8 independent acc chains per pass
#pragma unroll
                for (int nt = 0; nt < 4; nt++) {
                    uint32_t bh[2] = {Bh[nt >> 1][nt & 1], Bh[nt >> 1][2 + (nt & 1)]};
#pragma unroll
                    for (int mt = 0; mt < 2; mt++) mma16(acc[mt][nt], Ah[mt], bh);
                }
#pragma unroll
                for (int nt = 0; nt < 4; nt++) {
                    uint32_t bl[2] = {Bl[nt >> 1][nt & 1], Bl[nt >> 1][2 + (nt & 1)]};
#pragma unroll
                    for (int mt = 0; mt < 2; mt++) mma16(acc[mt][nt], Ah[mt], bl);
                }
#pragma unroll
                for (int nt = 0; nt < 4; nt++) {
                    uint32_t bh[2] = {Bh[nt >> 1][nt & 1], Bh[nt >> 1][2 + (nt & 1)]};
#pragma unroll
                    for (int mt = 0; mt < 2; mt++) mma16(acc[mt][nt], Al[mt], bh);
                }
            }
        }
    }
#undef QKV_ISSUE

#pragma unroll
    for (int mt = 0; mt < 2; mt++) {
#pragma unroll
        for (int nt = 0; nt < 4; nt++) {
            const int r0 = m0 + wm + mt * 16 + g;
            const int col = wn + nt * 8 + 2 * tg;
            if (mat == 2) {
                *reinterpret_cast<float2*>(g_v + (size_t)r0 * DK + col) =
                    make_float2(acc[mt][nt][0], acc[mt][nt][1]);
                *reinterpret_cast<float2*>(g_v + (size_t)(r0 + 8) * DK + col) =
                    make_float2(acc[mt][nt][2], acc[mt][nt][3]);
            } else {
                uint32_t* dst = (mat == 0) ? g_qb : g_kb;
                const int blk = col >> 5, kw = (col & 31) >> 1;
                uint2 p0 = split2(acc[mt][nt][0], acc[mt][nt][1]);
                uint2 p1 = split2(acc[mt][nt][2], acc[mt][nt][3]);
                uint32_t* b0 = dst + (size_t)r0 * 128 + blk * 32;
                uint32_t* b1 = dst + (size_t)(r0 + 8) * 128 + blk * 32;
                b0[kw] = p0.x; b0[16 + kw] = p0.y;
                b1[kw] = p1.x; b1[16 + kw] = p1.y;
            }
        }
    }
}

// ============================================================
// K2: scores tile 128(s) x 64(t), FULL K=128 resident (one-shot 96KB).
// grid (SEQ/64 t, SEQ/128 s), 256 thr (8 warps: 4m x 2n, warp 32x32).
// dyn smem (words): Q = 0 (128 rows x 128 words, 512B rows), K = 16384 (64 rows).
// Fused: fp16 (sc - m_tile) store + per-tile colmax + Z partials.
// ============================================================
__global__ __launch_bounds__(256, 2) void scores_kernel()
{
    extern __shared__ uint32_t dsm[];
    const uint32_t sqAddr = smem_u32(dsm);
    const uint32_t skAddr = sqAddr + 65536;

    const int t0 = blockIdx.x * 64, s0 = blockIdx.y * 128;
    const int tid = threadIdx.x;
    const int wid = tid >> 5, lane = tid & 31;
    const int g = lane >> 2, tg = lane & 3;
    const int wm = (wid & 3) * 32;
    const int wn = (wid >> 2) * 32;
    const int lr = (lane & 7) + ((lane >> 3) & 1) * 8;
    const int lc = lane >> 4;

    float acc[2][4][4];
#pragma unroll
    for (int i = 0; i < 2; i++)
#pragma unroll
        for (int j = 0; j < 4; j++)
#pragma unroll
            for (int q = 0; q < 4; q++) acc[i][j][q] = 0.f;

    // one-shot loads: Q 128x32 chunks (16/thr), K 64x32 (8/thr)
#pragma unroll
    for (int j = 0; j < 16; j++) {
        int idx = tid + j * 256, row = idx >> 5, c = idx & 31;
        int blk = c >> 3, q = c & 7;
        cp16(sqAddr + row * 512 + blk * 128 + ((q ^ (row & 7)) << 4),
             g_qb + (size_t)(s0 + row) * 128 + blk * 32 + q * 4);
    }
#pragma unroll
    for (int j = 0; j < 8; j++) {
        int idx = tid + j * 256, row = idx >> 5, c = idx & 31;
        int blk = c >> 3, q = c & 7;
        cp16(skAddr + row * 512 + blk * 128 + ((q ^ (row & 7)) << 4),
             g_kb + (size_t)(t0 + row) * 128 + blk * 32 + q * 4);
    }
    CP_COMMIT;
    CP_WAIT0;
    __syncthreads();

#pragma unroll
    for (int blk = 0; blk < 4; blk++) {
#pragma unroll
        for (int half = 0; half < 2; half++) {
            uint32_t Ah[2][4], Al[2][4], Bh[2][4], Bl[2][4];
#pragma unroll
            for (int mt = 0; mt < 2; mt++) {
                int r = wm + mt * 16 + lr;
                ldsm_x4(Ah[mt], tadr(sqAddr, r, 512, blk, half * 2 + lc));
                ldsm_x4(Al[mt], tadr(sqAddr, r, 512, blk, 4 + half * 2 + lc));
            }
#pragma unroll
            for (int pr = 0; pr < 2; pr++) {
                int r = wn + pr * 16 + lr;
                ldsm_x4(Bh[pr], tadr(skAddr, r, 512, blk, half * 2 + lc));
                ldsm_x4(Bl[pr], tadr(skAddr, r, 512, blk, 4 + half * 2 + lc));
            }
#pragma unroll
            for (int nt = 0; nt < 4; nt++) {
                uint32_t bh[2] = {Bh[nt >> 1][nt & 1], Bh[nt >> 1][2 + (nt & 1)]};
#pragma unroll
                for (int mt = 0; mt < 2; mt++) mma16(acc[mt][nt], Ah[mt], bh);
            }
#pragma unroll
            for (int nt = 0; nt < 4; nt++) {
                uint32_t bl[2] = {Bl[nt >> 1][nt & 1], Bl[nt >> 1][2 + (nt & 1)]};
#pragma unroll
                for (int mt = 0; mt < 2; mt++) mma16(acc[mt][nt], Ah[mt], bl);
            }
#pragma unroll
            for (int nt = 0; nt < 4; nt++) {
                uint32_t bh[2] = {Bh[nt >> 1][nt & 1], Bh[nt >> 1][2 + (nt & 1)]};
#pragma unroll
                for (int mt = 0; mt < 2; mt++) mma16(acc[mt][nt], Al[mt], bh);
            }
        }
    }

    __syncthreads();          // all LDSM reads done; safe to alias K region
    float (*s_red)[64] = reinterpret_cast<float(*)[64]>(dsm + 16384);

#pragma unroll
    for (int mt = 0; mt < 2; mt++)
#pragma unroll
        for (int nt = 0; nt < 4; nt++)
#pragma unroll
            for (int q = 0; q < 4; q++) acc[mt][nt][q] *= SCALE;

    float cm[8];
#pragma unroll
    for (int nt = 0; nt < 4; nt++) {
        float a0 = fmaxf(fmaxf(acc[0][nt][0], acc[0][nt][2]), fmaxf(acc[1][nt][0], acc[1][nt][2]));
        float a1 = fmaxf(fmaxf(acc[0][nt][1], acc[0][nt][3]), fmaxf(acc[1][nt][1], acc[1][nt][3]));
        cm[nt * 2] = a0; cm[nt * 2 + 1] = a1;
    }
#pragma unroll
    for (int off = 4; off < 32; off <<= 1)
#pragma unroll
        for (int j = 0; j < 8; j++)
            cm[j] = fmaxf(cm[j], __shfl_xor_sync(0xffffffffu, cm[j], off));
    if (g == 0) {
#pragma unroll
        for (int nt = 0; nt < 4; nt++) {
            s_red[wid & 3][wn + nt * 8 + 2 * tg + 0] = cm[nt * 2 + 0];
            s_red[wid & 3][wn + nt * 8 + 2 * tg + 1] = cm[nt * 2 + 1];
        }
    }
    __syncthreads();
    float m4 = 0.f;
    if (tid < 64) {
        m4 = fmaxf(fmaxf(s_red[0][tid], s_red[1][tid]), fmaxf(s_red[2][tid], s_red[3][tid]));
        g_pm[(s0 >> 7) * SEQ + t0 + tid] = m4;
    }
    __syncthreads();
    if (tid < 64) s_red[0][tid] = m4;
    __syncthreads();

    float mcol[8];
#pragma unroll
    for (int nt = 0; nt < 4; nt++) {
        const int c = wn + nt * 8 + 2 * tg;
        mcol[nt * 2 + 0] = s_red[0][c];
        mcol[nt * 2 + 1] = s_red[0][c + 1];
    }

    float z[8];
#pragma unroll
    for (int j = 0; j < 8; j++) z[j] = 0.f;
#pragma unroll
    for (int mt = 0; mt < 2; mt++) {
#pragma unroll
        for (int nt = 0; nt < 4; nt++) {
            const int r0 = s0 + wm + mt * 16 + g;
            const int col = t0 + wn + nt * 8 + 2 * tg;
            float d00 = acc[mt][nt][0] - mcol[nt * 2],     d01 = acc[mt][nt][1] - mcol[nt * 2 + 1];
            float d10 = acc[mt][nt][2] - mcol[nt * 2],     d11 = acc[mt][nt][3] - mcol[nt * 2 + 1];
            *reinterpret_cast<__half2*>(&g_sch[(size_t)r0 * SEQ + col]) = __floats2half2_rn(d00, d01);
            *reinterpret_cast<__half2*>(&g_sch[(size_t)(r0 + 8) * SEQ + col]) = __floats2half2_rn(d10, d11);
            z[nt * 2 + 0] += (d00 > THRESH ? __expf(d00) : 0.f) + (d10 > THRESH ? __expf(d10) : 0.f);
            z[nt * 2 + 1] += (d01 > THRESH ? __expf(d01) : 0.f) + (d11 > THRESH ? __expf(d11) : 0.f);
        }
    }
#pragma unroll
    for (int off = 4; off < 32; off <<= 1)
#pragma unroll
        for (int j = 0; j < 8; j++)
            z[j] += __shfl_xor_sync(0xffffffffu, z[j], off);
    __syncthreads();
    if (g == 0) {
#pragma unroll
        for (int nt = 0; nt < 4; nt++) {
            s_red[wid & 3][wn + nt * 8 + 2 * tg + 0] = z[nt * 2 + 0];
            s_red[wid & 3][wn + nt * 8 + 2 * tg + 1] = z[nt * 2 + 1];
        }
    }
    __syncthreads();
    if (tid < 64)
        g_pzt[(s0 >> 7) * SEQ + t0 + tid] =
            (s_red[0][tid] + s_red[1][tid]) + (s_red[2][tid] + s_red[3][tid]);
}

// ============================================================
// K3: combine tile stats -> global m_t and 1/Z_t
// ============================================================
__global__ void combine_kernel()
{
    const int t = blockIdx.x * 256 + threadIdx.x;
    float m = -3.4e38f;
#pragma unroll 8
    for (int b = 0; b < NT; b++) m = fmaxf(m, g_pm[b * SEQ + t]);
    float Z = 0.f;
#pragma unroll 8
    for (int b = 0; b < NT; b++) {
        float d = g_pm[b * SEQ + t] - m;
        if (d > THRESH - 10.f) Z += g_pzt[b * SEQ + t] * __expf(d);
    }
    g_m[t] = m;
    g_rz[t] = 1.0f / Z;
}

// ============================================================
// K4: split-K PV (unchanged)
// ============================================================
__global__ __launch_bounds__(256) void pv_kernel()
{
    __shared__ float s_adj[TCH];
    __shared__ float s_rz[TCH];
    __shared__ float sA[8][64];
    __shared__ float sB[8][128];
    const int s0 = blockIdx.y * 64;
    const int tb = blockIdx.x * TCH;
    const int b = blockIdx.y >> 1;
    const int tid = threadIdx.x;
    const int tx = tid & 15, ty = tid >> 4;
    const int ar = tid >> 2, ac = (tid & 3) * 2;
    const int br = tid >> 5, bc = (tid & 31) * 4;

#pragma unroll
    for (int j = 0; j < 2; j++) {
        int t = tid + j * 256;
        s_adj[t] = g_pm[b * SEQ + tb + t] - g_m[tb + t];
        s_rz[t] = g_rz[tb + t];
    }

    float acc[4][8];
#pragma unroll
    for (int i = 0; i < 4; i++)
#pragma unroll
        for (int j = 0; j < 8; j++) acc[i][j] = 0.f;

    const __half* sp = g_sch + (size_t)(s0 + ar) * SEQ + tb + ac;
    __syncthreads();

    for (int k0 = 0; k0 < TCH; k0 += 8) {
        __half2 hv = *reinterpret_cast<const __half2*>(sp + k0);
        float2 fv = __half22float2(hv);
        float dd0 = fv.x + s_adj[k0 + ac];
        float dd1 = fv.y + s_adj[k0 + ac + 1];
        float rzv = s_rz[k0 + br];
        float4 bv = *reinterpret_cast<const float4*>(g_v + (size_t)(tb + k0 + br) * DK + bc);
        float p0 = 0.f, p1 = 0.f;
        if (fmaxf(dd0, dd1) > THRESH) {
            if (dd0 > THRESH) p0 = __expf(dd0);
            if (dd1 > THRESH) p1 = __expf(dd1);
        }
        __syncthreads();
        sA[ac][ar] = p0;
        sA[ac + 1][ar] = p1;
        *reinterpret_cast<float4*>(&sB[br][bc]) =
            make_float4(bv.x * rzv, bv.y * rzv, bv.z * rzv, bv.w * rzv);
        int active = __syncthreads_or(p0 != 0.f || p1 != 0.f);
        if (active) {
#pragma unroll
            for (int kk = 0; kk < 8; kk++) {
                float4 a  = *reinterpret_cast<const float4*>(&sA[kk][ty * 4]);
                float4 b0 = *reinterpret_cast<const float4*>(&sB[kk][tx * 8]);
                float4 b1 = *reinterpret_cast<const float4*>(&sB[kk][tx * 8 + 4]);
                float aa[4] = {a.x, a.y, a.z, a.w};
                float bb[8] = {b0.x, b0.y, b0.z, b0.w, b1.x, b1.y, b1.z, b1.w};
#pragma unroll
                for (int i = 0; i < 4; i++)
#pragma unroll
                    for (int j = 0; j < 8; j++) acc[i][j] += aa[i] * bb[j];
            }
        }
    }
    float* po = g_po[blockIdx.x];
#pragma unroll
    for (int i = 0; i < 4; i++) {
        float* op = po + (size_t)(s0 + ty * 4 + i) * DK + tx * 8;
        *reinterpret_cast<float4*>(op)     = make_float4(acc[i][0], acc[i][1], acc[i][2], acc[i][3]);
        *reinterpret_cast<float4*>(op + 4) = make_float4(acc[i][4], acc[i][5], acc[i][6], acc[i][7]);
    }
}

// K5: fixed-order split reduction
__global__ void pv_reduce_kernel(float* __restrict__ out)
{
    const int i = blockIdx.x * 256 + threadIdx.x;
    float s = 0.f;
#pragma unroll
    for (int p = 0; p < SPLIT; p++) s += g_po[p][i];
    out[i] = s;
}

// ============================================================
extern "C" void kernel_launch(void* const* d_in, const int* in_sizes, int n_in,
                              void* d_out, int out_size)
{
    const float* x  = (const float*)d_in[0];
    const float* wq = (const float*)d_in[1];
    const float* wk = (const float*)d_in[2];
    const float* wv = (const float*)d_in[3];
    float* out = (float*)d_out;

    cudaFuncSetAttribute(qkv_kernel, cudaFuncAttributeMaxDynamicSharedMemorySize, 98304);
    cudaFuncSetAttribute(scores_kernel, cudaFuncAttributeMaxDynamicSharedMemorySize, 98304);

    cvt_x_kernel<<<SEQ * CTX / 4 / 256, 256>>>(x);
    cvt_w_kernel<<<3 * DK * 512 / 256, 256>>>(wq, wk, wv);
    qkv_kernel<<<dim3(SEQ / 64, 3), 256, 98304>>>();
    scores_kernel<<<dim3(SEQ / 64, SEQ / 128), 256, 98304>>>();
    combine_kernel<<<SEQ / 256, 256>>>();
    pv_kernel<<<dim3(SPLIT, SEQ / 64), 256>>>();
    pv_reduce_kernel<<<SEQ * DK / 256, 256>>>(out);
}

// round 8
// speedup vs baseline: 4.5908x; 1.0968x over previous
#include <cuda_runtime.h>
#include <cuda_fp16.h>
#include <cstdint>

#define SEQ 8192
#define CTX 2048
#define DK  128
#define NT  64                    // SEQ/128 s-tiles
#define SPLIT 16
#define TCH (SEQ / SPLIT)         // 512 t-columns per pv block
#define NCHUNK (TCH / 8)          // 64 chunks per pv block
#define SCALE 11.313708498984760f
#define THRESH -25.0f

// ---- scratch (device globals) ----
// blocked pair-plane format: per row, per 32-k block: [hi 32 bf16 (64B) | lo 32 bf16 (64B)]
__device__ uint32_t g_xb[(size_t)SEQ * (CTX / 32) * 32];   // 64 MB (words)
__device__ uint32_t g_wb[3 * DK * (CTX / 32) * 32];        // 3 MB
__device__ uint32_t g_qb[(size_t)SEQ * (DK / 32) * 32];    // 4 MB
__device__ uint32_t g_kb[(size_t)SEQ * (DK / 32) * 32];    // 4 MB
__device__ float  g_v[SEQ * DK];
__device__ __half g_sch[(size_t)SEQ * SEQ];                // 128 MB fp16 (sc - m_tile)
__device__ float  g_pm[NT * SEQ];
__device__ float  g_pzt[NT * SEQ];
__device__ float  g_m[SEQ];
__device__ float  g_rz[SEQ];
__device__ float  g_po[SPLIT][SEQ * DK];

// ============================================================
// helpers
// ============================================================
__device__ __forceinline__ uint32_t smem_u32(const void* p) {
    uint32_t a;
    asm("{ .reg .u64 t; cvta.to.shared.u64 t, %1; cvt.u32.u64 %0, t; }" : "=r"(a) : "l"(p));
    return a;
}
__device__ __forceinline__ void cp16(uint32_t dst, const void* src) {
    asm volatile("cp.async.cg.shared.global [%0], [%1], 16;" :: "r"(dst), "l"(src));
}
#define CP_COMMIT asm volatile("cp.async.commit_group;" ::: "memory")
#define CP_WAIT0  asm volatile("cp.async.wait_group 0;" ::: "memory")

__device__ __forceinline__ uint2 split2(float x0, float x1) {
    uint32_t h, l;
    asm("cvt.rn.bf16x2.f32 %0, %1, %2;" : "=r"(h) : "f"(x1), "f"(x0));
    float h0 = __uint_as_float(h << 16);
    float h1 = __uint_as_float(h & 0xffff0000u);
    asm("cvt.rn.bf16x2.f32 %0, %1, %2;" : "=r"(l) : "f"(x1 - h1), "f"(x0 - h0));
    return make_uint2(h, l);
}
__device__ __forceinline__ void mma16(float* c, const uint32_t* a, const uint32_t* b) {
    asm("mma.sync.aligned.m16n8k16.row.col.f32.bf16.bf16.f32 "
        "{%0,%1,%2,%3}, {%4,%5,%6,%7}, {%8,%9}, {%0,%1,%2,%3};"
        : "+f"(c[0]), "+f"(c[1]), "+f"(c[2]), "+f"(c[3])
        : "r"(a[0]), "r"(a[1]), "r"(a[2]), "r"(a[3]), "r"(b[0]), "r"(b[1]));
}
__device__ __forceinline__ void ldsm_x4(uint32_t* d, uint32_t a) {
    asm volatile("ldmatrix.sync.aligned.m8n8.x4.shared.b16 {%0,%1,%2,%3}, [%4];"
                 : "=r"(d[0]), "=r"(d[1]), "=r"(d[2]), "=r"(d[3]) : "r"(a));
}
// row = rowb bytes, per-128B-block swizzle: chunk ^= row&7
__device__ __forceinline__ uint32_t tadr(uint32_t base, int row, int rowb, int blk, int chunk) {
    return base + row * rowb + blk * 128 + (((chunk ^ (row & 7)) & 7) << 4);
}

// ============================================================
// K0a: x -> blocked pair-plane
// ============================================================
__global__ __launch_bounds__(256) void cvt_x_kernel(const float* __restrict__ x)
{
    const int i = blockIdx.x * 256 + threadIdx.x;       // < SEQ*CTX/4
    const int row = i >> 9;
    const int j = i & 511;
    const int k4 = j * 4;
    float4 v = *reinterpret_cast<const float4*>(x + (size_t)row * CTX + k4);
    uint2 p0 = split2(v.x, v.y), p1 = split2(v.z, v.w);
    uint32_t* base = g_xb + (size_t)row * 2048 + (k4 >> 5) * 32;
    const int kw = (k4 & 31) >> 1;
    base[kw] = p0.x; base[kw + 1] = p1.x;
    base[16 + kw] = p0.y; base[16 + kw + 1] = p1.y;
}

// K0b: w^T -> blocked pair-plane, [mat][n][blk]
__global__ __launch_bounds__(256) void cvt_w_kernel(
    const float* __restrict__ wq, const float* __restrict__ wk, const float* __restrict__ wv)
{
    const int i = blockIdx.x * 256 + threadIdx.x;       // < 3*128*512
    const int mat = i / (DK * 512);
    const int r = i % (DK * 512);
    const int n = r >> 9;
    const int k4 = (r & 511) * 4;
    const float* w = (mat == 0) ? wq : (mat == 1) ? wk : wv;
    float w0 = w[(size_t)(k4 + 0) * DK + n];
    float w1 = w[(size_t)(k4 + 1) * DK + n];
    float w2 = w[(size_t)(k4 + 2) * DK + n];
    float w3 = w[(size_t)(k4 + 3) * DK + n];
    uint2 p0 = split2(w0, w1), p1 = split2(w2, w3);
    uint32_t* base = g_wb + ((size_t)(mat * DK + n)) * 2048 + (k4 >> 5) * 32;
    const int kw = (k4 & 31) >> 1;
    base[kw] = p0.x; base[kw + 1] = p1.x;
    base[16 + kw] = p0.y; base[16 + kw + 1] = p1.y;
}

// ============================================================
// K1: Q/K/V = x @ w. Tile 64m x 128n, BK=64, dyn smem 96KB, 2-buf.
// ============================================================
__global__ __launch_bounds__(256, 2) void qkv_kernel()
{
    extern __shared__ uint32_t dsm[];
    const uint32_t base0 = smem_u32(dsm);

    const int m0 = blockIdx.x * 64;
    const int mat = blockIdx.y;
    const int tid = threadIdx.x;
    const int wid = tid >> 5, lane = tid & 31;
    const int g = lane >> 2, tg = lane & 3;
    const int wm = (wid & 1) * 32;
    const int wn = (wid >> 1) * 32;
    const int lr = (lane & 7) + ((lane >> 3) & 1) * 8;
    const int lc = lane >> 4;

    float acc[2][4][4];
#pragma unroll
    for (int i = 0; i < 2; i++)
#pragma unroll
        for (int j = 0; j < 4; j++)
#pragma unroll
            for (int q = 0; q < 4; q++) acc[i][j][q] = 0.f;

#define QKV_ISSUE(kc, buf)                                                        \
    do {                                                                          \
        _Pragma("unroll")                                                         \
        for (int j = 0; j < 4; j++) {                                             \
            int idx = tid + j * 256, row = idx >> 4, c = idx & 15;                \
            int blk = c >> 3, q = c & 7;                                          \
            cp16(base0 + (buf) * 16384 + row * 256 + blk * 128 + ((q ^ (row & 7)) << 4), \
                 g_xb + (size_t)(m0 + row) * 2048 + ((kc) * 2 + blk) * 32 + q * 4);      \
        }                                                                         \
        _Pragma("unroll")                                                         \
        for (int j = 0; j < 8; j++) {                                             \
            int idx = tid + j * 256, row = idx >> 4, c = idx & 15;                \
            int blk = c >> 3, q = c & 7;                                          \
            cp16(base0 + 32768 + (buf) * 32768 + row * 256 + blk * 128 + ((q ^ (row & 7)) << 4), \
                 g_wb + (size_t)(mat * DK + row) * 2048 + ((kc) * 2 + blk) * 32 + q * 4);        \
        }                                                                         \
    } while (0)

    QKV_ISSUE(0, 0);
    CP_COMMIT;
    const int NC = CTX / 64;   // 32
    for (int kc = 0; kc < NC; kc++) {
        CP_WAIT0;
        __syncthreads();
        if (kc + 1 < NC) { QKV_ISSUE(kc + 1, (kc + 1) & 1); CP_COMMIT; }
        const int buf = kc & 1;
        const uint32_t aB = base0 + buf * 16384;
        const uint32_t bB = base0 + 32768 + buf * 32768;
#pragma unroll
        for (int blk = 0; blk < 2; blk++) {
#pragma unroll
            for (int half = 0; half < 2; half++) {
                uint32_t Ah[2][4], Al[2][4], Bh[2][4], Bl[2][4];
#pragma unroll
                for (int mt = 0; mt < 2; mt++) {
                    int r = wm + mt * 16 + lr;
                    ldsm_x4(Ah[mt], tadr(aB, r, 256, blk, half * 2 + lc));
                    ldsm_x4(Al[mt], tadr(aB, r, 256, blk, 4 + half * 2 + lc));
                }
#pragma unroll
                for (int pr = 0; pr < 2; pr++) {
                    int r = wn + pr * 16 + lr;
                    ldsm_x4(Bh[pr], tadr(bB, r, 256, blk, half * 2 + lc));
                    ldsm_x4(Bl[pr], tadr(bB, r, 256, blk, 4 + half * 2 + lc));
                }
#pragma unroll
                for (int nt = 0; nt < 4; nt++) {
                    uint32_t bh[2] = {Bh[nt >> 1][nt & 1], Bh[nt >> 1][2 + (nt & 1)]};
#pragma unroll
                    for (int mt = 0; mt < 2; mt++) mma16(acc[mt][nt], Ah[mt], bh);
                }
#pragma unroll
                for (int nt = 0; nt < 4; nt++) {
                    uint32_t bl[2] = {Bl[nt >> 1][nt & 1], Bl[nt >> 1][2 + (nt & 1)]};
#pragma unroll
                    for (int mt = 0; mt < 2; mt++) mma16(acc[mt][nt], Ah[mt], bl);
                }
#pragma unroll
                for (int nt = 0; nt < 4; nt++) {
                    uint32_t bh[2] = {Bh[nt >> 1][nt & 1], Bh[nt >> 1][2 + (nt & 1)]};
#pragma unroll
                    for (int mt = 0; mt < 2; mt++) mma16(acc[mt][nt], Al[mt], bh);
                }
            }
        }
    }
#undef QKV_ISSUE

#pragma unroll
    for (int mt = 0; mt < 2; mt++) {
#pragma unroll
        for (int nt = 0; nt < 4; nt++) {
            const int r0 = m0 + wm + mt * 16 + g;
            const int col = wn + nt * 8 + 2 * tg;
            if (mat == 2) {
                *reinterpret_cast<float2*>(g_v + (size_t)r0 * DK + col) =
                    make_float2(acc[mt][nt][0], acc[mt][nt][1]);
                *reinterpret_cast<float2*>(g_v + (size_t)(r0 + 8) * DK + col) =
                    make_float2(acc[mt][nt][2], acc[mt][nt][3]);
            } else {
                uint32_t* dst = (mat == 0) ? g_qb : g_kb;
                const int blk = col >> 5, kw = (col & 31) >> 1;
                uint2 p0 = split2(acc[mt][nt][0], acc[mt][nt][1]);
                uint2 p1 = split2(acc[mt][nt][2], acc[mt][nt][3]);
                uint32_t* b0 = dst + (size_t)r0 * 128 + blk * 32;
                uint32_t* b1 = dst + (size_t)(r0 + 8) * 128 + blk * 32;
                b0[kw] = p0.x; b0[16 + kw] = p0.y;
                b1[kw] = p1.x; b1[16 + kw] = p1.y;
            }
        }
    }
}

// ============================================================
// K2: scores tile 128(s) x 64(t), FULL K=128 resident (one-shot 96KB).
// ============================================================
__global__ __launch_bounds__(256, 2) void scores_kernel()
{
    extern __shared__ uint32_t dsm[];
    const uint32_t sqAddr = smem_u32(dsm);
    const uint32_t skAddr = sqAddr + 65536;

    const int t0 = blockIdx.x * 64, s0 = blockIdx.y * 128;
    const int tid = threadIdx.x;
    const int wid = tid >> 5, lane = tid & 31;
    const int g = lane >> 2, tg = lane & 3;
    const int wm = (wid & 3) * 32;
    const int wn = (wid >> 2) * 32;
    const int lr = (lane & 7) + ((lane >> 3) & 1) * 8;
    const int lc = lane >> 4;

    float acc[2][4][4];
#pragma unroll
    for (int i = 0; i < 2; i++)
#pragma unroll
        for (int j = 0; j < 4; j++)
#pragma unroll
            for (int q = 0; q < 4; q++) acc[i][j][q] = 0.f;

#pragma unroll
    for (int j = 0; j < 16; j++) {
        int idx = tid + j * 256, row = idx >> 5, c = idx & 31;
        int blk = c >> 3, q = c & 7;
        cp16(sqAddr + row * 512 + blk * 128 + ((q ^ (row & 7)) << 4),
             g_qb + (size_t)(s0 + row) * 128 + blk * 32 + q * 4);
    }
#pragma unroll
    for (int j = 0; j < 8; j++) {
        int idx = tid + j * 256, row = idx >> 5, c = idx & 31;
        int blk = c >> 3, q = c & 7;
        cp16(skAddr + row * 512 + blk * 128 + ((q ^ (row & 7)) << 4),
             g_kb + (size_t)(t0 + row) * 128 + blk * 32 + q * 4);
    }
    CP_COMMIT;
    CP_WAIT0;
    __syncthreads();

#pragma unroll
    for (int blk = 0; blk < 4; blk++) {
#pragma unroll
        for (int half = 0; half < 2; half++) {
            uint32_t Ah[2][4], Al[2][4], Bh[2][4], Bl[2][4];
#pragma unroll
            for (int mt = 0; mt < 2; mt++) {
                int r = wm + mt * 16 + lr;
                ldsm_x4(Ah[mt], tadr(sqAddr, r, 512, blk, half * 2 + lc));
                ldsm_x4(Al[mt], tadr(sqAddr, r, 512, blk, 4 + half * 2 + lc));
            }
#pragma unroll
            for (int pr = 0; pr < 2; pr++) {
                int r = wn + pr * 16 + lr;
                ldsm_x4(Bh[pr], tadr(skAddr, r, 512, blk, half * 2 + lc));
                ldsm_x4(Bl[pr], tadr(skAddr, r, 512, blk, 4 + half * 2 + lc));
            }
#pragma unroll
            for (int nt = 0; nt < 4; nt++) {
                uint32_t bh[2] = {Bh[nt >> 1][nt & 1], Bh[nt >> 1][2 + (nt & 1)]};
#pragma unroll
                for (int mt = 0; mt < 2; mt++) mma16(acc[mt][nt], Ah[mt], bh);
            }
#pragma unroll
            for (int nt = 0; nt < 4; nt++) {
                uint32_t bl[2] = {Bl[nt >> 1][nt & 1], Bl[nt >> 1][2 + (nt & 1)]};
#pragma unroll
                for (int mt = 0; mt < 2; mt++) mma16(acc[mt][nt], Ah[mt], bl);
            }
#pragma unroll
            for (int nt = 0; nt < 4; nt++) {
                uint32_t bh[2] = {Bh[nt >> 1][nt & 1], Bh[nt >> 1][2 + (nt & 1)]};
#pragma unroll
                for (int mt = 0; mt < 2; mt++) mma16(acc[mt][nt], Al[mt], bh);
            }
        }
    }

    __syncthreads();
    float (*s_red)[64] = reinterpret_cast<float(*)[64]>(dsm + 16384);

#pragma unroll
    for (int mt = 0; mt < 2; mt++)
#pragma unroll
        for (int nt = 0; nt < 4; nt++)
#pragma unroll
            for (int q = 0; q < 4; q++) acc[mt][nt][q] *= SCALE;

    float cm[8];
#pragma unroll
    for (int nt = 0; nt < 4; nt++) {
        float a0 = fmaxf(fmaxf(acc[0][nt][0], acc[0][nt][2]), fmaxf(acc[1][nt][0], acc[1][nt][2]));
        float a1 = fmaxf(fmaxf(acc[0][nt][1], acc[0][nt][3]), fmaxf(acc[1][nt][1], acc[1][nt][3]));
        cm[nt * 2] = a0; cm[nt * 2 + 1] = a1;
    }
#pragma unroll
    for (int off = 4; off < 32; off <<= 1)
#pragma unroll
        for (int j = 0; j < 8; j++)
            cm[j] = fmaxf(cm[j], __shfl_xor_sync(0xffffffffu, cm[j], off));
    if (g == 0) {
#pragma unroll
        for (int nt = 0; nt < 4; nt++) {
            s_red[wid & 3][wn + nt * 8 + 2 * tg + 0] = cm[nt * 2 + 0];
            s_red[wid & 3][wn + nt * 8 + 2 * tg + 1] = cm[nt * 2 + 1];
        }
    }
    __syncthreads();
    float m4 = 0.f;
    if (tid < 64) {
        m4 = fmaxf(fmaxf(s_red[0][tid], s_red[1][tid]), fmaxf(s_red[2][tid], s_red[3][tid]));
        g_pm[(s0 >> 7) * SEQ + t0 + tid] = m4;
    }
    __syncthreads();
    if (tid < 64) s_red[0][tid] = m4;
    __syncthreads();

    float mcol[8];
#pragma unroll
    for (int nt = 0; nt < 4; nt++) {
        const int c = wn + nt * 8 + 2 * tg;
        mcol[nt * 2 + 0] = s_red[0][c];
        mcol[nt * 2 + 1] = s_red[0][c + 1];
    }

    float z[8];
#pragma unroll
    for (int j = 0; j < 8; j++) z[j] = 0.f;
#pragma unroll
    for (int mt = 0; mt < 2; mt++) {
#pragma unroll
        for (int nt = 0; nt < 4; nt++) {
            const int r0 = s0 + wm + mt * 16 + g;
            const int col = t0 + wn + nt * 8 + 2 * tg;
            float d00 = acc[mt][nt][0] - mcol[nt * 2],     d01 = acc[mt][nt][1] - mcol[nt * 2 + 1];
            float d10 = acc[mt][nt][2] - mcol[nt * 2],     d11 = acc[mt][nt][3] - mcol[nt * 2 + 1];
            *reinterpret_cast<__half2*>(&g_sch[(size_t)r0 * SEQ + col]) = __floats2half2_rn(d00, d01);
            *reinterpret_cast<__half2*>(&g_sch[(size_t)(r0 + 8) * SEQ + col]) = __floats2half2_rn(d10, d11);
            z[nt * 2 + 0] += (d00 > THRESH ? __expf(d00) : 0.f) + (d10 > THRESH ? __expf(d10) : 0.f);
            z[nt * 2 + 1] += (d01 > THRESH ? __expf(d01) : 0.f) + (d11 > THRESH ? __expf(d11) : 0.f);
        }
    }
#pragma unroll
    for (int off = 4; off < 32; off <<= 1)
#pragma unroll
        for (int j = 0; j < 8; j++)
            z[j] += __shfl_xor_sync(0xffffffffu, z[j], off);
    __syncthreads();
    if (g == 0) {
#pragma unroll
        for (int nt = 0; nt < 4; nt++) {
            s_red[wid & 3][wn + nt * 8 + 2 * tg + 0] = z[nt * 2 + 0];
            s_red[wid & 3][wn + nt * 8 + 2 * tg + 1] = z[nt * 2 + 1];
        }
    }
    __syncthreads();
    if (tid < 64)
        g_pzt[(s0 >> 7) * SEQ + t0 + tid] =
            (s_red[0][tid] + s_red[1][tid]) + (s_red[2][tid] + s_red[3][tid]);
}

// ============================================================
// K3: combine tile stats -> global m_t and 1/Z_t
// ============================================================
__global__ void combine_kernel()
{
    const int t = blockIdx.x * 256 + threadIdx.x;
    float m = -3.4e38f;
#pragma unroll 8
    for (int b = 0; b < NT; b++) m = fmaxf(m, g_pm[b * SEQ + t]);
    float Z = 0.f;
#pragma unroll 8
    for (int b = 0; b < NT; b++) {
        float d = g_pm[b * SEQ + t] - m;
        if (d > THRESH - 10.f) Z += g_pzt[b * SEQ + t] * __expf(d);
    }
    g_m[t] = m;
    g_rz[t] = 1.0f / Z;
}

// ============================================================
// K4: split-K PV with chunk-level liveness skip.
// grid (SPLIT, SEQ/64). Chunk (8 t-cols) dead iff max(s_adj) <= THRESH:
// then every P element in the 64x8 chunk is < e^-25 == previously-dropped zero.
// Dead chunks: 1 smem flag read. Live-but-inactive iterations: 1 barrier.
// ============================================================
__global__ __launch_bounds__(256) void pv_kernel()
{
    __shared__ float s_adj[TCH];
    __shared__ float s_rz[TCH];
    __shared__ char  s_flag[NCHUNK];
    __shared__ float sA[8][64];
    __shared__ float sB[8][128];
    const int s0 = blockIdx.y * 64;
    const int tb = blockIdx.x * TCH;
    const int b = blockIdx.y >> 1;
    const int tid = threadIdx.x;
    const int tx = tid & 15, ty = tid >> 4;
    const int ar = tid >> 2, ac = (tid & 3) * 2;
    const int br = tid >> 5, bc = (tid & 31) * 4;

#pragma unroll
    for (int j = 0; j < 2; j++) {
        int t = tid + j * 256;
        s_adj[t] = g_pm[b * SEQ + tb + t] - g_m[tb + t];
        s_rz[t] = g_rz[tb + t];
    }
    __syncthreads();
    if (tid < NCHUNK) {
        float mx = -3.4e38f;
#pragma unroll
        for (int j = 0; j < 8; j++) mx = fmaxf(mx, s_adj[tid * 8 + j]);
        s_flag[tid] = (mx > THRESH) ? 1 : 0;
    }

    float acc[4][8];
#pragma unroll
    for (int i = 0; i < 4; i++)
#pragma unroll
        for (int j = 0; j < 8; j++) acc[i][j] = 0.f;

    const __half* sp = g_sch + (size_t)(s0 + ar) * SEQ + tb + ac;
    __syncthreads();

    for (int c = 0; c < NCHUNK; c++) {
        if (!s_flag[c]) continue;                 // uniform: chunk provably dead
        const int k0 = c * 8;
        __half2 hv = *reinterpret_cast<const __half2*>(sp + k0);
        float2 fv = __half22float2(hv);
        float dd0 = fv.x + s_adj[k0 + ac];
        float dd1 = fv.y + s_adj[k0 + ac + 1];
        float p0 = 0.f, p1 = 0.f;
        if (fmaxf(dd0, dd1) > THRESH) {
            if (dd0 > THRESH) p0 = __expf(dd0);
            if (dd1 > THRESH) p1 = __expf(dd1);
        }
        // barrier doubles as WAR guard vs previous iteration's FMA reads
        int active = __syncthreads_or(p0 != 0.f || p1 != 0.f);
        if (!active) continue;
        float rzv = s_rz[k0 + br];
        float4 bv = *reinterpret_cast<const float4*>(g_v + (size_t)(tb + k0 + br) * DK + bc);
        sA[ac][ar] = p0;
        sA[ac + 1][ar] = p1;
        *reinterpret_cast<float4*>(&sB[br][bc]) =
            make_float4(bv.x * rzv, bv.y * rzv, bv.z * rzv, bv.w * rzv);
        __syncthreads();
#pragma unroll
        for (int kk = 0; kk < 8; kk++) {
            float4 a  = *reinterpret_cast<const float4*>(&sA[kk][ty * 4]);
            float4 b0 = *reinterpret_cast<const float4*>(&sB[kk][tx * 8]);
            float4 b1 = *reinterpret_cast<const float4*>(&sB[kk][tx * 8 + 4]);
            float aa[4] = {a.x, a.y, a.z, a.w};
            float bb[8] = {b0.x, b0.y, b0.z, b0.w, b1.x, b1.y, b1.z, b1.w};
#pragma unroll
            for (int i = 0; i < 4; i++)
#pragma unroll
                for (int j = 0; j < 8; j++) acc[i][j] += aa[i] * bb[j];
        }
    }
    float* po = g_po[blockIdx.x];
#pragma unroll
    for (int i = 0; i < 4; i++) {
        float* op = po + (size_t)(s0 + ty * 4 + i) * DK + tx * 8;
        *reinterpret_cast<float4*>(op)     = make_float4(acc[i][0], acc[i][1], acc[i][2], acc[i][3]);
        *reinterpret_cast<float4*>(op + 4) = make_float4(acc[i][4], acc[i][5], acc[i][6], acc[i][7]);
    }
}

// K5: fixed-order split reduction
__global__ void pv_reduce_kernel(float* __restrict__ out)
{
    const int i = blockIdx.x * 256 + threadIdx.x;
    float s = 0.f;
#pragma unroll
    for (int p = 0; p < SPLIT; p++) s += g_po[p][i];
    out[i] = s;
}

// ============================================================
extern "C" void kernel_launch(void* const* d_in, const int* in_sizes, int n_in,
                              void* d_out, int out_size)
{
    const float* x  = (const float*)d_in[0];
    const float* wq = (const float*)d_in[1];
    const float* wk = (const float*)d_in[2];
    const float* wv = (const float*)d_in[3];
    float* out = (float*)d_out;

    cudaFuncSetAttribute(qkv_kernel, cudaFuncAttributeMaxDynamicSharedMemorySize, 98304);
    cudaFuncSetAttribute(scores_kernel, cudaFuncAttributeMaxDynamicSharedMemorySize, 98304);

    cvt_x_kernel<<<SEQ * CTX / 4 / 256, 256>>>(x);
    cvt_w_kernel<<<3 * DK * 512 / 256, 256>>>(wq, wk, wv);
    qkv_kernel<<<dim3(SEQ / 64, 3), 256, 98304>>>();
    scores_kernel<<<dim3(SEQ / 64, SEQ / 128), 256, 98304>>>();
    combine_kernel<<<SEQ / 256, 256>>>();
    pv_kernel<<<dim3(SPLIT, SEQ / 64), 256>>>();
    pv_reduce_kernel<<<SEQ * DK / 256, 256>>>(out);
}

// round 9
// speedup vs baseline: 4.6004x; 1.0021x over previous
#include <cuda_runtime.h>
#include <cuda_fp16.h>
#include <cstdint>

#define SEQ 8192
#define CTX 2048
#define DK  128
#define NT  64                    // SEQ/128 s-tiles
#define SPLIT 16
#define TCH (SEQ / SPLIT)         // 512 t-columns per pv block
#define NCHUNK (TCH / 8)          // 64 chunks per pv block
#define SCALE 11.313708498984760f
#define THRESH -25.0f

// ---- scratch (device globals) ----
// blocked pair-plane format: per row, per 32-k block: [hi 32 bf16 (64B) | lo 32 bf16 (64B)]
__device__ uint32_t g_xb[(size_t)SEQ * (CTX / 32) * 32];   // 64 MB (words)
__device__ uint32_t g_wb[3 * DK * (CTX / 32) * 32];        // 3 MB
__device__ uint32_t g_qb[(size_t)SEQ * (DK / 32) * 32];    // 4 MB
__device__ uint32_t g_kb[(size_t)SEQ * (DK / 32) * 32];    // 4 MB
__device__ float  g_v[SEQ * DK];
__device__ __half g_sch[(size_t)SEQ * SEQ];                // 128 MB fp16 (sc - m_tile)
__device__ float  g_pm[NT * SEQ];
__device__ float  g_pzt[NT * SEQ];
__device__ float  g_m[SEQ];
__device__ float  g_rz[SEQ];
__device__ float  g_po[SPLIT][SEQ * DK];

// ============================================================
// helpers
// ============================================================
__device__ __forceinline__ uint32_t smem_u32(const void* p) {
    uint32_t a;
    asm("{ .reg .u64 t; cvta.to.shared.u64 t, %1; cvt.u32.u64 %0, t; }" : "=r"(a) : "l"(p));
    return a;
}
__device__ __forceinline__ void cp16(uint32_t dst, const void* src) {
    asm volatile("cp.async.cg.shared.global [%0], [%1], 16;" :: "r"(dst), "l"(src));
}
#define CP_COMMIT asm volatile("cp.async.commit_group;" ::: "memory")
#define CP_WAIT0  asm volatile("cp.async.wait_group 0;" ::: "memory")

__device__ __forceinline__ uint2 split2(float x0, float x1) {
    uint32_t h, l;
    asm("cvt.rn.bf16x2.f32 %0, %1, %2;" : "=r"(h) : "f"(x1), "f"(x0));
    float h0 = __uint_as_float(h << 16);
    float h1 = __uint_as_float(h & 0xffff0000u);
    asm("cvt.rn.bf16x2.f32 %0, %1, %2;" : "=r"(l) : "f"(x1 - h1), "f"(x0 - h0));
    return make_uint2(h, l);
}
__device__ __forceinline__ void mma16(float* c, const uint32_t* a, const uint32_t* b) {
    asm("mma.sync.aligned.m16n8k16.row.col.f32.bf16.bf16.f32 "
        "{%0,%1,%2,%3}, {%4,%5,%6,%7}, {%8,%9}, {%0,%1,%2,%3};"
        : "+f"(c[0]), "+f"(c[1]), "+f"(c[2]), "+f"(c[3])
        : "r"(a[0]), "r"(a[1]), "r"(a[2]), "r"(a[3]), "r"(b[0]), "r"(b[1]));
}
__device__ __forceinline__ void ldsm_x4(uint32_t* d, uint32_t a) {
    asm volatile("ldmatrix.sync.aligned.m8n8.x4.shared.b16 {%0,%1,%2,%3}, [%4];"
                 : "=r"(d[0]), "=r"(d[1]), "=r"(d[2]), "=r"(d[3]) : "r"(a));
}

// ============================================================
// K0a: x -> blocked pair-plane
// ============================================================
__global__ __launch_bounds__(256) void cvt_x_kernel(const float* __restrict__ x)
{
    const int i = blockIdx.x * 256 + threadIdx.x;       // < SEQ*CTX/4
    const int row = i >> 9;
    const int j = i & 511;
    const int k4 = j * 4;
    float4 v = *reinterpret_cast<const float4*>(x + (size_t)row * CTX + k4);
    uint2 p0 = split2(v.x, v.y), p1 = split2(v.z, v.w);
    uint32_t* base = g_xb + (size_t)row * 2048 + (k4 >> 5) * 32;
    const int kw = (k4 & 31) >> 1;
    base[kw] = p0.x; base[kw + 1] = p1.x;
    base[16 + kw] = p0.y; base[16 + kw + 1] = p1.y;
}

// K0b: w^T -> blocked pair-plane, [mat][n][blk]
__global__ __launch_bounds__(256) void cvt_w_kernel(
    const float* __restrict__ wq, const float* __restrict__ wk, const float* __restrict__ wv)
{
    const int i = blockIdx.x * 256 + threadIdx.x;       // < 3*128*512
    const int mat = i / (DK * 512);
    const int r = i % (DK * 512);
    const int n = r >> 9;
    const int k4 = (r & 511) * 4;
    const float* w = (mat == 0) ? wq : (mat == 1) ? wk : wv;
    float w0 = w[(size_t)(k4 + 0) * DK + n];
    float w1 = w[(size_t)(k4 + 1) * DK + n];
    float w2 = w[(size_t)(k4 + 2) * DK + n];
    float w3 = w[(size_t)(k4 + 3) * DK + n];
    uint2 p0 = split2(w0, w1), p1 = split2(w2, w3);
    uint32_t* base = g_wb + ((size_t)(mat * DK + n)) * 2048 + (k4 >> 5) * 32;
    const int kw = (k4 & 31) >> 1;
    base[kw] = p0.x; base[kw + 1] = p1.x;
    base[16 + kw] = p0.y; base[16 + kw + 1] = p1.y;
}

// ============================================================
// K1: Q/K/V = x @ w. Tile 64m x 128n, BK=64, dyn smem 96KB, 2-buf.
// Hoisted LDSM base addresses: loop body = IADD + LDSM + HMMA only.
// ============================================================
__global__ __launch_bounds__(256, 2) void qkv_kernel()
{
    extern __shared__ uint32_t dsm[];
    const uint32_t base0 = smem_u32(dsm);

    const int m0 = blockIdx.x * 64;
    const int mat = blockIdx.y;
    const int tid = threadIdx.x;
    const int wid = tid >> 5, lane = tid & 31;
    const int g = lane >> 2, tg = lane & 3;
    const int wm = (wid & 1) * 32;
    const int wn = (wid >> 1) * 32;
    const int lr = (lane & 7) + ((lane >> 3) & 1) * 8;
    const int lc = lane >> 4;

    float acc[2][4][4];
#pragma unroll
    for (int i = 0; i < 2; i++)
#pragma unroll
        for (int j = 0; j < 4; j++)
#pragma unroll
            for (int q = 0; q < 4; q++) acc[i][j][q] = 0.f;

    // hoisted LDSM bases: [mt|pr][plane][half]; add buf/blk offsets in-loop
    uint32_t aAd[2][2][2], bAd[2][2][2];
#pragma unroll
    for (int mt = 0; mt < 2; mt++)
#pragma unroll
        for (int p = 0; p < 2; p++)
#pragma unroll
            for (int h = 0; h < 2; h++) {
                const int ra = wm + mt * 16 + lr;
                const int rb = wn + mt * 16 + lr;
                const int ck = p * 4 + h * 2 + lc;
                aAd[mt][p][h] = base0 + ra * 256 + (((ck ^ (ra & 7)) & 7) << 4);
                bAd[mt][p][h] = base0 + 32768 * 4 / 4 + rb * 256 + (((ck ^ (rb & 7)) & 7) << 4);
            }

#define QKV_ISSUE(kc, buf)                                                        \
    do {                                                                          \
        _Pragma("unroll")                                                         \
        for (int j = 0; j < 4; j++) {                                             \
            int idx = tid + j * 256, row = idx >> 4, c = idx & 15;                \
            int blk = c >> 3, q = c & 7;                                          \
            cp16(base0 + (buf) * 16384 + row * 256 + blk * 128 + ((q ^ (row & 7)) << 4), \
                 g_xb + (size_t)(m0 + row) * 2048 + ((kc) * 2 + blk) * 32 + q * 4);      \
        }                                                                         \
        _Pragma("unroll")                                                         \
        for (int j = 0; j < 8; j++) {                                             \
            int idx = tid + j * 256, row = idx >> 4, c = idx & 15;                \
            int blk = c >> 3, q = c & 7;                                          \
            cp16(base0 + 32768 + (buf) * 32768 + row * 256 + blk * 128 + ((q ^ (row & 7)) << 4), \
                 g_wb + (size_t)(mat * DK + row) * 2048 + ((kc) * 2 + blk) * 32 + q * 4);        \
        }                                                                         \
    } while (0)

    QKV_ISSUE(0, 0);
    CP_COMMIT;
    const int NC = CTX / 64;   // 32
    for (int kc = 0; kc < NC; kc++) {
        CP_WAIT0;
        __syncthreads();
        if (kc + 1 < NC) { QKV_ISSUE(kc + 1, (kc + 1) & 1); CP_COMMIT; }
        const int buf = kc & 1;
        const uint32_t aOff = buf * 16384u;
        const uint32_t bOff = buf * 32768u;
#pragma unroll
        for (int blk = 0; blk < 2; blk++) {
            const uint32_t ao = aOff + blk * 128u;
            const uint32_t bo = bOff + blk * 128u;
#pragma unroll
            for (int h = 0; h < 2; h++) {
                uint32_t Ah[2][4], Al[2][4], Bh[2][4], Bl[2][4];
#pragma unroll
                for (int mt = 0; mt < 2; mt++) {
                    ldsm_x4(Ah[mt], aAd[mt][0][h] + ao);
                    ldsm_x4(Al[mt], aAd[mt][1][h] + ao);
                }
#pragma unroll
                for (int pr = 0; pr < 2; pr++) {
                    ldsm_x4(Bh[pr], bAd[pr][0][h] + bo);
                    ldsm_x4(Bl[pr], bAd[pr][1][h] + bo);
                }
#pragma unroll
                for (int nt = 0; nt < 4; nt++) {
                    uint32_t bh[2] = {Bh[nt >> 1][nt & 1], Bh[nt >> 1][2 + (nt & 1)]};
#pragma unroll
                    for (int mt = 0; mt < 2; mt++) mma16(acc[mt][nt], Ah[mt], bh);
                }
#pragma unroll
                for (int nt = 0; nt < 4; nt++) {
                    uint32_t bl[2] = {Bl[nt >> 1][nt & 1], Bl[nt >> 1][2 + (nt & 1)]};
#pragma unroll
                    for (int mt = 0; mt < 2; mt++) mma16(acc[mt][nt], Ah[mt], bl);
                }
#pragma unroll
                for (int nt = 0; nt < 4; nt++) {
                    uint32_t bh[2] = {Bh[nt >> 1][nt & 1], Bh[nt >> 1][2 + (nt & 1)]};
#pragma unroll
                    for (int mt = 0; mt < 2; mt++) mma16(acc[mt][nt], Al[mt], bh);
                }
            }
        }
    }
#undef QKV_ISSUE

#pragma unroll
    for (int mt = 0; mt < 2; mt++) {
#pragma unroll
        for (int nt = 0; nt < 4; nt++) {
            const int r0 = m0 + wm + mt * 16 + g;
            const int col = wn + nt * 8 + 2 * tg;
            if (mat == 2) {
                *reinterpret_cast<float2*>(g_v + (size_t)r0 * DK + col) =
                    make_float2(acc[mt][nt][0], acc[mt][nt][1]);
                *reinterpret_cast<float2*>(g_v + (size_t)(r0 + 8) * DK + col) =
                    make_float2(acc[mt][nt][2], acc[mt][nt][3]);
            } else {
                uint32_t* dst = (mat == 0) ? g_qb : g_kb;
                const int blk = col >> 5, kw = (col & 31) >> 1;
                uint2 p0 = split2(acc[mt][nt][0], acc[mt][nt][1]);
                uint2 p1 = split2(acc[mt][nt][2], acc[mt][nt][3]);
                uint32_t* b0 = dst + (size_t)r0 * 128 + blk * 32;
                uint32_t* b1 = dst + (size_t)(r0 + 8) * 128 + blk * 32;
                b0[kw] = p0.x; b0[16 + kw] = p0.y;
                b1[kw] = p1.x; b1[16 + kw] = p1.y;
            }
        }
    }
}

// ============================================================
// K2: scores tile 128(s) x 64(t), FULL K=128 resident (one-shot 96KB).
// Hoisted LDSM base addresses.
// ============================================================
__global__ __launch_bounds__(256, 2) void scores_kernel()
{
    extern __shared__ uint32_t dsm[];
    const uint32_t sqAddr = smem_u32(dsm);
    const uint32_t skAddr = sqAddr + 65536;

    const int t0 = blockIdx.x * 64, s0 = blockIdx.y * 128;
    const int tid = threadIdx.x;
    const int wid = tid >> 5, lane = tid & 31;
    const int g = lane >> 2, tg = lane & 3;
    const int wm = (wid & 3) * 32;
    const int wn = (wid >> 2) * 32;
    const int lr = (lane & 7) + ((lane >> 3) & 1) * 8;
    const int lc = lane >> 4;

    float acc[2][4][4];
#pragma unroll
    for (int i = 0; i < 2; i++)
#pragma unroll
        for (int j = 0; j < 4; j++)
#pragma unroll
            for (int q = 0; q < 4; q++) acc[i][j][q] = 0.f;

    // hoisted LDSM bases
    uint32_t aAd[2][2][2], bAd[2][2][2];
#pragma unroll
    for (int mt = 0; mt < 2; mt++)
#pragma unroll
        for (int p = 0; p < 2; p++)
#pragma unroll
            for (int h = 0; h < 2; h++) {
                const int ra = wm + mt * 16 + lr;
                const int rb = wn + mt * 16 + lr;
                const int ck = p * 4 + h * 2 + lc;
                aAd[mt][p][h] = sqAddr + ra * 512 + (((ck ^ (ra & 7)) & 7) << 4);
                bAd[mt][p][h] = skAddr + rb * 512 + (((ck ^ (rb & 7)) & 7) << 4);
            }

#pragma unroll
    for (int j = 0; j < 16; j++) {
        int idx = tid + j * 256, row = idx >> 5, c = idx & 31;
        int blk = c >> 3, q = c & 7;
        cp16(sqAddr + row * 512 + blk * 128 + ((q ^ (row & 7)) << 4),
             g_qb + (size_t)(s0 + row) * 128 + blk * 32 + q * 4);
    }
#pragma unroll
    for (int j = 0; j < 8; j++) {
        int idx = tid + j * 256, row = idx >> 5, c = idx & 31;
        int blk = c >> 3, q = c & 7;
        cp16(skAddr + row * 512 + blk * 128 + ((q ^ (row & 7)) << 4),
             g_kb + (size_t)(t0 + row) * 128 + blk * 32 + q * 4);
    }
    CP_COMMIT;
    CP_WAIT0;
    __syncthreads();

#pragma unroll
    for (int blk = 0; blk < 4; blk++) {
        const uint32_t bo = blk * 128u;
#pragma unroll
        for (int h = 0; h < 2; h++) {
            uint32_t Ah[2][4], Al[2][4], Bh[2][4], Bl[2][4];
#pragma unroll
            for (int mt = 0; mt < 2; mt++) {
                ldsm_x4(Ah[mt], aAd[mt][0][h] + bo);
                ldsm_x4(Al[mt], aAd[mt][1][h] + bo);
            }
#pragma unroll
            for (int pr = 0; pr < 2; pr++) {
                ldsm_x4(Bh[pr], bAd[pr][0][h] + bo);
                ldsm_x4(Bl[pr], bAd[pr][1][h] + bo);
            }
#pragma unroll
            for (int nt = 0; nt < 4; nt++) {
                uint32_t bh[2] = {Bh[nt >> 1][nt & 1], Bh[nt >> 1][2 + (nt & 1)]};
#pragma unroll
                for (int mt = 0; mt < 2; mt++) mma16(acc[mt][nt], Ah[mt], bh);
            }
#pragma unroll
            for (int nt = 0; nt < 4; nt++) {
                uint32_t bl[2] = {Bl[nt >> 1][nt & 1], Bl[nt >> 1][2 + (nt & 1)]};
#pragma unroll
                for (int mt = 0; mt < 2; mt++) mma16(acc[mt][nt], Ah[mt], bl);
            }
#pragma unroll
            for (int nt = 0; nt < 4; nt++) {
                uint32_t bh[2] = {Bh[nt >> 1][nt & 1], Bh[nt >> 1][2 + (nt & 1)]};
#pragma unroll
                for (int mt = 0; mt < 2; mt++) mma16(acc[mt][nt], Al[mt], bh);
            }
        }
    }

    __syncthreads();
    float (*s_red)[64] = reinterpret_cast<float(*)[64]>(dsm + 16384);

#pragma unroll
    for (int mt = 0; mt < 2; mt++)
#pragma unroll
        for (int nt = 0; nt < 4; nt++)
#pragma unroll
            for (int q = 0; q < 4; q++) acc[mt][nt][q] *= SCALE;

    float cm[8];
#pragma unroll
    for (int nt = 0; nt < 4; nt++) {
        float a0 = fmaxf(fmaxf(acc[0][nt][0], acc[0][nt][2]), fmaxf(acc[1][nt][0], acc[1][nt][2]));
        float a1 = fmaxf(fmaxf(acc[0][nt][1], acc[0][nt][3]), fmaxf(acc[1][nt][1], acc[1][nt][3]));
        cm[nt * 2] = a0; cm[nt * 2 + 1] = a1;
    }
#pragma unroll
    for (int off = 4; off < 32; off <<= 1)
#pragma unroll
        for (int j = 0; j < 8; j++)
            cm[j] = fmaxf(cm[j], __shfl_xor_sync(0xffffffffu, cm[j], off));
    if (g == 0) {
#pragma unroll
        for (int nt = 0; nt < 4; nt++) {
            s_red[wid & 3][wn + nt * 8 + 2 * tg + 0] = cm[nt * 2 + 0];
            s_red[wid & 3][wn + nt * 8 + 2 * tg + 1] = cm[nt * 2 + 1];
        }
    }
    __syncthreads();
    float m4 = 0.f;
    if (tid < 64) {
        m4 = fmaxf(fmaxf(s_red[0][tid], s_red[1][tid]), fmaxf(s_red[2][tid], s_red[3][tid]));
        g_pm[(s0 >> 7) * SEQ + t0 + tid] = m4;
    }
    __syncthreads();
    if (tid < 64) s_red[0][tid] = m4;
    __syncthreads();

    float mcol[8];
#pragma unroll
    for (int nt = 0; nt < 4; nt++) {
        const int c = wn + nt * 8 + 2 * tg;
        mcol[nt * 2 + 0] = s_red[0][c];
        mcol[nt * 2 + 1] = s_red[0][c + 1];
    }

    float z[8];
#pragma unroll
    for (int j = 0; j < 8; j++) z[j] = 0.f;
#pragma unroll
    for (int mt = 0; mt < 2; mt++) {
#pragma unroll
        for (int nt = 0; nt < 4; nt++) {
            const int r0 = s0 + wm + mt * 16 + g;
            const int col = t0 + wn + nt * 8 + 2 * tg;
            float d00 = acc[mt][nt][0] - mcol[nt * 2],     d01 = acc[mt][nt][1] - mcol[nt * 2 + 1];
            float d10 = acc[mt][nt][2] - mcol[nt * 2],     d11 = acc[mt][nt][3] - mcol[nt * 2 + 1];
            *reinterpret_cast<__half2*>(&g_sch[(size_t)r0 * SEQ + col]) = __floats2half2_rn(d00, d01);
            *reinterpret_cast<__half2*>(&g_sch[(size_t)(r0 + 8) * SEQ + col]) = __floats2half2_rn(d10, d11);
            z[nt * 2 + 0] += (d00 > THRESH ? __expf(d00) : 0.f) + (d10 > THRESH ? __expf(d10) : 0.f);
            z[nt * 2 + 1] += (d01 > THRESH ? __expf(d01) : 0.f) + (d11 > THRESH ? __expf(d11) : 0.f);
        }
    }
#pragma unroll
    for (int off = 4; off < 32; off <<= 1)
#pragma unroll
        for (int j = 0; j < 8; j++)
            z[j] += __shfl_xor_sync(0xffffffffu, z[j], off);
    __syncthreads();
    if (g == 0) {
#pragma unroll
        for (int nt = 0; nt < 4; nt++) {
            s_red[wid & 3][wn + nt * 8 + 2 * tg + 0] = z[nt * 2 + 0];
            s_red[wid & 3][wn + nt * 8 + 2 * tg + 1] = z[nt * 2 + 1];
        }
    }
    __syncthreads();
    if (tid < 64)
        g_pzt[(s0 >> 7) * SEQ + t0 + tid] =
            (s_red[0][tid] + s_red[1][tid]) + (s_red[2][tid] + s_red[3][tid]);
}

// ============================================================
// K3: combine tile stats -> global m_t and 1/Z_t
// ============================================================
__global__ void combine_kernel()
{
    const int t = blockIdx.x * 256 + threadIdx.x;
    float m = -3.4e38f;
#pragma unroll 8
    for (int b = 0; b < NT; b++) m = fmaxf(m, g_pm[b * SEQ + t]);
    float Z = 0.f;
#pragma unroll 8
    for (int b = 0; b < NT; b++) {
        float d = g_pm[b * SEQ + t] - m;
        if (d > THRESH - 10.f) Z += g_pzt[b * SEQ + t] * __expf(d);
    }
    g_m[t] = m;
    g_rz[t] = 1.0f / Z;
}

// ============================================================
// K4: split-K PV with chunk-level liveness skip (unchanged)
// ============================================================
__global__ __launch_bounds__(256) void pv_kernel()
{
    __shared__ float s_adj[TCH];
    __shared__ float s_rz[TCH];
    __shared__ char  s_flag[NCHUNK];
    __shared__ float sA[8][64];
    __shared__ float sB[8][128];
    const int s0 = blockIdx.y * 64;
    const int tb = blockIdx.x * TCH;
    const int b = blockIdx.y >> 1;
    const int tid = threadIdx.x;
    const int tx = tid & 15, ty = tid >> 4;
    const int ar = tid >> 2, ac = (tid & 3) * 2;
    const int br = tid >> 5, bc = (tid & 31) * 4;

#pragma unroll
    for (int j = 0; j < 2; j++) {
        int t = tid + j * 256;
        s_adj[t] = g_pm[b * SEQ + tb + t] - g_m[tb + t];
        s_rz[t] = g_rz[tb + t];
    }
    __syncthreads();
    if (tid < NCHUNK) {
        float mx = -3.4e38f;
#pragma unroll
        for (int j = 0; j < 8; j++) mx = fmaxf(mx, s_adj[tid * 8 + j]);
        s_flag[tid] = (mx > THRESH) ? 1 : 0;
    }

    float acc[4][8];
#pragma unroll
    for (int i = 0; i < 4; i++)
#pragma unroll
        for (int j = 0; j < 8; j++) acc[i][j] = 0.f;

    const __half* sp = g_sch + (size_t)(s0 + ar) * SEQ + tb + ac;
    __syncthreads();

    for (int c = 0; c < NCHUNK; c++) {
        if (!s_flag[c]) continue;
        const int k0 = c * 8;
        __half2 hv = *reinterpret_cast<const __half2*>(sp + k0);
        float2 fv = __half22float2(hv);
        float dd0 = fv.x + s_adj[k0 + ac];
        float dd1 = fv.y + s_adj[k0 + ac + 1];
        float p0 = 0.f, p1 = 0.f;
        if (fmaxf(dd0, dd1) > THRESH) {
            if (dd0 > THRESH) p0 = __expf(dd0);
            if (dd1 > THRESH) p1 = __expf(dd1);
        }
        int active = __syncthreads_or(p0 != 0.f || p1 != 0.f);
        if (!active) continue;
        float rzv = s_rz[k0 + br];
        float4 bv = *reinterpret_cast<const float4*>(g_v + (size_t)(tb + k0 + br) * DK + bc);
        sA[ac][ar] = p0;
        sA[ac + 1][ar] = p1;
        *reinterpret_cast<float4*>(&sB[br][bc]) =
            make_float4(bv.x * rzv, bv.y * rzv, bv.z * rzv, bv.w * rzv);
        __syncthreads();
#pragma unroll
        for (int kk = 0; kk < 8; kk++) {
            float4 a  = *reinterpret_cast<const float4*>(&sA[kk][ty * 4]);
            float4 b0 = *reinterpret_cast<const float4*>(&sB[kk][tx * 8]);
            float4 b1 = *reinterpret_cast<const float4*>(&sB[kk][tx * 8 + 4]);
            float aa[4] = {a.x, a.y, a.z, a.w};
            float bb[8] = {b0.x, b0.y, b0.z, b0.w, b1.x, b1.y, b1.z, b1.w};
#pragma unroll
            for (int i = 0; i < 4; i++)
#pragma unroll
                for (int j = 0; j < 8; j++) acc[i][j] += aa[i] * bb[j];
        }
    }
    float* po = g_po[blockIdx.x];
#pragma unroll
    for (int i = 0; i < 4; i++) {
        float* op = po + (size_t)(s0 + ty * 4 + i) * DK + tx * 8;
        *reinterpret_cast<float4*>(op)     = make_float4(acc[i][0], acc[i][1], acc[i][2], acc[i][3]);
        *reinterpret_cast<float4*>(op + 4) = make_float4(acc[i][4], acc[i][5], acc[i][6], acc[i][7]);
    }
}

// K5: fixed-order split reduction
__global__ void pv_reduce_kernel(float* __restrict__ out)
{
    const int i = blockIdx.x * 256 + threadIdx.x;
    float s = 0.f;
#pragma unroll
    for (int p = 0; p < SPLIT; p++) s += g_po[p][i];
    out[i] = s;
}

// ============================================================
extern "C" void kernel_launch(void* const* d_in, const int* in_sizes, int n_in,
                              void* d_out, int out_size)
{
    const float* x  = (const float*)d_in[0];
    const float* wq = (const float*)d_in[1];
    const float* wk = (const float*)d_in[2];
    const float* wv = (const float*)d_in[3];
    float* out = (float*)d_out;

    cudaFuncSetAttribute(qkv_kernel, cudaFuncAttributeMaxDynamicSharedMemorySize, 98304);
    cudaFuncSetAttribute(scores_kernel, cudaFuncAttributeMaxDynamicSharedMemorySize, 98304);

    cvt_x_kernel<<<SEQ * CTX / 4 / 256, 256>>>(x);
    cvt_w_kernel<<<3 * DK * 512 / 256, 256>>>(wq, wk, wv);
    qkv_kernel<<<dim3(SEQ / 64, 3), 256, 98304>>>();
    scores_kernel<<<dim3(SEQ / 64, SEQ / 128), 256, 98304>>>();
    combine_kernel<<<SEQ / 256, 256>>>();
    pv_kernel<<<dim3(SPLIT, SEQ / 64), 256>>>();
    pv_reduce_kernel<<<SEQ * DK / 256, 256>>>(out);
}

// round 11
// speedup vs baseline: 5.6013x; 1.2175x over previous
#include <cuda_runtime.h>
#include <cuda_fp16.h>
#include <cstdint>

#define SEQ 8192
#define CTX 2048
#define DK  128
#define NT  64                    // SEQ/128 s-tiles
#define SPLIT 16
#define TCH (SEQ / SPLIT)         // 512 t-columns per pv block
#define NCHUNK (TCH / 8)          // 64 chunks per pv block
#define SCALE 11.313708498984760f
#define THRESH -25.0f

// ---- scratch (device globals) ----
// fp16 single-plane (A-side): row-major fp16, 2 values/word
__device__ uint32_t g_xh[(size_t)SEQ * (CTX / 2)];         // 32 MB
__device__ uint32_t g_qh[(size_t)SEQ * (DK / 2)];          // 2 MB
// fp16 pair-plane (B-side): per row, per 32-k block: [hi 32 fp16 (64B) | lo 32 fp16 (64B)]
// => 2048 words per w-row (CTX values), 128 words per k-row (DK values)
__device__ uint32_t g_wb[3 * DK * CTX];                    // 6 MB  (FIX: pair format needs CTX words/row)
__device__ uint32_t g_kb[(size_t)SEQ * DK];                // 4 MB
__device__ float  g_v[SEQ * DK];
__device__ __half g_sch[(size_t)SEQ * SEQ];                // 128 MB fp16 (sc - m_tile)
__device__ float  g_pm[NT * SEQ];
__device__ float  g_pzt[NT * SEQ];
__device__ float  g_m[SEQ];
__device__ float  g_rz[SEQ];
__device__ float  g_po[SPLIT][SEQ * DK];

// ============================================================
// helpers
// ============================================================
__device__ __forceinline__ uint32_t smem_u32(const void* p) {
    uint32_t a;
    asm("{ .reg .u64 t; cvta.to.shared.u64 t, %1; cvt.u32.u64 %0, t; }" : "=r"(a) : "l"(p));
    return a;
}
__device__ __forceinline__ void cp16(uint32_t dst, const void* src) {
    asm volatile("cp.async.cg.shared.global [%0], [%1], 16;" :: "r"(dst), "l"(src));
}
#define CP_COMMIT asm volatile("cp.async.commit_group;" ::: "memory")
#define CP_WAIT0  asm volatile("cp.async.wait_group 0;" ::: "memory")

// fp16 pack: (x0 -> low, x1 -> high)
__device__ __forceinline__ uint32_t packh2(float x0, float x1) {
    uint32_t h;
    asm("cvt.rn.f16x2.f32 %0, %1, %2;" : "=r"(h) : "f"(x1), "f"(x0));
    return h;
}
// fp16 pair split: hi = rn-fp16, lo = rn-fp16(residual)
__device__ __forceinline__ uint2 split2h(float x0, float x1) {
    uint32_t h = packh2(x0, x1);
    __half2 hh = *reinterpret_cast<__half2*>(&h);
    float f0 = __half2float(__low2half(hh));
    float f1 = __half2float(__high2half(hh));
    uint32_t l = packh2(x0 - f0, x1 - f1);
    return make_uint2(h, l);
}
__device__ __forceinline__ void mma16(float* c, const uint32_t* a, const uint32_t* b) {
    asm("mma.sync.aligned.m16n8k16.row.col.f32.f16.f16.f32 "
        "{%0,%1,%2,%3}, {%4,%5,%6,%7}, {%8,%9}, {%0,%1,%2,%3};"
        : "+f"(c[0]), "+f"(c[1]), "+f"(c[2]), "+f"(c[3])
        : "r"(a[0]), "r"(a[1]), "r"(a[2]), "r"(a[3]), "r"(b[0]), "r"(b[1]));
}
__device__ __forceinline__ void ldsm_x4(uint32_t* d, uint32_t a) {
    asm volatile("ldmatrix.sync.aligned.m8n8.x4.shared.b16 {%0,%1,%2,%3}, [%4];"
                 : "=r"(d[0]), "=r"(d[1]), "=r"(d[2]), "=r"(d[3]) : "r"(a));
}

// ============================================================
// K0a: x -> row-major fp16 single plane
// ============================================================
__global__ __launch_bounds__(256) void cvt_x_kernel(const float* __restrict__ x)
{
    const int i = blockIdx.x * 256 + threadIdx.x;       // < SEQ*CTX/4
    float4 v = reinterpret_cast<const float4*>(x)[i];
    g_xh[2 * (size_t)i]     = packh2(v.x, v.y);
    g_xh[2 * (size_t)i + 1] = packh2(v.z, v.w);
}

// K0b: w^T -> fp16 pair blocked, [mat][n][blk]
__global__ __launch_bounds__(256) void cvt_w_kernel(
    const float* __restrict__ wq, const float* __restrict__ wk, const float* __restrict__ wv)
{
    const int i = blockIdx.x * 256 + threadIdx.x;       // < 3*128*512
    const int mat = i / (DK * 512);
    const int r = i % (DK * 512);
    const int n = r >> 9;
    const int k4 = (r & 511) * 4;
    const float* w = (mat == 0) ? wq : (mat == 1) ? wk : wv;
    float w0 = w[(size_t)(k4 + 0) * DK + n];
    float w1 = w[(size_t)(k4 + 1) * DK + n];
    float w2 = w[(size_t)(k4 + 2) * DK + n];
    float w3 = w[(size_t)(k4 + 3) * DK + n];
    uint2 p0 = split2h(w0, w1), p1 = split2h(w2, w3);
    uint32_t* base = g_wb + ((size_t)(mat * DK + n)) * 2048 + (k4 >> 5) * 32;
    const int kw = (k4 & 31) >> 1;
    base[kw] = p0.x; base[kw + 1] = p1.x;
    base[16 + kw] = p0.y; base[16 + kw + 1] = p1.y;
}

// ============================================================
// K1: Q/K/V = x @ w, 2-pass fp16: D = Xh*(Wh + Wl).
// Tile 64m x 128n, BK=64, dyn smem 80KB, 2-buf.
// smem bytes: A0 [0,8K) A1 [8K,16K) B0 [16K,48K) B1 [48K,80K)
// ============================================================
__global__ __launch_bounds__(256, 2) void qkv_kernel()
{
    extern __shared__ uint32_t dsm[];
    const uint32_t base0 = smem_u32(dsm);

    const int m0 = blockIdx.x * 64;
    const int mat = blockIdx.y;
    const int tid = threadIdx.x;
    const int wid = tid >> 5, lane = tid & 31;
    const int g = lane >> 2, tg = lane & 3;
    const int wm = (wid & 1) * 32;
    const int wn = (wid >> 1) * 32;
    const int lr = (lane & 7) + ((lane >> 3) & 1) * 8;
    const int lc = lane >> 4;

    float acc[2][4][4];
#pragma unroll
    for (int i = 0; i < 2; i++)
#pragma unroll
        for (int j = 0; j < 4; j++)
#pragma unroll
            for (int q = 0; q < 4; q++) acc[i][j][q] = 0.f;

#define QKV_ISSUE(kc, buf)                                                        \
    do {                                                                          \
        _Pragma("unroll")                                                         \
        for (int j = 0; j < 2; j++) {                                             \
            int idx = tid + j * 256, row = idx >> 3, q = idx & 7;                 \
            cp16(base0 + (buf) * 8192 + row * 128 + ((q ^ (row & 7)) << 4),       \
                 g_xh + (size_t)(m0 + row) * (CTX / 2) + (kc) * 32 + q * 4);      \
        }                                                                         \
        _Pragma("unroll")                                                         \
        for (int j = 0; j < 8; j++) {                                             \
            int idx = tid + j * 256, row = idx >> 4, c = idx & 15;                \
            int blk = c >> 3, q = c & 7;                                          \
            cp16(base0 + 16384 + (buf) * 32768 + row * 256 + blk * 128 + ((q ^ (row & 7)) << 4), \
                 g_wb + (size_t)(mat * DK + row) * 2048 + ((kc) * 2 + blk) * 32 + q * 4);        \
        }                                                                         \
    } while (0)

    QKV_ISSUE(0, 0);
    CP_COMMIT;
    const int NC = CTX / 64;   // 32
    for (int kc = 0; kc < NC; kc++) {
        CP_WAIT0;
        __syncthreads();
        if (kc + 1 < NC) { QKV_ISSUE(kc + 1, (kc + 1) & 1); CP_COMMIT; }
        const int buf = kc & 1;
        const uint32_t aB = base0 + buf * 8192u;
        const uint32_t bB = base0 + 16384u + buf * 32768u;
#pragma unroll
        for (int j = 0; j < 4; j++) {            // 4 k16 steps in BK=64
            const int bblk = j >> 1, bh2 = j & 1;
            uint32_t Aq[2][4], Bh[2][4], Bl[2][4];
#pragma unroll
            for (int mt = 0; mt < 2; mt++) {
                const int ra = wm + mt * 16 + lr;
                ldsm_x4(Aq[mt], aB + ra * 128 + (((j * 2 + lc) ^ (ra & 7)) << 4));
            }
#pragma unroll
            for (int pr = 0; pr < 2; pr++) {
                const int rb = wn + pr * 16 + lr;
                const uint32_t rbase = bB + rb * 256 + bblk * 128;
                ldsm_x4(Bh[pr], rbase + (((bh2 * 2 + lc) ^ (rb & 7)) << 4));
                ldsm_x4(Bl[pr], rbase + (((4 + bh2 * 2 + lc) ^ (rb & 7)) << 4));
            }
#pragma unroll
            for (int nt = 0; nt < 4; nt++) {
                uint32_t bh[2] = {Bh[nt >> 1][nt & 1], Bh[nt >> 1][2 + (nt & 1)]};
#pragma unroll
                for (int mt = 0; mt < 2; mt++) mma16(acc[mt][nt], Aq[mt], bh);
            }
#pragma unroll
            for (int nt = 0; nt < 4; nt++) {
                uint32_t bl[2] = {Bl[nt >> 1][nt & 1], Bl[nt >> 1][2 + (nt & 1)]};
#pragma unroll
                for (int mt = 0; mt < 2; mt++) mma16(acc[mt][nt], Aq[mt], bl);
            }
        }
    }
#undef QKV_ISSUE

#pragma unroll
    for (int mt = 0; mt < 2; mt++) {
#pragma unroll
        for (int nt = 0; nt < 4; nt++) {
            const int r0 = m0 + wm + mt * 16 + g;
            const int col = wn + nt * 8 + 2 * tg;
            if (mat == 2) {
                *reinterpret_cast<float2*>(g_v + (size_t)r0 * DK + col) =
                    make_float2(acc[mt][nt][0], acc[mt][nt][1]);
                *reinterpret_cast<float2*>(g_v + (size_t)(r0 + 8) * DK + col) =
                    make_float2(acc[mt][nt][2], acc[mt][nt][3]);
            } else if (mat == 0) {
                g_qh[(size_t)r0 * 64 + (col >> 1)] = packh2(acc[mt][nt][0], acc[mt][nt][1]);
                g_qh[(size_t)(r0 + 8) * 64 + (col >> 1)] = packh2(acc[mt][nt][2], acc[mt][nt][3]);
            } else {
                const int blk = col >> 5, kw = (col & 31) >> 1;
                uint2 p0 = split2h(acc[mt][nt][0], acc[mt][nt][1]);
                uint2 p1 = split2h(acc[mt][nt][2], acc[mt][nt][3]);
                uint32_t* b0 = g_kb + (size_t)r0 * 128 + blk * 32;
                uint32_t* b1 = g_kb + (size_t)(r0 + 8) * 128 + blk * 32;
                b0[kw] = p0.x; b0[16 + kw] = p0.y;
                b1[kw] = p1.x; b1[16 + kw] = p1.y;
            }
        }
    }
}

// ============================================================
// K2: scores = (Q @ K^T)*SCALE, 2-pass fp16: D = Qh*(Kh + Kl).
// Tile 128(s) x 64(t), FULL K=128 resident, one-shot 64KB.
// smem: Q [0,32K) (256B rows), K [32K,64K) (512B rows).
// ============================================================
__global__ __launch_bounds__(256, 3) void scores_kernel()
{
    extern __shared__ uint32_t dsm[];
    const uint32_t sqAddr = smem_u32(dsm);
    const uint32_t skAddr = sqAddr + 32768;

    const int t0 = blockIdx.x * 64, s0 = blockIdx.y * 128;
    const int tid = threadIdx.x;
    const int wid = tid >> 5, lane = tid & 31;
    const int g = lane >> 2, tg = lane & 3;
    const int wm = (wid & 3) * 32;
    const int wn = (wid >> 2) * 32;
    const int lr = (lane & 7) + ((lane >> 3) & 1) * 8;
    const int lc = lane >> 4;

    float acc[2][4][4];
#pragma unroll
    for (int i = 0; i < 2; i++)
#pragma unroll
        for (int j = 0; j < 4; j++)
#pragma unroll
            for (int q = 0; q < 4; q++) acc[i][j][q] = 0.f;

    // one-shot loads: Q 128 rows x 16 chunks (8/thr), K 64 rows x 32 chunks (8/thr)
#pragma unroll
    for (int j = 0; j < 8; j++) {
        int idx = tid + j * 256, row = idx >> 4, q = idx & 15;
        int blk = q >> 3, qq = q & 7;
        cp16(sqAddr + row * 256 + blk * 128 + ((qq ^ (row & 7)) << 4),
             g_qh + (size_t)(s0 + row) * 64 + q * 4);
    }
#pragma unroll
    for (int j = 0; j < 8; j++) {
        int idx = tid + j * 256, row = idx >> 5, c = idx & 31;
        int blk = c >> 3, q = c & 7;
        cp16(skAddr + row * 512 + blk * 128 + ((q ^ (row & 7)) << 4),
             g_kb + (size_t)(t0 + row) * 128 + blk * 32 + q * 4);
    }
    CP_COMMIT;
    CP_WAIT0;
    __syncthreads();

#pragma unroll
    for (int blk = 0; blk < 4; blk++) {          // K 32-blocks
#pragma unroll
        for (int h = 0; h < 2; h++) {            // k16 halves
            const int j = blk * 2 + h;           // k16 step 0..7
            const int ablk = j >> 2, ach = (j & 3) * 2;
            uint32_t Aq[2][4], Bh[2][4], Bl[2][4];
#pragma unroll
            for (int mt = 0; mt < 2; mt++) {
                const int ra = wm + mt * 16 + lr;
                ldsm_x4(Aq[mt], sqAddr + ra * 256 + ablk * 128 + (((ach + lc) ^ (ra & 7)) << 4));
            }
#pragma unroll
            for (int pr = 0; pr < 2; pr++) {
                const int rb = wn + pr * 16 + lr;
                const uint32_t rbase = skAddr + rb * 512 + blk * 128;
                ldsm_x4(Bh[pr], rbase + (((h * 2 + lc) ^ (rb & 7)) << 4));
                ldsm_x4(Bl[pr], rbase + (((4 + h * 2 + lc) ^ (rb & 7)) << 4));
            }
#pragma unroll
            for (int nt = 0; nt < 4; nt++) {
                uint32_t bh[2] = {Bh[nt >> 1][nt & 1], Bh[nt >> 1][2 + (nt & 1)]};
#pragma unroll
                for (int mt = 0; mt < 2; mt++) mma16(acc[mt][nt], Aq[mt], bh);
            }
#pragma unroll
            for (int nt = 0; nt < 4; nt++) {
                uint32_t bl[2] = {Bl[nt >> 1][nt & 1], Bl[nt >> 1][2 + (nt & 1)]};
#pragma unroll
                for (int mt = 0; mt < 2; mt++) mma16(acc[mt][nt], Aq[mt], bl);
            }
        }
    }

    __syncthreads();          // all LDSM reads done; alias K region for reductions
    float (*s_red)[64] = reinterpret_cast<float(*)[64]>(dsm + 8192);

#pragma unroll
    for (int mt = 0; mt < 2; mt++)
#pragma unroll
        for (int nt = 0; nt < 4; nt++)
#pragma unroll
            for (int q = 0; q < 4; q++) acc[mt][nt][q] *= SCALE;

    float cm[8];
#pragma unroll
    for (int nt = 0; nt < 4; nt++) {
        float a0 = fmaxf(fmaxf(acc[0][nt][0], acc[0][nt][2]), fmaxf(acc[1][nt][0], acc[1][nt][2]));
        float a1 = fmaxf(fmaxf(acc[0][nt][1], acc[0][nt][3]), fmaxf(acc[1][nt][1], acc[1][nt][3]));
        cm[nt * 2] = a0; cm[nt * 2 + 1] = a1;
    }
#pragma unroll
    for (int off = 4; off < 32; off <<= 1)
#pragma unroll
        for (int j = 0; j < 8; j++)
            cm[j] = fmaxf(cm[j], __shfl_xor_sync(0xffffffffu, cm[j], off));
    if (g == 0) {
#pragma unroll
        for (int nt = 0; nt < 4; nt++) {
            s_red[wid & 3][wn + nt * 8 + 2 * tg + 0] = cm[nt * 2 + 0];
            s_red[wid & 3][wn + nt * 8 + 2 * tg + 1] = cm[nt * 2 + 1];
        }
    }
    __syncthreads();
    float m4 = 0.f;
    if (tid < 64) {
        m4 = fmaxf(fmaxf(s_red[0][tid], s_red[1][tid]), fmaxf(s_red[2][tid], s_red[3][tid]));
        g_pm[(s0 >> 7) * SEQ + t0 + tid] = m4;
    }
    __syncthreads();
    if (tid < 64) s_red[0][tid] = m4;
    __syncthreads();

    float mcol[8];
#pragma unroll
    for (int nt = 0; nt < 4; nt++) {
        const int c = wn + nt * 8 + 2 * tg;
        mcol[nt * 2 + 0] = s_red[0][c];
        mcol[nt * 2 + 1] = s_red[0][c + 1];
    }

    float z[8];
#pragma unroll
    for (int j = 0; j < 8; j++) z[j] = 0.f;
#pragma unroll
    for (int mt = 0; mt < 2; mt++) {
#pragma unroll
        for (int nt = 0; nt < 4; nt++) {
            const int r0 = s0 + wm + mt * 16 + g;
            const int col = t0 + wn + nt * 8 + 2 * tg;
            float d00 = acc[mt][nt][0] - mcol[nt * 2],     d01 = acc[mt][nt][1] - mcol[nt * 2 + 1];
            float d10 = acc[mt][nt][2] - mcol[nt * 2],     d11 = acc[mt][nt][3] - mcol[nt * 2 + 1];
            *reinterpret_cast<__half2*>(&g_sch[(size_t)r0 * SEQ + col]) = __floats2half2_rn(d00, d01);
            *reinterpret_cast<__half2*>(&g_sch[(size_t)(r0 + 8) * SEQ + col]) = __floats2half2_rn(d10, d11);
            z[nt * 2 + 0] += (d00 > THRESH ? __expf(d00) : 0.f) + (d10 > THRESH ? __expf(d10) : 0.f);
            z[nt * 2 + 1] += (d01 > THRESH ? __expf(d01) : 0.f) + (d11 > THRESH ? __expf(d11) : 0.f);
        }
    }
#pragma unroll
    for (int off = 4; off < 32; off <<= 1)
#pragma unroll
        for (int j = 0; j < 8; j++)
            z[j] += __shfl_xor_sync(0xffffffffu, z[j], off);
    __syncthreads();
    if (g == 0) {
#pragma unroll
        for (int nt = 0; nt < 4; nt++) {
            s_red[wid & 3][wn + nt * 8 + 2 * tg + 0] = z[nt * 2 + 0];
            s_red[wid & 3][wn + nt * 8 + 2 * tg + 1] = z[nt * 2 + 1];
        }
    }
    __syncthreads();
    if (tid < 64)
        g_pzt[(s0 >> 7) * SEQ + t0 + tid] =
            (s_red[0][tid] + s_red[1][tid]) + (s_red[2][tid] + s_red[3][tid]);
}

// ============================================================
// K3: combine tile stats -> global m_t and 1/Z_t
// ============================================================
__global__ void combine_kernel()
{
    const int t = blockIdx.x * 256 + threadIdx.x;
    float m = -3.4e38f;
#pragma unroll 8
    for (int b = 0; b < NT; b++) m = fmaxf(m, g_pm[b * SEQ + t]);
    float Z = 0.f;
#pragma unroll 8
    for (int b = 0; b < NT; b++) {
        float d = g_pm[b * SEQ + t] - m;
        if (d > THRESH - 10.f) Z += g_pzt[b * SEQ + t] * __expf(d);
    }
    g_m[t] = m;
    g_rz[t] = 1.0f / Z;
}

// ============================================================
// K4: split-K PV with chunk-level liveness skip (unchanged)
// ============================================================
__global__ __launch_bounds__(256) void pv_kernel()
{
    __shared__ float s_adj[TCH];
    __shared__ float s_rz[TCH];
    __shared__ char  s_flag[NCHUNK];
    __shared__ float sA[8][64];
    __shared__ float sB[8][128];
    const int s0 = blockIdx.y * 64;
    const int tb = blockIdx.x * TCH;
    const int b = blockIdx.y >> 1;
    const int tid = threadIdx.x;
    const int tx = tid & 15, ty = tid >> 4;
    const int ar = tid >> 2, ac = (tid & 3) * 2;
    const int br = tid >> 5, bc = (tid & 31) * 4;

#pragma unroll
    for (int j = 0; j < 2; j++) {
        int t = tid + j * 256;
        s_adj[t] = g_pm[b * SEQ + tb + t] - g_m[tb + t];
        s_rz[t] = g_rz[tb + t];
    }
    __syncthreads();
    if (tid < NCHUNK) {
        float mx = -3.4e38f;
#pragma unroll
        for (int j = 0; j < 8; j++) mx = fmaxf(mx, s_adj[tid * 8 + j]);
        s_flag[tid] = (mx > THRESH) ? 1 : 0;
    }

    float acc[4][8];
#pragma unroll
    for (int i = 0; i < 4; i++)
#pragma unroll
        for (int j = 0; j < 8; j++) acc[i][j] = 0.f;

    const __half* sp = g_sch + (size_t)(s0 + ar) * SEQ + tb + ac;
    __syncthreads();

    for (int c = 0; c < NCHUNK; c++) {
        if (!s_flag[c]) continue;
        const int k0 = c * 8;
        __half2 hv = *reinterpret_cast<const __half2*>(sp + k0);
        float2 fv = __half22float2(hv);
        float dd0 = fv.x + s_adj[k0 + ac];
        float dd1 = fv.y + s_adj[k0 + ac + 1];
        float p0 = 0.f, p1 = 0.f;
        if (fmaxf(dd0, dd1) > THRESH) {
            if (dd0 > THRESH) p0 = __expf(dd0);
            if (dd1 > THRESH) p1 = __expf(dd1);
        }
        int active = __syncthreads_or(p0 != 0.f || p1 != 0.f);
        if (!active) continue;
        float rzv = s_rz[k0 + br];
        float4 bv = *reinterpret_cast<const float4*>(g_v + (size_t)(tb + k0 + br) * DK + bc);
        sA[ac][ar] = p0;
        sA[ac + 1][ar] = p1;
        *reinterpret_cast<float4*>(&sB[br][bc]) =
            make_float4(bv.x * rzv, bv.y * rzv, bv.z * rzv, bv.w * rzv);
        __syncthreads();
#pragma unroll
        for (int kk = 0; kk < 8; kk++) {
            float4 a  = *reinterpret_cast<const float4*>(&sA[kk][ty * 4]);
            float4 b0 = *reinterpret_cast<const float4*>(&sB[kk][tx * 8]);
            float4 b1 = *reinterpret_cast<const float4*>(&sB[kk][tx * 8 + 4]);
            float aa[4] = {a.x, a.y, a.z, a.w};
            float bb[8] = {b0.x, b0.y, b0.z, b0.w, b1.x, b1.y, b1.z, b1.w};
#pragma unroll
            for (int i = 0; i < 4; i++)
#pragma unroll
                for (int j = 0; j < 8; j++) acc[i][j] += aa[i] * bb[j];
        }
    }
    float* po = g_po[blockIdx.x];
#pragma unroll
    for (int i = 0; i < 4; i++) {
        float* op = po + (size_t)(s0 + ty * 4 + i) * DK + tx * 8;
        *reinterpret_cast<float4*>(op)     = make_float4(acc[i][0], acc[i][1], acc[i][2], acc[i][3]);
        *reinterpret_cast<float4*>(op + 4) = make_float4(acc[i][4], acc[i][5], acc[i][6], acc[i][7]);
    }
}

// K5: fixed-order split reduction
__global__ void pv_reduce_kernel(float* __restrict__ out)
{
    const int i = blockIdx.x * 256 + threadIdx.x;
    float s = 0.f;
#pragma unroll
    for (int p = 0; p < SPLIT; p++) s += g_po[p][i];
    out[i] = s;
}

// ============================================================
extern "C" void kernel_launch(void* const* d_in, const int* in_sizes, int n_in,
                              void* d_out, int out_size)
{
    const float* x  = (const float*)d_in[0];
    const float* wq = (const float*)d_in[1];
    const float* wk = (const float*)d_in[2];
    const float* wv = (const float*)d_in[3];
    float* out = (float*)d_out;

    cudaFuncSetAttribute(qkv_kernel, cudaFuncAttributeMaxDynamicSharedMemorySize, 81920);
    cudaFuncSetAttribute(scores_kernel, cudaFuncAttributeMaxDynamicSharedMemorySize, 65536);

    cvt_x_kernel<<<SEQ * CTX / 4 / 256, 256>>>(x);
    cvt_w_kernel<<<3 * DK * 512 / 256, 256>>>(wq, wk, wv);
    qkv_kernel<<<dim3(SEQ / 64, 3), 256, 81920>>>();
    scores_kernel<<<dim3(SEQ / 64, SEQ / 128), 256, 65536>>>();
    combine_kernel<<<SEQ / 256, 256>>>();
    pv_kernel<<<dim3(SPLIT, SEQ / 64), 256>>>();
    pv_reduce_kernel<<<SEQ * DK / 256, 256>>>(out);
}

// round 12
// speedup vs baseline: 6.5939x; 1.1772x over previous
#include <cuda_runtime.h>
#include <cuda_fp16.h>
#include <cstdint>

#define SEQ 8192
#define CTX 2048
#define DK  128
#define NT  64                    // SEQ/128 s-tiles
#define SPLIT 16
#define TCH (SEQ / SPLIT)         // 512 t-columns per pv block
#define NCHUNK (TCH / 8)          // 64 chunks per pv block
#define SCALE 11.313708498984760f
#define THRESH -25.0f

// ---- scratch (device globals) ----
// fp16 single-plane everywhere: row-major fp16, 2 values/word
__device__ uint32_t g_xh[(size_t)SEQ * (CTX / 2)];         // 32 MB
__device__ uint32_t g_wh[3 * DK * (CTX / 2)];              // 3 MB   [mat][n][k]
__device__ uint32_t g_qh[(size_t)SEQ * (DK / 2)];          // 2 MB
__device__ uint32_t g_kh[(size_t)SEQ * (DK / 2)];          // 2 MB
__device__ float  g_v[SEQ * DK];
__device__ __half g_sch[(size_t)SEQ * SEQ];                // 128 MB fp16 (sc - m_tile)
__device__ float  g_pm[NT * SEQ];
__device__ float  g_pzt[NT * SEQ];
__device__ float  g_m[SEQ];
__device__ float  g_rz[SEQ];
__device__ float  g_po[SPLIT][SEQ * DK];

// ============================================================
// helpers
// ============================================================
__device__ __forceinline__ uint32_t smem_u32(const void* p) {
    uint32_t a;
    asm("{ .reg .u64 t; cvta.to.shared.u64 t, %1; cvt.u32.u64 %0, t; }" : "=r"(a) : "l"(p));
    return a;
}
__device__ __forceinline__ void cp16(uint32_t dst, const void* src) {
    asm volatile("cp.async.cg.shared.global [%0], [%1], 16;" :: "r"(dst), "l"(src));
}
#define CP_COMMIT asm volatile("cp.async.commit_group;" ::: "memory")
#define CP_WAIT0  asm volatile("cp.async.wait_group 0;" ::: "memory")

// fp16 pack: (x0 -> low, x1 -> high)
__device__ __forceinline__ uint32_t packh2(float x0, float x1) {
    uint32_t h;
    asm("cvt.rn.f16x2.f32 %0, %1, %2;" : "=r"(h) : "f"(x1), "f"(x0));
    return h;
}
__device__ __forceinline__ void mma16(float* c, const uint32_t* a, const uint32_t* b) {
    asm("mma.sync.aligned.m16n8k16.row.col.f32.f16.f16.f32 "
        "{%0,%1,%2,%3}, {%4,%5,%6,%7}, {%8,%9}, {%0,%1,%2,%3};"
        : "+f"(c[0]), "+f"(c[1]), "+f"(c[2]), "+f"(c[3])
        : "r"(a[0]), "r"(a[1]), "r"(a[2]), "r"(a[3]), "r"(b[0]), "r"(b[1]));
}
__device__ __forceinline__ void ldsm_x4(uint32_t* d, uint32_t a) {
    asm volatile("ldmatrix.sync.aligned.m8n8.x4.shared.b16 {%0,%1,%2,%3}, [%4];"
                 : "=r"(d[0]), "=r"(d[1]), "=r"(d[2]), "=r"(d[3]) : "r"(a));
}

// ============================================================
// K0a: x -> row-major fp16 single plane
// ============================================================
__global__ __launch_bounds__(256) void cvt_x_kernel(const float* __restrict__ x)
{
    const int i = blockIdx.x * 256 + threadIdx.x;       // < SEQ*CTX/4
    float4 v = reinterpret_cast<const float4*>(x)[i];
    g_xh[2 * (size_t)i]     = packh2(v.x, v.y);
    g_xh[2 * (size_t)i + 1] = packh2(v.z, v.w);
}

// K0b: w^T -> fp16 single plane, [mat][n][k]
__global__ __launch_bounds__(256) void cvt_w_kernel(
    const float* __restrict__ wq, const float* __restrict__ wk, const float* __restrict__ wv)
{
    const int i = blockIdx.x * 256 + threadIdx.x;       // < 3*128*512
    const int mat = i / (DK * 512);
    const int r = i % (DK * 512);
    const int n = r >> 9;
    const int k4 = (r & 511) * 4;
    const float* w = (mat == 0) ? wq : (mat == 1) ? wk : wv;
    float w0 = w[(size_t)(k4 + 0) * DK + n];
    float w1 = w[(size_t)(k4 + 1) * DK + n];
    float w2 = w[(size_t)(k4 + 2) * DK + n];
    float w3 = w[(size_t)(k4 + 3) * DK + n];
    uint32_t* base = g_wh + ((size_t)(mat * DK + n)) * 1024 + (k4 >> 1);
    base[0] = packh2(w0, w1);
    base[1] = packh2(w2, w3);
}

// ============================================================
// K1: Q/K/V = x @ w, 1-pass fp16. Tile 64m x 128n, BK=64, 48KB 2-buf.
// smem bytes: A0 [0,8K) A1 [8K,16K) B0 [16K,32K) B1 [32K,48K)
// ============================================================
__global__ __launch_bounds__(256, 3) void qkv_kernel()
{
    extern __shared__ uint32_t dsm[];
    const uint32_t base0 = smem_u32(dsm);

    const int m0 = blockIdx.x * 64;
    const int mat = blockIdx.y;
    const int tid = threadIdx.x;
    const int wid = tid >> 5, lane = tid & 31;
    const int g = lane >> 2, tg = lane & 3;
    const int wm = (wid & 1) * 32;
    const int wn = (wid >> 1) * 32;
    const int lr = (lane & 7) + ((lane >> 3) & 1) * 8;
    const int lc = lane >> 4;

    float acc[2][4][4];
#pragma unroll
    for (int i = 0; i < 2; i++)
#pragma unroll
        for (int j = 0; j < 4; j++)
#pragma unroll
            for (int q = 0; q < 4; q++) acc[i][j][q] = 0.f;

#define QKV_ISSUE(kc, buf)                                                        \
    do {                                                                          \
        _Pragma("unroll")                                                         \
        for (int j = 0; j < 2; j++) {                                             \
            int idx = tid + j * 256, row = idx >> 3, q = idx & 7;                 \
            cp16(base0 + (buf) * 8192 + row * 128 + ((q ^ (row & 7)) << 4),       \
                 g_xh + (size_t)(m0 + row) * (CTX / 2) + (kc) * 32 + q * 4);      \
        }                                                                         \
        _Pragma("unroll")                                                         \
        for (int j = 0; j < 4; j++) {                                             \
            int idx = tid + j * 256, row = idx >> 3, q = idx & 7;                 \
            cp16(base0 + 16384 + (buf) * 16384 + row * 128 + ((q ^ (row & 7)) << 4), \
                 g_wh + (size_t)(mat * DK + row) * 1024 + (kc) * 32 + q * 4);     \
        }                                                                         \
    } while (0)

    QKV_ISSUE(0, 0);
    CP_COMMIT;
    const int NC = CTX / 64;   // 32
    for (int kc = 0; kc < NC; kc++) {
        CP_WAIT0;
        __syncthreads();
        if (kc + 1 < NC) { QKV_ISSUE(kc + 1, (kc + 1) & 1); CP_COMMIT; }
        const int buf = kc & 1;
        const uint32_t aB = base0 + buf * 8192u;
        const uint32_t bB = base0 + 16384u + buf * 16384u;
#pragma unroll
        for (int j = 0; j < 4; j++) {            // 4 k16 steps in BK=64
            uint32_t Aq[2][4], Bq[2][4];
#pragma unroll
            for (int mt = 0; mt < 2; mt++) {
                const int ra = wm + mt * 16 + lr;
                ldsm_x4(Aq[mt], aB + ra * 128 + (((j * 2 + lc) ^ (ra & 7)) << 4));
            }
#pragma unroll
            for (int pr = 0; pr < 2; pr++) {
                const int rb = wn + pr * 16 + lr;
                ldsm_x4(Bq[pr], bB + rb * 128 + (((j * 2 + lc) ^ (rb & 7)) << 4));
            }
#pragma unroll
            for (int nt = 0; nt < 4; nt++) {
                uint32_t bh[2] = {Bq[nt >> 1][nt & 1], Bq[nt >> 1][2 + (nt & 1)]};
#pragma unroll
                for (int mt = 0; mt < 2; mt++) mma16(acc[mt][nt], Aq[mt], bh);
            }
        }
    }
#undef QKV_ISSUE

#pragma unroll
    for (int mt = 0; mt < 2; mt++) {
#pragma unroll
        for (int nt = 0; nt < 4; nt++) {
            const int r0 = m0 + wm + mt * 16 + g;
            const int col = wn + nt * 8 + 2 * tg;
            if (mat == 2) {
                *reinterpret_cast<float2*>(g_v + (size_t)r0 * DK + col) =
                    make_float2(acc[mt][nt][0], acc[mt][nt][1]);
                *reinterpret_cast<float2*>(g_v + (size_t)(r0 + 8) * DK + col) =
                    make_float2(acc[mt][nt][2], acc[mt][nt][3]);
            } else {
                uint32_t* dst = (mat == 0) ? g_qh : g_kh;
                dst[(size_t)r0 * 64 + (col >> 1)] = packh2(acc[mt][nt][0], acc[mt][nt][1]);
                dst[(size_t)(r0 + 8) * 64 + (col >> 1)] = packh2(acc[mt][nt][2], acc[mt][nt][3]);
            }
        }
    }
}

// ============================================================
// K2: scores = (Q @ K^T)*SCALE, 1-pass fp16, FULL K=128 one-shot 48KB.
// Tile 128(s) x 64(t). smem: Q [0,32K) K [32K,48K), 256B rows.
// ============================================================
__global__ __launch_bounds__(256, 3) void scores_kernel()
{
    extern __shared__ uint32_t dsm[];
    const uint32_t sqAddr = smem_u32(dsm);
    const uint32_t skAddr = sqAddr + 32768;

    const int t0 = blockIdx.x * 64, s0 = blockIdx.y * 128;
    const int tid = threadIdx.x;
    const int wid = tid >> 5, lane = tid & 31;
    const int g = lane >> 2, tg = lane & 3;
    const int wm = (wid & 3) * 32;
    const int wn = (wid >> 2) * 32;
    const int lr = (lane & 7) + ((lane >> 3) & 1) * 8;
    const int lc = lane >> 4;

    float acc[2][4][4];
#pragma unroll
    for (int i = 0; i < 2; i++)
#pragma unroll
        for (int j = 0; j < 4; j++)
#pragma unroll
            for (int q = 0; q < 4; q++) acc[i][j][q] = 0.f;

    // one-shot loads: Q 128 rows x 16 chunks (8/thr), K 64 x 16 (4/thr)
#pragma unroll
    for (int j = 0; j < 8; j++) {
        int idx = tid + j * 256, row = idx >> 4, q = idx & 15;
        int blk = q >> 3, qq = q & 7;
        cp16(sqAddr + row * 256 + blk * 128 + ((qq ^ (row & 7)) << 4),
             g_qh + (size_t)(s0 + row) * 64 + q * 4);
    }
#pragma unroll
    for (int j = 0; j < 4; j++) {
        int idx = tid + j * 256, row = idx >> 4, q = idx & 15;
        int blk = q >> 3, qq = q & 7;
        cp16(skAddr + row * 256 + blk * 128 + ((qq ^ (row & 7)) << 4),
             g_kh + (size_t)(t0 + row) * 64 + q * 4);
    }
    CP_COMMIT;
    CP_WAIT0;
    __syncthreads();

#pragma unroll
    for (int j = 0; j < 8; j++) {                // 8 k16 steps
        const int ablk = j >> 2, ach = (j & 3) * 2;
        uint32_t Aq[2][4], Bq[2][4];
#pragma unroll
        for (int mt = 0; mt < 2; mt++) {
            const int ra = wm + mt * 16 + lr;
            ldsm_x4(Aq[mt], sqAddr + ra * 256 + ablk * 128 + (((ach + lc) ^ (ra & 7)) << 4));
        }
#pragma unroll
        for (int pr = 0; pr < 2; pr++) {
            const int rb = wn + pr * 16 + lr;
            ldsm_x4(Bq[pr], skAddr + rb * 256 + ablk * 128 + (((ach + lc) ^ (rb & 7)) << 4));
        }
#pragma unroll
        for (int nt = 0; nt < 4; nt++) {
            uint32_t bh[2] = {Bq[nt >> 1][nt & 1], Bq[nt >> 1][2 + (nt & 1)]};
#pragma unroll
            for (int mt = 0; mt < 2; mt++) mma16(acc[mt][nt], Aq[mt], bh);
        }
    }

    __syncthreads();          // all LDSM reads done; alias K region for reductions
    float (*s_red)[64] = reinterpret_cast<float(*)[64]>(dsm + 8192);

#pragma unroll
    for (int mt = 0; mt < 2; mt++)
#pragma unroll
        for (int nt = 0; nt < 4; nt++)
#pragma unroll
            for (int q = 0; q < 4; q++) acc[mt][nt][q] *= SCALE;

    float cm[8];
#pragma unroll
    for (int nt = 0; nt < 4; nt++) {
        float a0 = fmaxf(fmaxf(acc[0][nt][0], acc[0][nt][2]), fmaxf(acc[1][nt][0], acc[1][nt][2]));
        float a1 = fmaxf(fmaxf(acc[0][nt][1], acc[0][nt][3]), fmaxf(acc[1][nt][1], acc[1][nt][3]));
        cm[nt * 2] = a0; cm[nt * 2 + 1] = a1;
    }
#pragma unroll
    for (int off = 4; off < 32; off <<= 1)
#pragma unroll
        for (int j = 0; j < 8; j++)
            cm[j] = fmaxf(cm[j], __shfl_xor_sync(0xffffffffu, cm[j], off));
    if (g == 0) {
#pragma unroll
        for (int nt = 0; nt < 4; nt++) {
            s_red[wid & 3][wn + nt * 8 + 2 * tg + 0] = cm[nt * 2 + 0];
            s_red[wid & 3][wn + nt * 8 + 2 * tg + 1] = cm[nt * 2 + 1];
        }
    }
    __syncthreads();
    float m4 = 0.f;
    if (tid < 64) {
        m4 = fmaxf(fmaxf(s_red[0][tid], s_red[1][tid]), fmaxf(s_red[2][tid], s_red[3][tid]));
        g_pm[(s0 >> 7) * SEQ + t0 + tid] = m4;
    }
    __syncthreads();
    if (tid < 64) s_red[0][tid] = m4;
    __syncthreads();

    float mcol[8];
#pragma unroll
    for (int nt = 0; nt < 4; nt++) {
        const int c = wn + nt * 8 + 2 * tg;
        mcol[nt * 2 + 0] = s_red[0][c];
        mcol[nt * 2 + 1] = s_red[0][c + 1];
    }

    float z[8];
#pragma unroll
    for (int j = 0; j < 8; j++) z[j] = 0.f;
#pragma unroll
    for (int mt = 0; mt < 2; mt++) {
#pragma unroll
        for (int nt = 0; nt < 4; nt++) {
            const int r0 = s0 + wm + mt * 16 + g;
            const int col = t0 + wn + nt * 8 + 2 * tg;
            float d00 = acc[mt][nt][0] - mcol[nt * 2],     d01 = acc[mt][nt][1] - mcol[nt * 2 + 1];
            float d10 = acc[mt][nt][2] - mcol[nt * 2],     d11 = acc[mt][nt][3] - mcol[nt * 2 + 1];
            *reinterpret_cast<__half2*>(&g_sch[(size_t)r0 * SEQ + col]) = __floats2half2_rn(d00, d01);
            *reinterpret_cast<__half2*>(&g_sch[(size_t)(r0 + 8) * SEQ + col]) = __floats2half2_rn(d10, d11);
            z[nt * 2 + 0] += (d00 > THRESH ? __expf(d00) : 0.f) + (d10 > THRESH ? __expf(d10) : 0.f);
            z[nt * 2 + 1] += (d01 > THRESH ? __expf(d01) : 0.f) + (d11 > THRESH ? __expf(d11) : 0.f);
        }
    }
#pragma unroll
    for (int off = 4; off < 32; off <<= 1)
#pragma unroll
        for (int j = 0; j < 8; j++)
            z[j] += __shfl_xor_sync(0xffffffffu, z[j], off);
    __syncthreads();
    if (g == 0) {
#pragma unroll
        for (int nt = 0; nt < 4; nt++) {
            s_red[wid & 3][wn + nt * 8 + 2 * tg + 0] = z[nt * 2 + 0];
            s_red[wid & 3][wn + nt * 8 + 2 * tg + 1] = z[nt * 2 + 1];
        }
    }
    __syncthreads();
    if (tid < 64)
        g_pzt[(s0 >> 7) * SEQ + t0 + tid] =
            (s_red[0][tid] + s_red[1][tid]) + (s_red[2][tid] + s_red[3][tid]);
}

// ============================================================
// K3: combine tile stats -> global m_t and 1/Z_t
// ============================================================
__global__ void combine_kernel()
{
    const int t = blockIdx.x * 256 + threadIdx.x;
    float m = -3.4e38f;
#pragma unroll 8
    for (int b = 0; b < NT; b++) m = fmaxf(m, g_pm[b * SEQ + t]);
    float Z = 0.f;
#pragma unroll 8
    for (int b = 0; b < NT; b++) {
        float d = g_pm[b * SEQ + t] - m;
        if (d > THRESH - 10.f) Z += g_pzt[b * SEQ + t] * __expf(d);
    }
    g_m[t] = m;
    g_rz[t] = 1.0f / Z;
}

// ============================================================
// K4: split-K PV with chunk-level liveness skip (unchanged)
// ============================================================
__global__ __launch_bounds__(256) void pv_kernel()
{
    __shared__ float s_adj[TCH];
    __shared__ float s_rz[TCH];
    __shared__ char  s_flag[NCHUNK];
    __shared__ float sA[8][64];
    __shared__ float sB[8][128];
    const int s0 = blockIdx.y * 64;
    const int tb = blockIdx.x * TCH;
    const int b = blockIdx.y >> 1;
    const int tid = threadIdx.x;
    const int tx = tid & 15, ty = tid >> 4;
    const int ar = tid >> 2, ac = (tid & 3) * 2;
    const int br = tid >> 5, bc = (tid & 31) * 4;

#pragma unroll
    for (int j = 0; j < 2; j++) {
        int t = tid + j * 256;
        s_adj[t] = g_pm[b * SEQ + tb + t] - g_m[tb + t];
        s_rz[t] = g_rz[tb + t];
    }
    __syncthreads();
    if (tid < NCHUNK) {
        float mx = -3.4e38f;
#pragma unroll
        for (int j = 0; j < 8; j++) mx = fmaxf(mx, s_adj[tid * 8 + j]);
        s_flag[tid] = (mx > THRESH) ? 1 : 0;
    }

    float acc[4][8];
#pragma unroll
    for (int i = 0; i < 4; i++)
#pragma unroll
        for (int j = 0; j < 8; j++) acc[i][j] = 0.f;

    const __half* sp = g_sch + (size_t)(s0 + ar) * SEQ + tb + ac;
    __syncthreads();

    for (int c = 0; c < NCHUNK; c++) {
        if (!s_flag[c]) continue;
        const int k0 = c * 8;
        __half2 hv = *reinterpret_cast<const __half2*>(sp + k0);
        float2 fv = __half22float2(hv);
        float dd0 = fv.x + s_adj[k0 + ac];
        float dd1 = fv.y + s_adj[k0 + ac + 1];
        float p0 = 0.f, p1 = 0.f;
        if (fmaxf(dd0, dd1) > THRESH) {
            if (dd0 > THRESH) p0 = __expf(dd0);
            if (dd1 > THRESH) p1 = __expf(dd1);
        }
        int active = __syncthreads_or(p0 != 0.f || p1 != 0.f);
        if (!active) continue;
        float rzv = s_rz[k0 + br];
        float4 bv = *reinterpret_cast<const float4*>(g_v + (size_t)(tb + k0 + br) * DK + bc);
        sA[ac][ar] = p0;
        sA[ac + 1][ar] = p1;
        *reinterpret_cast<float4*>(&sB[br][bc]) =
            make_float4(bv.x * rzv, bv.y * rzv, bv.z * rzv, bv.w * rzv);
        __syncthreads();
#pragma unroll
        for (int kk = 0; kk < 8; kk++) {
            float4 a  = *reinterpret_cast<const float4*>(&sA[kk][ty * 4]);
            float4 b0 = *reinterpret_cast<const float4*>(&sB[kk][tx * 8]);
            float4 b1 = *reinterpret_cast<const float4*>(&sB[kk][tx * 8 + 4]);
            float aa[4] = {a.x, a.y, a.z, a.w};
            float bb[8] = {b0.x, b0.y, b0.z, b0.w, b1.x, b1.y, b1.z, b1.w};
#pragma unroll
            for (int i = 0; i < 4; i++)
#pragma unroll
                for (int j = 0; j < 8; j++) acc[i][j] += aa[i] * bb[j];
        }
    }
    float* po = g_po[blockIdx.x];
#pragma unroll
    for (int i = 0; i < 4; i++) {
        float* op = po + (size_t)(s0 + ty * 4 + i) * DK + tx * 8;
        *reinterpret_cast<float4*>(op)     = make_float4(acc[i][0], acc[i][1], acc[i][2], acc[i][3]);
        *reinterpret_cast<float4*>(op + 4) = make_float4(acc[i][4], acc[i][5], acc[i][6], acc[i][7]);
    }
}

// K5: fixed-order split reduction
__global__ void pv_reduce_kernel(float* __restrict__ out)
{
    const int i = blockIdx.x * 256 + threadIdx.x;
    float s = 0.f;
#pragma unroll
    for (int p = 0; p < SPLIT; p++) s += g_po[p][i];
    out[i] = s;
}

// ============================================================
extern "C" void kernel_launch(void* const* d_in, const int* in_sizes, int n_in,
                              void* d_out, int out_size)
{
    const float* x  = (const float*)d_in[0];
    const float* wq = (const float*)d_in[1];
    const float* wk = (const float*)d_in[2];
    const float* wv = (const float*)d_in[3];
    float* out = (float*)d_out;

    cudaFuncSetAttribute(qkv_kernel, cudaFuncAttributeMaxDynamicSharedMemorySize, 49152);
    cudaFuncSetAttribute(scores_kernel, cudaFuncAttributeMaxDynamicSharedMemorySize, 49152);

    cvt_x_kernel<<<SEQ * CTX / 4 / 256, 256>>>(x);
    cvt_w_kernel<<<3 * DK * 512 / 256, 256>>>(wq, wk, wv);
    qkv_kernel<<<dim3(SEQ / 64, 3), 256, 49152>>>();
    scores_kernel<<<dim3(SEQ / 64, SEQ / 128), 256, 49152>>>();
    combine_kernel<<<SEQ / 256, 256>>>();
    pv_kernel<<<dim3(SPLIT, SEQ / 64), 256>>>();
    pv_reduce_kernel<<<SEQ * DK / 256, 256>>>(out);
}